// round 3
// baseline (speedup 1.0000x reference)
#include <cuda_runtime.h>
#include <math.h>

#define NMAX 50000
#define TE 128

// Scratch (device globals: allocation-free rule)
__device__ float g_agg[NMAX * 128];   // per-node aggregated messages
__device__ float g_pacc[NMAX * 3];    // per-node position correction

__device__ __forceinline__ float silu_f(float x) {
    return x / (1.0f + __expf(-x));
}

__global__ void zero_kernel(int n_agg, int n_pacc) {
    int i = blockIdx.x * blockDim.x + threadIdx.x;
    int stride = gridDim.x * blockDim.x;
    for (int k = i; k < n_agg; k += stride) g_agg[k] = 0.f;
    for (int k = i; k < n_pacc; k += stride) g_pacc[k] = 0.f;
}

// ---------------------------------------------------------------------------
// Edge kernel: per tile of 128 edges
//   msg1 = silu(concat(h[s], h[r], radial) @ eW1 + eb1)       (K=257)
//   msg2 = silu(msg1 @ eW2 + eb2)                             (K=128)
//   atomicAdd agg[r] += msg2
//   p1   = silu(msg2 @ pW1 + pb1); pc = p1 @ pW2              (K=128 + dot)
//   atomicAdd pacc[s] += clip(coord_diff * pc, -100, 100)
// Block: 256 threads, 16x16 thread grid, each thread owns 8 edges x 8 cols.
// Shared: A-chunk/B-chunk staging + k-major msg buffers T1/T2.
// ---------------------------------------------------------------------------
__global__ __launch_bounds__(256, 1)
void edge_kernel(const float* __restrict__ h, const float* __restrict__ pos,
                 const int* __restrict__ snd, const int* __restrict__ rcv,
                 const float* __restrict__ eW1, const float* __restrict__ eb1,
                 const float* __restrict__ eW2, const float* __restrict__ eb2,
                 const float* __restrict__ pW1, const float* __restrict__ pb1,
                 const float* __restrict__ pW2, int E)
{
    extern __shared__ float sm[];
    float* As  = sm;            // [16][128] k-major A chunk
    float* Bs  = As + 2048;     // [16][128] weight chunk
    float* T1  = Bs + 2048;     // [128][128] msg1, k-major: T1[k*128+e]
    float* T2  = T1 + 16384;    // [128][128] msg2, k-major
    float* cd  = T2 + 16384;    // [128][3] coord_diff
    float* rad = cd + 384;      // [128] radial
    float* red = rad + 128;     // [16][128] pc reduction
    int*   se  = (int*)(red + 2048);  // [128]
    int*   re  = se + 128;            // [128]

    const int tid = threadIdx.x;
    const int tx = tid & 15, ty = tid >> 4;
    const int e0 = tx * 8, j0 = ty * 8;
    const int ebase = blockIdx.x * TE;

    if (tid < TE) {
        int ge = ebase + tid; if (ge >= E) ge = E - 1;
        int s = snd[ge], r = rcv[ge];
        se[tid] = s; re[tid] = r;
        float dx = pos[s * 3 + 0] - pos[r * 3 + 0];
        float dy = pos[s * 3 + 1] - pos[r * 3 + 1];
        float dz = pos[s * 3 + 2] - pos[r * 3 + 2];
        cd[tid * 3 + 0] = dx; cd[tid * 3 + 1] = dy; cd[tid * 3 + 2] = dz;
        rad[tid] = dx * dx + dy * dy + dz * dz;
    }
    __syncthreads();

    float acc[8][8];
#pragma unroll
    for (int i = 0; i < 8; i++)
#pragma unroll
        for (int j = 0; j < 8; j++) acc[i][j] = 0.f;

    float ra[8], rb[8];

    // ---- stage 1: K=256 concat features (+ radial term in epilogue) ----
    // prefetch chunk 0
#pragma unroll
    for (int t = 0; t < 8; t++) {
        int idx = tid + t * 256;
        int kk = idx >> 7, col = idx & 127;
        int node = se[col];                 // k in [0,16) -> sender features
        ra[t] = h[node * 128 + kk];
        rb[t] = eW1[kk * 128 + col];
    }
#pragma unroll 1
    for (int c = 0; c < 16; c++) {
        __syncthreads();
#pragma unroll
        for (int t = 0; t < 8; t++) {
            int idx = tid + t * 256;
            As[idx] = ra[t];
            Bs[idx] = rb[t];
        }
        __syncthreads();
        if (c + 1 < 16) {
            int kb = (c + 1) * 16;
#pragma unroll
            for (int t = 0; t < 8; t++) {
                int idx = tid + t * 256;
                int kk = idx >> 7, col = idx & 127;
                int k = kb + kk;
                int node = (k < 128) ? se[col] : re[col];
                ra[t] = h[node * 128 + (k & 127)];
                rb[t] = eW1[k * 128 + col];
            }
        }
#pragma unroll
        for (int kk = 0; kk < 16; kk++) {
            float a[8], b[8];
#pragma unroll
            for (int i = 0; i < 8; i++) a[i] = As[kk * 128 + e0 + i];
#pragma unroll
            for (int j = 0; j < 8; j++) b[j] = Bs[kk * 128 + j0 + j];
#pragma unroll
            for (int i = 0; i < 8; i++)
#pragma unroll
                for (int j = 0; j < 8; j++) acc[i][j] = fmaf(a[i], b[j], acc[i][j]);
        }
    }
    // epilogue: radial term + bias + silu -> T1 (k-major)
    {
        float bj[8], wr[8];
#pragma unroll
        for (int j = 0; j < 8; j++) {
            bj[j] = eb1[j0 + j];
            wr[j] = eW1[256 * 128 + j0 + j];
        }
#pragma unroll
        for (int i = 0; i < 8; i++) {
            float rd = rad[e0 + i];
#pragma unroll
            for (int j = 0; j < 8; j++) {
                float v = acc[i][j] + rd * wr[j] + bj[j];
                T1[(j0 + j) * 128 + e0 + i] = silu_f(v);
            }
        }
    }

    // ---- stage 2: msg2 = silu(msg1 @ eW2 + eb2) ----
#pragma unroll
    for (int i = 0; i < 8; i++)
#pragma unroll
        for (int j = 0; j < 8; j++) acc[i][j] = 0.f;
#pragma unroll
    for (int t = 0; t < 8; t++) rb[t] = eW2[tid + t * 256];
#pragma unroll 1
    for (int c = 0; c < 8; c++) {
        __syncthreads();     // (c==0 also publishes T1)
#pragma unroll
        for (int t = 0; t < 8; t++) Bs[tid + t * 256] = rb[t];
        __syncthreads();
        if (c + 1 < 8) {
#pragma unroll
            for (int t = 0; t < 8; t++) rb[t] = eW2[(c + 1) * 2048 + tid + t * 256];
        }
#pragma unroll
        for (int kk = 0; kk < 16; kk++) {
            int k = c * 16 + kk;
            float a[8], b[8];
#pragma unroll
            for (int i = 0; i < 8; i++) a[i] = T1[k * 128 + e0 + i];
#pragma unroll
            for (int j = 0; j < 8; j++) b[j] = Bs[kk * 128 + j0 + j];
#pragma unroll
            for (int i = 0; i < 8; i++)
#pragma unroll
                for (int j = 0; j < 8; j++) acc[i][j] = fmaf(a[i], b[j], acc[i][j]);
        }
    }
    // epilogue: silu, scatter into agg[receiver], stash msg2 in T2
    {
        float bj[8];
#pragma unroll
        for (int j = 0; j < 8; j++) bj[j] = eb2[j0 + j];
#pragma unroll
        for (int i = 0; i < 8; i++) {
            int ge = ebase + e0 + i;
            bool valid = ge < E;
            int r = re[e0 + i];
#pragma unroll
            for (int j = 0; j < 8; j++) {
                float v = silu_f(acc[i][j] + bj[j]);
                T2[(j0 + j) * 128 + e0 + i] = v;
                if (valid) atomicAdd(&g_agg[r * 128 + j0 + j], v);
            }
        }
    }

    // ---- stage 3: p1 = silu(msg2 @ pW1 + pb1); pc = p1 @ pW2 ----
#pragma unroll
    for (int i = 0; i < 8; i++)
#pragma unroll
        for (int j = 0; j < 8; j++) acc[i][j] = 0.f;
#pragma unroll
    for (int t = 0; t < 8; t++) rb[t] = pW1[tid + t * 256];
#pragma unroll 1
    for (int c = 0; c < 8; c++) {
        __syncthreads();     // (c==0 also publishes T2)
#pragma unroll
        for (int t = 0; t < 8; t++) Bs[tid + t * 256] = rb[t];
        __syncthreads();
        if (c + 1 < 8) {
#pragma unroll
            for (int t = 0; t < 8; t++) rb[t] = pW1[(c + 1) * 2048 + tid + t * 256];
        }
#pragma unroll
        for (int kk = 0; kk < 16; kk++) {
            int k = c * 16 + kk;
            float a[8], b[8];
#pragma unroll
            for (int i = 0; i < 8; i++) a[i] = T2[k * 128 + e0 + i];
#pragma unroll
            for (int j = 0; j < 8; j++) b[j] = Bs[kk * 128 + j0 + j];
#pragma unroll
            for (int i = 0; i < 8; i++)
#pragma unroll
                for (int j = 0; j < 8; j++) acc[i][j] = fmaf(a[i], b[j], acc[i][j]);
        }
    }
    // epilogue: silu, dot with pW2, reduce pc across column groups
    {
        float bj[8], wj[8];
#pragma unroll
        for (int j = 0; j < 8; j++) {
            bj[j] = pb1[j0 + j];
            wj[j] = pW2[j0 + j];
        }
#pragma unroll
        for (int i = 0; i < 8; i++) {
            float part = 0.f;
#pragma unroll
            for (int j = 0; j < 8; j++)
                part += silu_f(acc[i][j] + bj[j]) * wj[j];
            red[ty * 128 + e0 + i] = part;
        }
    }
    __syncthreads();
    if (tid < 128) {
        float pc = 0.f;
#pragma unroll
        for (int t = 0; t < 16; t++) pc += red[t * 128 + tid];
        int ge = ebase + tid;
        if (ge < E) {
            int s = se[tid];
#pragma unroll
            for (int d = 0; d < 3; d++) {
                float v = cd[tid * 3 + d] * pc;
                v = fminf(fmaxf(v, -100.f), 100.f);
                atomicAdd(&g_pacc[s * 3 + d], v);
            }
        }
    }
}

// ---------------------------------------------------------------------------
// Node kernel: per tile of 128 nodes
//   x = silu(concat(h, agg) @ nW1 + nb1) @ nW2 + nb2; h_new = h + x
//   pos_new = pos + pacc
// ---------------------------------------------------------------------------
__global__ __launch_bounds__(256, 1)
void node_kernel(const float* __restrict__ h, const float* __restrict__ pos,
                 const float* __restrict__ nW1, const float* __restrict__ nb1,
                 const float* __restrict__ nW2, const float* __restrict__ nb2,
                 float* __restrict__ out, int N)
{
    extern __shared__ float sm[];
    float* As = sm;           // [16][128]
    float* Bs = As + 2048;    // [16][128]
    float* T1 = Bs + 2048;    // [128][128] k-major

    const int tid = threadIdx.x;
    const int tx = tid & 15, ty = tid >> 4;
    const int e0 = tx * 8, j0 = ty * 8;
    const int nb = blockIdx.x * 128;

    float acc[8][8];
#pragma unroll
    for (int i = 0; i < 8; i++)
#pragma unroll
        for (int j = 0; j < 8; j++) acc[i][j] = 0.f;

    float ra[8], rb[8];
    // stage 1: K = 256 (h | agg)
#pragma unroll
    for (int t = 0; t < 8; t++) {
        int idx = tid + t * 256;
        int kk = idx >> 7, col = idx & 127;
        int node = nb + col; if (node >= N) node = N - 1;
        ra[t] = h[node * 128 + kk];
        rb[t] = nW1[kk * 128 + col];
    }
#pragma unroll 1
    for (int c = 0; c < 16; c++) {
        __syncthreads();
#pragma unroll
        for (int t = 0; t < 8; t++) {
            int idx = tid + t * 256;
            As[idx] = ra[t];
            Bs[idx] = rb[t];
        }
        __syncthreads();
        if (c + 1 < 16) {
            int kb = (c + 1) * 16;
#pragma unroll
            for (int t = 0; t < 8; t++) {
                int idx = tid + t * 256;
                int kk = idx >> 7, col = idx & 127;
                int k = kb + kk;
                int node = nb + col; if (node >= N) node = N - 1;
                ra[t] = (k < 128) ? h[node * 128 + k]
                                  : g_agg[node * 128 + (k - 128)];
                rb[t] = nW1[k * 128 + col];
            }
        }
#pragma unroll
        for (int kk = 0; kk < 16; kk++) {
            float a[8], b[8];
#pragma unroll
            for (int i = 0; i < 8; i++) a[i] = As[kk * 128 + e0 + i];
#pragma unroll
            for (int j = 0; j < 8; j++) b[j] = Bs[kk * 128 + j0 + j];
#pragma unroll
            for (int i = 0; i < 8; i++)
#pragma unroll
                for (int j = 0; j < 8; j++) acc[i][j] = fmaf(a[i], b[j], acc[i][j]);
        }
    }
    {
        float bj[8];
#pragma unroll
        for (int j = 0; j < 8; j++) bj[j] = nb1[j0 + j];
#pragma unroll
        for (int i = 0; i < 8; i++)
#pragma unroll
            for (int j = 0; j < 8; j++)
                T1[(j0 + j) * 128 + e0 + i] = silu_f(acc[i][j] + bj[j]);
    }

    // stage 2: K = 128 -> h_new
#pragma unroll
    for (int i = 0; i < 8; i++)
#pragma unroll
        for (int j = 0; j < 8; j++) acc[i][j] = 0.f;
#pragma unroll
    for (int t = 0; t < 8; t++) rb[t] = nW2[tid + t * 256];
#pragma unroll 1
    for (int c = 0; c < 8; c++) {
        __syncthreads();
#pragma unroll
        for (int t = 0; t < 8; t++) Bs[tid + t * 256] = rb[t];
        __syncthreads();
        if (c + 1 < 8) {
#pragma unroll
            for (int t = 0; t < 8; t++) rb[t] = nW2[(c + 1) * 2048 + tid + t * 256];
        }
#pragma unroll
        for (int kk = 0; kk < 16; kk++) {
            int k = c * 16 + kk;
            float a[8], b[8];
#pragma unroll
            for (int i = 0; i < 8; i++) a[i] = T1[k * 128 + e0 + i];
#pragma unroll
            for (int j = 0; j < 8; j++) b[j] = Bs[kk * 128 + j0 + j];
#pragma unroll
            for (int i = 0; i < 8; i++)
#pragma unroll
                for (int j = 0; j < 8; j++) acc[i][j] = fmaf(a[i], b[j], acc[i][j]);
        }
    }
    {
        float bj[8];
#pragma unroll
        for (int j = 0; j < 8; j++) bj[j] = nb2[j0 + j];
#pragma unroll
        for (int i = 0; i < 8; i++) {
            int node = nb + e0 + i;
            if (node < N) {
#pragma unroll
                for (int j = 0; j < 8; j++)
                    out[node * 128 + j0 + j] =
                        acc[i][j] + bj[j] + h[node * 128 + j0 + j];
            }
        }
    }

    // pos_new = pos + pacc
    if (tid < 128) {
        int node = nb + tid;
        if (node < N) {
#pragma unroll
            for (int d = 0; d < 3; d++)
                out[N * 128 + node * 3 + d] =
                    pos[node * 3 + d] + g_pacc[node * 3 + d];
        }
    }
}

extern "C" void kernel_launch(void* const* d_in, const int* in_sizes, int n_in,
                              void* d_out, int out_size)
{
    const float* h   = (const float*)d_in[0];
    const float* pos = (const float*)d_in[1];
    const int*   snd = (const int*)d_in[2];
    const int*   rcv = (const int*)d_in[3];
    const float* eW1 = (const float*)d_in[4];
    const float* eb1 = (const float*)d_in[5];
    const float* eW2 = (const float*)d_in[6];
    const float* eb2 = (const float*)d_in[7];
    const float* nW1 = (const float*)d_in[8];
    const float* nb1 = (const float*)d_in[9];
    const float* nW2 = (const float*)d_in[10];
    const float* nb2 = (const float*)d_in[11];
    const float* pW1 = (const float*)d_in[12];
    const float* pb1 = (const float*)d_in[13];
    const float* pW2 = (const float*)d_in[14];
    float* out = (float*)d_out;

    int N = in_sizes[0] / 128;
    int E = in_sizes[2];

    const int smE = (2048 + 2048 + 16384 + 16384 + 384 + 128 + 2048) * 4 + 256 * 4;
    const int smN = (2048 + 2048 + 16384) * 4;
    cudaFuncSetAttribute(edge_kernel, cudaFuncAttributeMaxDynamicSharedMemorySize, smE);
    cudaFuncSetAttribute(node_kernel, cudaFuncAttributeMaxDynamicSharedMemorySize, smN);

    zero_kernel<<<256, 256>>>(N * 128, N * 3);
    edge_kernel<<<(E + TE - 1) / TE, 256, smE>>>(h, pos, snd, rcv,
                                                 eW1, eb1, eW2, eb2,
                                                 pW1, pb1, pW2, E);
    node_kernel<<<(N + 127) / 128, 256, smN>>>(h, pos, nW1, nb1, nW2, nb2, out, N);
}

// round 5
// speedup vs baseline: 1.0091x; 1.0091x over previous
#include <cuda_runtime.h>
#include <math.h>

#define NMAX 50000
#define TE 128

// Scratch (device globals: allocation-free rule)
__device__ float g_agg[NMAX * 128];   // per-node aggregated messages
__device__ float g_pacc[NMAX * 3];    // per-node position correction

__device__ __forceinline__ float silu_f(float x) {
    return x / (1.0f + __expf(-x));
}

// ---- packed f32x2 helpers (Blackwell FFMA2 path; ptxas never emits this) ----
__device__ __forceinline__ unsigned long long dup2(float x) {
    unsigned long long r;
    asm("mov.b64 %0, {%1, %1};" : "=l"(r) : "f"(x));
    return r;
}
__device__ __forceinline__ void fma2(unsigned long long& d,
                                     unsigned long long a,
                                     unsigned long long b) {
    asm("fma.rn.f32x2 %0, %1, %2, %0;" : "+l"(d) : "l"(a), "l"(b));
}
__device__ __forceinline__ float2 unpack2(unsigned long long v) {
    float2 f;
    asm("mov.b64 {%0, %1}, %2;" : "=f"(f.x), "=f"(f.y) : "l"(v));
    return f;
}

__global__ void zero_kernel(int n_agg, int n_pacc) {
    int i = blockIdx.x * blockDim.x + threadIdx.x;
    int stride = gridDim.x * blockDim.x;
    for (int k = i; k < n_agg; k += stride) g_agg[k] = 0.f;
    for (int k = i; k < n_pacc; k += stride) g_pacc[k] = 0.f;
}

// Inner-product micro-kernel over one 16-deep K chunk held in SMEM.
// A chunk k-major at As[kk*128 + e], B chunk k-major at Bs[kk*128 + j].
// acc2[i][t] packs columns (j0+2t, j0+2t+1) for edge e0+i.
__device__ __forceinline__ void mm_chunk16(const float* __restrict__ As,
                                           const float* __restrict__ Bs,
                                           int e0, int j0,
                                           unsigned long long acc2[8][4]) {
#pragma unroll
    for (int kk = 0; kk < 16; kk++) {
        float4 a03 = *(const float4*)&As[kk * 128 + e0];
        float4 a47 = *(const float4*)&As[kk * 128 + e0 + 4];
        ulonglong2 bq0 = *(const ulonglong2*)&Bs[kk * 128 + j0];
        ulonglong2 bq1 = *(const ulonglong2*)&Bs[kk * 128 + j0 + 4];
        unsigned long long b2[4] = {bq0.x, bq0.y, bq1.x, bq1.y};
        float av[8] = {a03.x, a03.y, a03.z, a03.w, a47.x, a47.y, a47.z, a47.w};
#pragma unroll
        for (int i = 0; i < 8; i++) {
            unsigned long long ad = dup2(av[i]);
#pragma unroll
            for (int t = 0; t < 4; t++) fma2(acc2[i][t], ad, b2[t]);
        }
    }
}

// ---------------------------------------------------------------------------
// Edge kernel: per tile of 128 edges
//   msg1 = silu(concat(h[s], h[r], radial) @ eW1 + eb1)       (K=257)
//   msg2 = silu(msg1 @ eW2 + eb2)                             (K=128)
//   atomicAdd agg[r] += msg2
//   p1   = silu(msg2 @ pW1 + pb1); pc = p1 @ pW2              (K=128 + dot)
//   atomicAdd pacc[s] += clip(coord_diff * pc, -100, 100)
// Block: 256 threads, 16x16 thread grid, each thread owns 8 edges x 8 cols.
// ---------------------------------------------------------------------------
__global__ __launch_bounds__(256, 1)
void edge_kernel(const float* __restrict__ h, const float* __restrict__ pos,
                 const int* __restrict__ snd, const int* __restrict__ rcv,
                 const float* __restrict__ eW1, const float* __restrict__ eb1,
                 const float* __restrict__ eW2, const float* __restrict__ eb2,
                 const float* __restrict__ pW1, const float* __restrict__ pb1,
                 const float* __restrict__ pW2, int E)
{
    extern __shared__ float sm[];
    float* As  = sm;            // [16][128] k-major A chunk
    float* Bs  = As + 2048;     // [16][128] weight chunk
    float* T1  = Bs + 2048;     // [128][128] msg1, k-major: T1[k*128+e]
    float* T2  = T1 + 16384;    // [128][128] msg2, k-major
    float* cd  = T2 + 16384;    // [128][3] coord_diff
    float* rad = cd + 384;      // [128] radial
    float* red = rad + 128;     // [16][128] pc reduction
    int*   se  = (int*)(red + 2048);  // [128]
    int*   re  = se + 128;            // [128]

    const int tid = threadIdx.x;
    const int tx = tid & 15, ty = tid >> 4;
    const int e0 = tx * 8, j0 = ty * 8;
    const int ebase = blockIdx.x * TE;

    if (tid < TE) {
        int ge = ebase + tid; if (ge >= E) ge = E - 1;
        int s = snd[ge], r = rcv[ge];
        se[tid] = s; re[tid] = r;
        float dx = pos[s * 3 + 0] - pos[r * 3 + 0];
        float dy = pos[s * 3 + 1] - pos[r * 3 + 1];
        float dz = pos[s * 3 + 2] - pos[r * 3 + 2];
        cd[tid * 3 + 0] = dx; cd[tid * 3 + 1] = dy; cd[tid * 3 + 2] = dz;
        rad[tid] = dx * dx + dy * dy + dz * dz;
    }
    __syncthreads();

    unsigned long long acc2[8][4];
#pragma unroll
    for (int i = 0; i < 8; i++)
#pragma unroll
        for (int t = 0; t < 4; t++) acc2[i][t] = 0ull;

    float ra[8], rb[8];

    // ---- stage 1: K=256 concat features (+ radial term in epilogue) ----
#pragma unroll
    for (int t = 0; t < 8; t++) {
        int idx = tid + t * 256;
        int kk = idx >> 7, col = idx & 127;
        int node = se[col];
        ra[t] = h[node * 128 + kk];
        rb[t] = eW1[kk * 128 + col];
    }
#pragma unroll 1
    for (int c = 0; c < 16; c++) {
        __syncthreads();
#pragma unroll
        for (int t = 0; t < 8; t++) {
            int idx = tid + t * 256;
            As[idx] = ra[t];
            Bs[idx] = rb[t];
        }
        __syncthreads();
        if (c + 1 < 16) {
            int kb = (c + 1) * 16;
#pragma unroll
            for (int t = 0; t < 8; t++) {
                int idx = tid + t * 256;
                int kk = idx >> 7, col = idx & 127;
                int k = kb + kk;
                int node = (k < 128) ? se[col] : re[col];
                ra[t] = h[node * 128 + (k & 127)];
                rb[t] = eW1[k * 128 + col];
            }
        }
        mm_chunk16(As, Bs, e0, j0, acc2);
    }
    // epilogue: radial term + bias + silu -> T1 (k-major)
    {
        float bj[8], wr[8];
#pragma unroll
        for (int j = 0; j < 8; j++) {
            bj[j] = eb1[j0 + j];
            wr[j] = eW1[256 * 128 + j0 + j];
        }
#pragma unroll
        for (int i = 0; i < 8; i++) {
            float rd = rad[e0 + i];
#pragma unroll
            for (int t = 0; t < 4; t++) {
                float2 v = unpack2(acc2[i][t]);
                float v0 = v.x + rd * wr[2 * t]     + bj[2 * t];
                float v1 = v.y + rd * wr[2 * t + 1] + bj[2 * t + 1];
                T1[(j0 + 2 * t) * 128 + e0 + i]     = silu_f(v0);
                T1[(j0 + 2 * t + 1) * 128 + e0 + i] = silu_f(v1);
            }
        }
    }

    // ---- stage 2: msg2 = silu(msg1 @ eW2 + eb2) ----
#pragma unroll
    for (int i = 0; i < 8; i++)
#pragma unroll
        for (int t = 0; t < 4; t++) acc2[i][t] = 0ull;
#pragma unroll
    for (int t = 0; t < 8; t++) rb[t] = eW2[tid + t * 256];
#pragma unroll 1
    for (int c = 0; c < 8; c++) {
        __syncthreads();     // (c==0 also publishes T1)
#pragma unroll
        for (int t = 0; t < 8; t++) Bs[tid + t * 256] = rb[t];
        __syncthreads();
        if (c + 1 < 8) {
#pragma unroll
            for (int t = 0; t < 8; t++) rb[t] = eW2[(c + 1) * 2048 + tid + t * 256];
        }
        mm_chunk16(T1 + c * 16 * 128, Bs, e0, j0, acc2);
    }
    // epilogue: silu, scatter into agg[receiver], stash msg2 in T2
    {
        float bj[8];
#pragma unroll
        for (int j = 0; j < 8; j++) bj[j] = eb2[j0 + j];
#pragma unroll
        for (int i = 0; i < 8; i++) {
            int ge = ebase + e0 + i;
            bool valid = ge < E;
            int r = re[e0 + i];
#pragma unroll
            for (int t = 0; t < 4; t++) {
                float2 v = unpack2(acc2[i][t]);
                float v0 = silu_f(v.x + bj[2 * t]);
                float v1 = silu_f(v.y + bj[2 * t + 1]);
                T2[(j0 + 2 * t) * 128 + e0 + i]     = v0;
                T2[(j0 + 2 * t + 1) * 128 + e0 + i] = v1;
                if (valid) {
                    atomicAdd(&g_agg[r * 128 + j0 + 2 * t], v0);
                    atomicAdd(&g_agg[r * 128 + j0 + 2 * t + 1], v1);
                }
            }
        }
    }

    // ---- stage 3: p1 = silu(msg2 @ pW1 + pb1); pc = p1 @ pW2 ----
#pragma unroll
    for (int i = 0; i < 8; i++)
#pragma unroll
        for (int t = 0; t < 4; t++) acc2[i][t] = 0ull;
#pragma unroll
    for (int t = 0; t < 8; t++) rb[t] = pW1[tid + t * 256];
#pragma unroll 1
    for (int c = 0; c < 8; c++) {
        __syncthreads();     // (c==0 also publishes T2)
#pragma unroll
        for (int t = 0; t < 8; t++) Bs[tid + t * 256] = rb[t];
        __syncthreads();
        if (c + 1 < 8) {
#pragma unroll
            for (int t = 0; t < 8; t++) rb[t] = pW1[(c + 1) * 2048 + tid + t * 256];
        }
        mm_chunk16(T2 + c * 16 * 128, Bs, e0, j0, acc2);
    }
    // epilogue: silu, dot with pW2, reduce pc across column groups
    {
        float bj[8], wj[8];
#pragma unroll
        for (int j = 0; j < 8; j++) {
            bj[j] = pb1[j0 + j];
            wj[j] = pW2[j0 + j];
        }
#pragma unroll
        for (int i = 0; i < 8; i++) {
            float part = 0.f;
#pragma unroll
            for (int t = 0; t < 4; t++) {
                float2 v = unpack2(acc2[i][t]);
                part += silu_f(v.x + bj[2 * t]) * wj[2 * t];
                part += silu_f(v.y + bj[2 * t + 1]) * wj[2 * t + 1];
            }
            red[ty * 128 + e0 + i] = part;
        }
    }
    __syncthreads();
    if (tid < 128) {
        float pc = 0.f;
#pragma unroll
        for (int t = 0; t < 16; t++) pc += red[t * 128 + tid];
        int ge = ebase + tid;
        if (ge < E) {
            int s = se[tid];
#pragma unroll
            for (int d = 0; d < 3; d++) {
                float v = cd[tid * 3 + d] * pc;
                v = fminf(fmaxf(v, -100.f), 100.f);
                atomicAdd(&g_pacc[s * 3 + d], v);
            }
        }
    }
}

// ---------------------------------------------------------------------------
// Node kernel: per tile of 128 nodes
//   x = silu(concat(h, agg) @ nW1 + nb1) @ nW2 + nb2; h_new = h + x
//   pos_new = pos + pacc
// ---------------------------------------------------------------------------
__global__ __launch_bounds__(256, 1)
void node_kernel(const float* __restrict__ h, const float* __restrict__ pos,
                 const float* __restrict__ nW1, const float* __restrict__ nb1,
                 const float* __restrict__ nW2, const float* __restrict__ nb2,
                 float* __restrict__ out, int N)
{
    extern __shared__ float sm[];
    float* As = sm;           // [16][128]
    float* Bs = As + 2048;    // [16][128]
    float* T1 = Bs + 2048;    // [128][128] k-major

    const int tid = threadIdx.x;
    const int tx = tid & 15, ty = tid >> 4;
    const int e0 = tx * 8, j0 = ty * 8;
    const int nb = blockIdx.x * 128;

    unsigned long long acc2[8][4];
#pragma unroll
    for (int i = 0; i < 8; i++)
#pragma unroll
        for (int t = 0; t < 4; t++) acc2[i][t] = 0ull;

    float ra[8], rb[8];
    // stage 1: K = 256 (h | agg)
#pragma unroll
    for (int t = 0; t < 8; t++) {
        int idx = tid + t * 256;
        int kk = idx >> 7, col = idx & 127;
        int node = nb + col; if (node >= N) node = N - 1;
        ra[t] = h[node * 128 + kk];
        rb[t] = nW1[kk * 128 + col];
    }
#pragma unroll 1
    for (int c = 0; c < 16; c++) {
        __syncthreads();
#pragma unroll
        for (int t = 0; t < 8; t++) {
            int idx = tid + t * 256;
            As[idx] = ra[t];
            Bs[idx] = rb[t];
        }
        __syncthreads();
        if (c + 1 < 16) {
            int kb = (c + 1) * 16;
#pragma unroll
            for (int t = 0; t < 8; t++) {
                int idx = tid + t * 256;
                int kk = idx >> 7, col = idx & 127;
                int k = kb + kk;
                int node = nb + col; if (node >= N) node = N - 1;
                ra[t] = (k < 128) ? h[node * 128 + k]
                                  : g_agg[node * 128 + (k - 128)];
                rb[t] = nW1[k * 128 + col];
            }
        }
        mm_chunk16(As, Bs, e0, j0, acc2);
    }
    {
        float bj[8];
#pragma unroll
        for (int j = 0; j < 8; j++) bj[j] = nb1[j0 + j];
#pragma unroll
        for (int i = 0; i < 8; i++)
#pragma unroll
            for (int t = 0; t < 4; t++) {
                float2 v = unpack2(acc2[i][t]);
                T1[(j0 + 2 * t) * 128 + e0 + i]     = silu_f(v.x + bj[2 * t]);
                T1[(j0 + 2 * t + 1) * 128 + e0 + i] = silu_f(v.y + bj[2 * t + 1]);
            }
    }

    // stage 2: K = 128 -> h_new
#pragma unroll
    for (int i = 0; i < 8; i++)
#pragma unroll
        for (int t = 0; t < 4; t++) acc2[i][t] = 0ull;
#pragma unroll
    for (int t = 0; t < 8; t++) rb[t] = nW2[tid + t * 256];
#pragma unroll 1
    for (int c = 0; c < 8; c++) {
        __syncthreads();
#pragma unroll
        for (int t = 0; t < 8; t++) Bs[tid + t * 256] = rb[t];
        __syncthreads();
        if (c + 1 < 8) {
#pragma unroll
            for (int t = 0; t < 8; t++) rb[t] = nW2[(c + 1) * 2048 + tid + t * 256];
        }
        mm_chunk16(T1 + c * 16 * 128, Bs, e0, j0, acc2);
    }
    {
        float bj[8];
#pragma unroll
        for (int j = 0; j < 8; j++) bj[j] = nb2[j0 + j];
#pragma unroll
        for (int i = 0; i < 8; i++) {
            int node = nb + e0 + i;
            if (node < N) {
#pragma unroll
                for (int t = 0; t < 4; t++) {
                    float2 v = unpack2(acc2[i][t]);
                    out[node * 128 + j0 + 2 * t] =
                        v.x + bj[2 * t] + h[node * 128 + j0 + 2 * t];
                    out[node * 128 + j0 + 2 * t + 1] =
                        v.y + bj[2 * t + 1] + h[node * 128 + j0 + 2 * t + 1];
                }
            }
        }
    }

    // pos_new = pos + pacc
    if (tid < 128) {
        int node = nb + tid;
        if (node < N) {
#pragma unroll
            for (int d = 0; d < 3; d++)
                out[N * 128 + node * 3 + d] =
                    pos[node * 3 + d] + g_pacc[node * 3 + d];
        }
    }
}

extern "C" void kernel_launch(void* const* d_in, const int* in_sizes, int n_in,
                              void* d_out, int out_size)
{
    const float* h   = (const float*)d_in[0];
    const float* pos = (const float*)d_in[1];
    const int*   snd = (const int*)d_in[2];
    const int*   rcv = (const int*)d_in[3];
    const float* eW1 = (const float*)d_in[4];
    const float* eb1 = (const float*)d_in[5];
    const float* eW2 = (const float*)d_in[6];
    const float* eb2 = (const float*)d_in[7];
    const float* nW1 = (const float*)d_in[8];
    const float* nb1 = (const float*)d_in[9];
    const float* nW2 = (const float*)d_in[10];
    const float* nb2 = (const float*)d_in[11];
    const float* pW1 = (const float*)d_in[12];
    const float* pb1 = (const float*)d_in[13];
    const float* pW2 = (const float*)d_in[14];
    float* out = (float*)d_out;

    int N = in_sizes[0] / 128;
    int E = in_sizes[2];

    const int smE = (2048 + 2048 + 16384 + 16384 + 384 + 128 + 2048) * 4 + 256 * 4;
    const int smN = (2048 + 2048 + 16384) * 4;
    cudaFuncSetAttribute(edge_kernel, cudaFuncAttributeMaxDynamicSharedMemorySize, smE);
    cudaFuncSetAttribute(node_kernel, cudaFuncAttributeMaxDynamicSharedMemorySize, smN);

    zero_kernel<<<256, 256>>>(N * 128, N * 3);
    edge_kernel<<<(E + TE - 1) / TE, 256, smE>>>(h, pos, snd, rcv,
                                                 eW1, eb1, eW2, eb2,
                                                 pW1, pb1, pW2, E);
    node_kernel<<<(N + 127) / 128, 256, smN>>>(h, pos, nW1, nb1, nW2, nb2, out, N);
}

// round 11
// speedup vs baseline: 2.0006x; 1.9826x over previous
#include <cuda_runtime.h>
#include <cuda_bf16.h>
#include <math.h>
#include <cstdint>

#define NMAX 50000

// ---------------------------------------------------------------------------
// Device scratch (allocation-free rule)
// ---------------------------------------------------------------------------
__device__ float g_agg[NMAX * 128];   // per-node aggregated messages
__device__ float g_pacc[NMAX * 3];    // per-node position correction
__device__ __nv_bfloat16 g_h_hi[NMAX * 128];
__device__ __nv_bfloat16 g_h_lo[NMAX * 128];
__device__ __nv_bfloat16 g_eW1t_hi[128 * 256];  // [n][k] transposed eW1 (k<256)
__device__ __nv_bfloat16 g_eW1t_lo[128 * 256];
__device__ __nv_bfloat16 g_eW2t_hi[128 * 128];  // [n][k]
__device__ __nv_bfloat16 g_eW2t_lo[128 * 128];
__device__ __nv_bfloat16 g_pW1t_hi[128 * 128];  // [n][k]
__device__ __nv_bfloat16 g_pW1t_lo[128 * 128];

__device__ __forceinline__ float silu_f(float x) {
    return x / (1.0f + __expf(-x));
}

// ---- packed f32x2 helpers (node kernel) ----
__device__ __forceinline__ unsigned long long dup2(float x) {
    unsigned long long r;
    asm("mov.b64 %0, {%1, %1};" : "=l"(r) : "f"(x));
    return r;
}
__device__ __forceinline__ void fma2(unsigned long long& d,
                                     unsigned long long a,
                                     unsigned long long b) {
    asm("fma.rn.f32x2 %0, %1, %2, %0;" : "+l"(d) : "l"(a), "l"(b));
}
__device__ __forceinline__ float2 unpack2(unsigned long long v) {
    float2 f;
    asm("mov.b64 {%0, %1}, %2;" : "=f"(f.x), "=f"(f.y) : "l"(v));
    return f;
}

__device__ __forceinline__ uint32_t smem_u32(const void* p) {
    uint32_t a;
    asm("{ .reg .u64 t; cvta.to.shared.u64 t, %1; cvt.u32.u64 %0, t; }"
        : "=r"(a) : "l"(p));
    return a;
}

// ---- warp MMA primitives (base-ISA: legal on .target sm_103) ----
__device__ __forceinline__ void ldsm4(uint32_t r[4], uint32_t addr) {
    asm volatile("ldmatrix.sync.aligned.m8n8.x4.shared.b16 {%0,%1,%2,%3}, [%4];"
                 : "=r"(r[0]), "=r"(r[1]), "=r"(r[2]), "=r"(r[3]) : "r"(addr));
}
__device__ __forceinline__ void mma_bf16(float d[4], const uint32_t a[4],
                                         uint32_t b0, uint32_t b1) {
    asm volatile(
        "mma.sync.aligned.m16n8k16.row.col.f32.bf16.bf16.f32 "
        "{%0,%1,%2,%3}, {%4,%5,%6,%7}, {%8,%9}, {%0,%1,%2,%3};"
        : "+f"(d[0]), "+f"(d[1]), "+f"(d[2]), "+f"(d[3])
        : "r"(a[0]), "r"(a[1]), "r"(a[2]), "r"(a[3]), "r"(b0), "r"(b1));
}

// split float pair to bf16 hi/lo packed words
__device__ __forceinline__ void split_pack(float a, float b,
                                           uint32_t& hip, uint32_t& lop) {
    __nv_bfloat16 ah = __float2bfloat16(a);
    __nv_bfloat16 bh = __float2bfloat16(b);
    __nv_bfloat16 al = __float2bfloat16(a - __bfloat162float(ah));
    __nv_bfloat16 bl = __float2bfloat16(b - __bfloat162float(bh));
    __nv_bfloat162 hp, lp;
    hp.x = ah; hp.y = bh; lp.x = al; lp.y = bl;
    hip = *(uint32_t*)&hp;
    lop = *(uint32_t*)&lp;
}

// One 64-deep K window: A frag addresses pre-baked per lane (row stride baked),
// B tiles at stride 144B. 3-pass hi/lo emulation, fp32 accumulate.
__device__ __forceinline__ void mma_win64(uint32_t aH, uint32_t aL,
                                          uint32_t bH, uint32_t bL,
                                          float (*d)[4]) {
#pragma unroll
    for (int kk = 0; kk < 4; kk++) {
        uint32_t ah[4], al[4];
        ldsm4(ah, aH + kk * 32);
        ldsm4(al, aL + kk * 32);
#pragma unroll
        for (int np = 0; np < 8; np++) {
            uint32_t bh[4], bl[4];
            ldsm4(bh, bH + np * (16 * 144) + kk * 32);
            ldsm4(bl, bL + np * (16 * 144) + kk * 32);
            mma_bf16(d[2 * np],     ah, bh[0], bh[1]);
            mma_bf16(d[2 * np],     ah, bl[0], bl[1]);
            mma_bf16(d[2 * np],     al, bh[0], bh[1]);
            mma_bf16(d[2 * np + 1], ah, bh[2], bh[3]);
            mma_bf16(d[2 * np + 1], ah, bl[2], bl[3]);
            mma_bf16(d[2 * np + 1], al, bh[2], bh[3]);
        }
    }
}

// ---------------------------------------------------------------------------
// Prep kernels
// ---------------------------------------------------------------------------
__global__ void zero_kernel(int n_agg, int n_pacc) {
    int i = blockIdx.x * blockDim.x + threadIdx.x;
    int stride = gridDim.x * blockDim.x;
    for (int k = i; k < n_agg; k += stride) g_agg[k] = 0.f;
    for (int k = i; k < n_pacc; k += stride) g_pacc[k] = 0.f;
}

__global__ void prep_kernel(const float* __restrict__ h,
                            const float* __restrict__ eW1,
                            const float* __restrict__ eW2,
                            const float* __restrict__ pW1, int N) {
    int i = blockIdx.x * blockDim.x + threadIdx.x;
    int stride = gridDim.x * blockDim.x;
    for (int k = i; k < N * 128; k += stride) {
        float v = h[k];
        __nv_bfloat16 hi = __float2bfloat16(v);
        g_h_hi[k] = hi;
        g_h_lo[k] = __float2bfloat16(v - __bfloat162float(hi));
    }
    for (int k = i; k < 128 * 256; k += stride) {
        int n = k >> 8, kk = k & 255;
        float v = eW1[kk * 128 + n];
        __nv_bfloat16 hi = __float2bfloat16(v);
        g_eW1t_hi[k] = hi;
        g_eW1t_lo[k] = __float2bfloat16(v - __bfloat162float(hi));
    }
    for (int k = i; k < 128 * 128; k += stride) {
        int n = k >> 7, kk = k & 127;
        float v = eW2[kk * 128 + n];
        __nv_bfloat16 hi = __float2bfloat16(v);
        g_eW2t_hi[k] = hi;
        g_eW2t_lo[k] = __float2bfloat16(v - __bfloat162float(hi));
        float w = pW1[kk * 128 + n];
        __nv_bfloat16 wh = __float2bfloat16(w);
        g_pW1t_hi[k] = wh;
        g_pW1t_lo[k] = __float2bfloat16(w - __bfloat162float(wh));
    }
}

// ---------------------------------------------------------------------------
// Edge kernel: 128 edges/block, 256 threads (8 warps x 16 edge-rows).
// A/B tiles: bf16, row-padded 144B (64k window) / 272B (128k msg buffers)
// so ldmatrix's 8 row-addresses land in distinct 16B phases (conflict-free).
// ---------------------------------------------------------------------------
#define OFF_AH 0
#define OFF_AL 18432
#define OFF_BH 36864
#define OFF_BL 55296
#define OFF_MH 73728
#define OFF_ML 108544
#define OFF_SE 143360
#define OFF_RE 143872
#define OFF_RAD 144384
#define OFF_CD 144896
#define OFF_EB1 146432
#define OFF_EB2 146944
#define OFF_PB1 147456
#define OFF_PW2 147968
#define OFF_W1R 148480
#define SM_TOTAL 148992

__global__ __launch_bounds__(256, 1)
void edge_kernel(const float* __restrict__ pos,
                 const int* __restrict__ snd, const int* __restrict__ rcv,
                 const float* __restrict__ eW1, const float* __restrict__ eb1,
                 const float* __restrict__ eb2,
                 const float* __restrict__ pb1, const float* __restrict__ pW2,
                 int E)
{
    extern __shared__ char sm[];
    const uint32_t smb = smem_u32(sm);
    const int tid = threadIdx.x;
    const int lane = tid & 31, w = tid >> 5;
    const int ebase = blockIdx.x * 128;

    int* se = (int*)(sm + OFF_SE);
    int* re = (int*)(sm + OFF_RE);
    float* rad = (float*)(sm + OFF_RAD);
    float* cd = (float*)(sm + OFF_CD);
    float* s_eb1 = (float*)(sm + OFF_EB1);
    float* s_eb2 = (float*)(sm + OFF_EB2);
    float* s_pb1 = (float*)(sm + OFF_PB1);
    float* s_pw2 = (float*)(sm + OFF_PW2);
    float* s_w1r = (float*)(sm + OFF_W1R);

    if (tid < 128) {
        int ge = ebase + tid; if (ge >= E) ge = E - 1;
        int s = snd[ge], r = rcv[ge];
        se[tid] = s; re[tid] = r;
        float dx = pos[s * 3 + 0] - pos[r * 3 + 0];
        float dy = pos[s * 3 + 1] - pos[r * 3 + 1];
        float dz = pos[s * 3 + 2] - pos[r * 3 + 2];
        cd[tid * 3 + 0] = dx; cd[tid * 3 + 1] = dy; cd[tid * 3 + 2] = dz;
        rad[tid] = dx * dx + dy * dy + dz * dz;
        s_eb1[tid] = eb1[tid];
        s_eb2[tid] = eb2[tid];
        s_pb1[tid] = pb1[tid];
        s_pw2[tid] = pW2[tid];
        s_w1r[tid] = eW1[256 * 128 + tid];  // radial row of eW1 (kept fp32)
    }
    __syncthreads();

    // ldmatrix lane-address bake.
    // A (m16k16 row-major, 4 frags): m0 rows0-7@k0, m1 rows8-15@k0,
    //   m2 rows0-7@k0+8, m3 rows8-15@k0+8 -> regs (a0,a1,a2,a3).
    const int arow = lane & 15;
    const int akb = (lane >> 4) * 16;
    // B^T [n][k] (col-major B, x4 covers two n-tiles):
    //   m0 n0-7@k0, m1 n0-7@k0+8, m2 n8-15@k0, m3 n8-15@k0+8 -> (b0,b1) x2 tiles
    const int bn = (lane & 7) + ((lane >> 4) << 3);
    const int bkb = ((lane >> 3) & 1) * 16;

    const uint32_t aA_h = smb + OFF_AH + (w * 16 + arow) * 144 + akb;
    const uint32_t aA_l = smb + OFF_AL + (w * 16 + arow) * 144 + akb;
    const uint32_t aM_h = smb + OFF_MH + (w * 16 + arow) * 272 + akb;
    const uint32_t aM_l = smb + OFF_ML + (w * 16 + arow) * 272 + akb;
    const uint32_t aB_h = smb + OFF_BH + bn * 144 + bkb;
    const uint32_t aB_l = smb + OFF_BL + bn * 144 + bkb;

    const int r0 = w * 16 + (lane >> 2);
    const int r1 = r0 + 8;
    const int row2 = tid >> 1, half = tid & 1;

    float d[16][4];
#pragma unroll
    for (int nt = 0; nt < 16; nt++)
#pragma unroll
        for (int q = 0; q < 4; q++) d[nt][q] = 0.f;

    // ================= stage 1: K=256 (sender | receiver features) =========
#pragma unroll 1
    for (int c = 0; c < 4; c++) {
        int node = (c < 2) ? se[row2] : re[row2];
        const uint4* shh = (const uint4*)(g_h_hi + node * 128 + (c & 1) * 64 + half * 32);
        const uint4* shl = (const uint4*)(g_h_lo + node * 128 + (c & 1) * 64 + half * 32);
        const uint4* swh = (const uint4*)(g_eW1t_hi + row2 * 256 + c * 64 + half * 32);
        const uint4* swl = (const uint4*)(g_eW1t_lo + row2 * 256 + c * 64 + half * 32);
        uint4* dah = (uint4*)(sm + OFF_AH + row2 * 144 + half * 64);
        uint4* dal = (uint4*)(sm + OFF_AL + row2 * 144 + half * 64);
        uint4* dbh = (uint4*)(sm + OFF_BH + row2 * 144 + half * 64);
        uint4* dbl = (uint4*)(sm + OFF_BL + row2 * 144 + half * 64);
#pragma unroll
        for (int t = 0; t < 4; t++) {
            dah[t] = shh[t]; dal[t] = shl[t];
            dbh[t] = swh[t]; dbl[t] = swl[t];
        }
        __syncthreads();
        mma_win64(aA_h, aA_l, aB_h, aB_l, d);
        __syncthreads();
    }
    // epilogue 1: + radial*w_r + bias, silu -> msg1 bf16 hi/lo in MH/ML
    {
        float rd0 = rad[r0], rd1 = rad[r1];
#pragma unroll
        for (int nt = 0; nt < 16; nt++) {
            int j = nt * 8 + (lane & 3) * 2;
            float v00 = silu_f(d[nt][0] + rd0 * s_w1r[j] + s_eb1[j]);
            float v01 = silu_f(d[nt][1] + rd0 * s_w1r[j + 1] + s_eb1[j + 1]);
            float v10 = silu_f(d[nt][2] + rd1 * s_w1r[j] + s_eb1[j]);
            float v11 = silu_f(d[nt][3] + rd1 * s_w1r[j + 1] + s_eb1[j + 1]);
            uint32_t hp, lp;
            split_pack(v00, v01, hp, lp);
            *(uint32_t*)(sm + OFF_MH + r0 * 272 + j * 2) = hp;
            *(uint32_t*)(sm + OFF_ML + r0 * 272 + j * 2) = lp;
            split_pack(v10, v11, hp, lp);
            *(uint32_t*)(sm + OFF_MH + r1 * 272 + j * 2) = hp;
            *(uint32_t*)(sm + OFF_ML + r1 * 272 + j * 2) = lp;
        }
    }
    __syncthreads();

    // ================= stage 2: msg2 = silu(msg1 @ eW2 + eb2) ==============
#pragma unroll
    for (int nt = 0; nt < 16; nt++)
#pragma unroll
        for (int q = 0; q < 4; q++) d[nt][q] = 0.f;
#pragma unroll 1
    for (int c = 0; c < 2; c++) {
        const uint4* swh = (const uint4*)(g_eW2t_hi + row2 * 128 + c * 64 + half * 32);
        const uint4* swl = (const uint4*)(g_eW2t_lo + row2 * 128 + c * 64 + half * 32);
        uint4* dbh = (uint4*)(sm + OFF_BH + row2 * 144 + half * 64);
        uint4* dbl = (uint4*)(sm + OFF_BL + row2 * 144 + half * 64);
#pragma unroll
        for (int t = 0; t < 4; t++) { dbh[t] = swh[t]; dbl[t] = swl[t]; }
        __syncthreads();
        mma_win64(aM_h + c * 128, aM_l + c * 128, aB_h, aB_l, d);
        __syncthreads();
    }
    // epilogue 2: silu -> scatter agg[receiver], msg2 back into MH/ML
    {
        bool val0 = (ebase + r0) < E, val1 = (ebase + r1) < E;
        int rn0 = re[r0], rn1 = re[r1];
#pragma unroll
        for (int nt = 0; nt < 16; nt++) {
            int j = nt * 8 + (lane & 3) * 2;
            float v00 = silu_f(d[nt][0] + s_eb2[j]);
            float v01 = silu_f(d[nt][1] + s_eb2[j + 1]);
            float v10 = silu_f(d[nt][2] + s_eb2[j]);
            float v11 = silu_f(d[nt][3] + s_eb2[j + 1]);
            uint32_t hp, lp;
            split_pack(v00, v01, hp, lp);
            *(uint32_t*)(sm + OFF_MH + r0 * 272 + j * 2) = hp;
            *(uint32_t*)(sm + OFF_ML + r0 * 272 + j * 2) = lp;
            split_pack(v10, v11, hp, lp);
            *(uint32_t*)(sm + OFF_MH + r1 * 272 + j * 2) = hp;
            *(uint32_t*)(sm + OFF_ML + r1 * 272 + j * 2) = lp;
            if (val0) {
                atomicAdd(&g_agg[rn0 * 128 + j], v00);
                atomicAdd(&g_agg[rn0 * 128 + j + 1], v01);
            }
            if (val1) {
                atomicAdd(&g_agg[rn1 * 128 + j], v10);
                atomicAdd(&g_agg[rn1 * 128 + j + 1], v11);
            }
        }
    }
    __syncthreads();

    // ================= stage 3: pc = silu(msg2 @ pW1 + pb1) . pW2 ==========
#pragma unroll
    for (int nt = 0; nt < 16; nt++)
#pragma unroll
        for (int q = 0; q < 4; q++) d[nt][q] = 0.f;
#pragma unroll 1
    for (int c = 0; c < 2; c++) {
        const uint4* swh = (const uint4*)(g_pW1t_hi + row2 * 128 + c * 64 + half * 32);
        const uint4* swl = (const uint4*)(g_pW1t_lo + row2 * 128 + c * 64 + half * 32);
        uint4* dbh = (uint4*)(sm + OFF_BH + row2 * 144 + half * 64);
        uint4* dbl = (uint4*)(sm + OFF_BL + row2 * 144 + half * 64);
#pragma unroll
        for (int t = 0; t < 4; t++) { dbh[t] = swh[t]; dbl[t] = swl[t]; }
        __syncthreads();
        mma_win64(aM_h + c * 128, aM_l + c * 128, aB_h, aB_l, d);
        __syncthreads();
    }
    // epilogue 3: quad-reduce pc, scatter position correction
    {
        float p0 = 0.f, p1 = 0.f;
#pragma unroll
        for (int nt = 0; nt < 16; nt++) {
            int j = nt * 8 + (lane & 3) * 2;
            p0 += silu_f(d[nt][0] + s_pb1[j]) * s_pw2[j]
                + silu_f(d[nt][1] + s_pb1[j + 1]) * s_pw2[j + 1];
            p1 += silu_f(d[nt][2] + s_pb1[j]) * s_pw2[j]
                + silu_f(d[nt][3] + s_pb1[j + 1]) * s_pw2[j + 1];
        }
        p0 += __shfl_xor_sync(0xffffffffu, p0, 1);
        p0 += __shfl_xor_sync(0xffffffffu, p0, 2);
        p1 += __shfl_xor_sync(0xffffffffu, p1, 1);
        p1 += __shfl_xor_sync(0xffffffffu, p1, 2);
        float* redpc = (float*)(sm + OFF_AH);  // reuse A region
        if ((lane & 3) == 0) { redpc[r0] = p0; redpc[r1] = p1; }
        __syncthreads();
        if (tid < 128 && (ebase + tid) < E) {
            int s = se[tid];
            float pc = redpc[tid];
#pragma unroll
            for (int dd = 0; dd < 3; dd++) {
                float v = cd[tid * 3 + dd] * pc;
                v = fminf(fmaxf(v, -100.f), 100.f);
                atomicAdd(&g_pacc[s * 3 + dd], v);
            }
        }
    }
}

// ---------------------------------------------------------------------------
// Node kernel (fp32 SIMT, unchanged): per tile of 128 nodes
// ---------------------------------------------------------------------------
__device__ __forceinline__ void mm_chunk16(const float* __restrict__ As,
                                           const float* __restrict__ Bs,
                                           int e0, int j0,
                                           unsigned long long acc2[8][4]) {
#pragma unroll
    for (int kk = 0; kk < 16; kk++) {
        float4 a03 = *(const float4*)&As[kk * 128 + e0];
        float4 a47 = *(const float4*)&As[kk * 128 + e0 + 4];
        ulonglong2 bq0 = *(const ulonglong2*)&Bs[kk * 128 + j0];
        ulonglong2 bq1 = *(const ulonglong2*)&Bs[kk * 128 + j0 + 4];
        unsigned long long b2[4] = {bq0.x, bq0.y, bq1.x, bq1.y};
        float av[8] = {a03.x, a03.y, a03.z, a03.w, a47.x, a47.y, a47.z, a47.w};
#pragma unroll
        for (int i = 0; i < 8; i++) {
            unsigned long long ad = dup2(av[i]);
#pragma unroll
            for (int t = 0; t < 4; t++) fma2(acc2[i][t], ad, b2[t]);
        }
    }
}

__global__ __launch_bounds__(256, 1)
void node_kernel(const float* __restrict__ h, const float* __restrict__ pos,
                 const float* __restrict__ nW1, const float* __restrict__ nb1,
                 const float* __restrict__ nW2, const float* __restrict__ nb2,
                 float* __restrict__ out, int N)
{
    extern __shared__ float smf[];
    float* As = smf;          // [16][128]
    float* Bs = As + 2048;    // [16][128]
    float* T1 = Bs + 2048;    // [128][128] k-major

    const int tid = threadIdx.x;
    const int tx = tid & 15, ty = tid >> 4;
    const int e0 = tx * 8, j0 = ty * 8;
    const int nb = blockIdx.x * 128;

    unsigned long long acc2[8][4];
#pragma unroll
    for (int i = 0; i < 8; i++)
#pragma unroll
        for (int t = 0; t < 4; t++) acc2[i][t] = 0ull;

    float ra[8], rb[8];
#pragma unroll
    for (int t = 0; t < 8; t++) {
        int idx = tid + t * 256;
        int kk = idx >> 7, col = idx & 127;
        int node = nb + col; if (node >= N) node = N - 1;
        ra[t] = h[node * 128 + kk];
        rb[t] = nW1[kk * 128 + col];
    }
#pragma unroll 1
    for (int c = 0; c < 16; c++) {
        __syncthreads();
#pragma unroll
        for (int t = 0; t < 8; t++) {
            int idx = tid + t * 256;
            As[idx] = ra[t];
            Bs[idx] = rb[t];
        }
        __syncthreads();
        if (c + 1 < 16) {
            int kb = (c + 1) * 16;
#pragma unroll
            for (int t = 0; t < 8; t++) {
                int idx = tid + t * 256;
                int kk = idx >> 7, col = idx & 127;
                int k = kb + kk;
                int node = nb + col; if (node >= N) node = N - 1;
                ra[t] = (k < 128) ? h[node * 128 + k]
                                  : g_agg[node * 128 + (k - 128)];
                rb[t] = nW1[k * 128 + col];
            }
        }
        mm_chunk16(As, Bs, e0, j0, acc2);
    }
    {
        float bj[8];
#pragma unroll
        for (int j = 0; j < 8; j++) bj[j] = nb1[j0 + j];
#pragma unroll
        for (int i = 0; i < 8; i++)
#pragma unroll
            for (int t = 0; t < 4; t++) {
                float2 v = unpack2(acc2[i][t]);
                T1[(j0 + 2 * t) * 128 + e0 + i]     = silu_f(v.x + bj[2 * t]);
                T1[(j0 + 2 * t + 1) * 128 + e0 + i] = silu_f(v.y + bj[2 * t + 1]);
            }
    }

#pragma unroll
    for (int i = 0; i < 8; i++)
#pragma unroll
        for (int t = 0; t < 4; t++) acc2[i][t] = 0ull;
#pragma unroll
    for (int t = 0; t < 8; t++) rb[t] = nW2[tid + t * 256];
#pragma unroll 1
    for (int c = 0; c < 8; c++) {
        __syncthreads();
#pragma unroll
        for (int t = 0; t < 8; t++) Bs[tid + t * 256] = rb[t];
        __syncthreads();
        if (c + 1 < 8) {
#pragma unroll
            for (int t = 0; t < 8; t++) rb[t] = nW2[(c + 1) * 2048 + tid + t * 256];
        }
        mm_chunk16(T1 + c * 16 * 128, Bs, e0, j0, acc2);
    }
    {
        float bj[8];
#pragma unroll
        for (int j = 0; j < 8; j++) bj[j] = nb2[j0 + j];
#pragma unroll
        for (int i = 0; i < 8; i++) {
            int node = nb + e0 + i;
            if (node < N) {
#pragma unroll
                for (int t = 0; t < 4; t++) {
                    float2 v = unpack2(acc2[i][t]);
                    out[node * 128 + j0 + 2 * t] =
                        v.x + bj[2 * t] + h[node * 128 + j0 + 2 * t];
                    out[node * 128 + j0 + 2 * t + 1] =
                        v.y + bj[2 * t + 1] + h[node * 128 + j0 + 2 * t + 1];
                }
            }
        }
    }

    if (tid < 128) {
        int node = nb + tid;
        if (node < N) {
#pragma unroll
            for (int dd = 0; dd < 3; dd++)
                out[N * 128 + node * 3 + dd] =
                    pos[node * 3 + dd] + g_pacc[node * 3 + dd];
        }
    }
}

extern "C" void kernel_launch(void* const* d_in, const int* in_sizes, int n_in,
                              void* d_out, int out_size)
{
    const float* h   = (const float*)d_in[0];
    const float* pos = (const float*)d_in[1];
    const int*   snd = (const int*)d_in[2];
    const int*   rcv = (const int*)d_in[3];
    const float* eW1 = (const float*)d_in[4];
    const float* eb1 = (const float*)d_in[5];
    const float* eW2 = (const float*)d_in[6];
    const float* eb2 = (const float*)d_in[7];
    const float* nW1 = (const float*)d_in[8];
    const float* nb1 = (const float*)d_in[9];
    const float* nW2 = (const float*)d_in[10];
    const float* nb2 = (const float*)d_in[11];
    const float* pW1 = (const float*)d_in[12];
    const float* pb1 = (const float*)d_in[13];
    const float* pW2 = (const float*)d_in[14];
    float* out = (float*)d_out;

    int N = in_sizes[0] / 128;
    int E = in_sizes[2];

    const int smN = (2048 + 2048 + 16384) * 4;
    cudaFuncSetAttribute(edge_kernel, cudaFuncAttributeMaxDynamicSharedMemorySize, SM_TOTAL);
    cudaFuncSetAttribute(node_kernel, cudaFuncAttributeMaxDynamicSharedMemorySize, smN);

    zero_kernel<<<256, 256>>>(N * 128, N * 3);
    prep_kernel<<<512, 256>>>(h, eW1, eW2, pW1, N);
    edge_kernel<<<(E + 127) / 128, 256, SM_TOTAL>>>(pos, snd, rcv,
                                                    eW1, eb1, eb2,
                                                    pb1, pW2, E);
    node_kernel<<<(N + 127) / 128, 256, smN>>>(h, pos, nW1, nb1, nW2, nb2, out, N);
}

// round 12
// speedup vs baseline: 2.3606x; 1.1799x over previous
#include <cuda_runtime.h>
#include <cuda_bf16.h>
#include <math.h>
#include <cstdint>

#define NMAX 50000

// ---------------------------------------------------------------------------
// Device scratch (allocation-free rule)
// ---------------------------------------------------------------------------
__device__ float g_agg[NMAX * 128];   // per-node aggregated messages
__device__ float g_pacc[NMAX * 3];    // per-node position correction
__device__ __nv_bfloat16 g_h_hi[NMAX * 128];
__device__ __nv_bfloat16 g_h_lo[NMAX * 128];
__device__ __nv_bfloat16 g_eW1t_hi[128 * 256];  // [n][k] transposed eW1 (k<256)
__device__ __nv_bfloat16 g_eW1t_lo[128 * 256];
__device__ __nv_bfloat16 g_eW2t_hi[128 * 128];  // [n][k]
__device__ __nv_bfloat16 g_eW2t_lo[128 * 128];
__device__ __nv_bfloat16 g_pW1t_hi[128 * 128];  // [n][k]
__device__ __nv_bfloat16 g_pW1t_lo[128 * 128];

__device__ __forceinline__ float silu_f(float x) {
    return x * __fdividef(1.0f, 1.0f + __expf(-x));
}

// ---- packed f32x2 helpers (node kernel) ----
__device__ __forceinline__ unsigned long long dup2(float x) {
    unsigned long long r;
    asm("mov.b64 %0, {%1, %1};" : "=l"(r) : "f"(x));
    return r;
}
__device__ __forceinline__ void fma2(unsigned long long& d,
                                     unsigned long long a,
                                     unsigned long long b) {
    asm("fma.rn.f32x2 %0, %1, %2, %0;" : "+l"(d) : "l"(a), "l"(b));
}
__device__ __forceinline__ float2 unpack2(unsigned long long v) {
    float2 f;
    asm("mov.b64 {%0, %1}, %2;" : "=f"(f.x), "=f"(f.y) : "l"(v));
    return f;
}

__device__ __forceinline__ uint32_t smem_u32(const void* p) {
    uint32_t a;
    asm("{ .reg .u64 t; cvta.to.shared.u64 t, %1; cvt.u32.u64 %0, t; }"
        : "=r"(a) : "l"(p));
    return a;
}

// ---- base-ISA async copy + vector reduction (legal on .target sm_103) ----
__device__ __forceinline__ void cpa16(uint32_t smem, const void* g) {
    asm volatile("cp.async.cg.shared.global [%0], [%1], 16;"
                 :: "r"(smem), "l"(g) : "memory");
}
#define CPA_COMMIT() asm volatile("cp.async.commit_group;" ::: "memory")
#define CPA_WAIT(n)  asm volatile("cp.async.wait_group %0;" :: "n"(n) : "memory")

__device__ __forceinline__ void red2(float* addr, float a, float b) {
    asm volatile("red.global.add.v2.f32 [%0], {%1, %2};"
                 :: "l"(addr), "f"(a), "f"(b) : "memory");
}

// ---- warp MMA primitives ----
__device__ __forceinline__ void ldsm4(uint32_t r[4], uint32_t addr) {
    asm volatile("ldmatrix.sync.aligned.m8n8.x4.shared.b16 {%0,%1,%2,%3}, [%4];"
                 : "=r"(r[0]), "=r"(r[1]), "=r"(r[2]), "=r"(r[3]) : "r"(addr));
}
__device__ __forceinline__ void mma_bf16(float d[4], const uint32_t a[4],
                                         uint32_t b0, uint32_t b1) {
    asm volatile(
        "mma.sync.aligned.m16n8k16.row.col.f32.bf16.bf16.f32 "
        "{%0,%1,%2,%3}, {%4,%5,%6,%7}, {%8,%9}, {%0,%1,%2,%3};"
        : "+f"(d[0]), "+f"(d[1]), "+f"(d[2]), "+f"(d[3])
        : "r"(a[0]), "r"(a[1]), "r"(a[2]), "r"(a[3]), "r"(b0), "r"(b1));
}

// split float pair to bf16 hi/lo packed words
__device__ __forceinline__ void split_pack(float a, float b,
                                           uint32_t& hip, uint32_t& lop) {
    __nv_bfloat16 ah = __float2bfloat16(a);
    __nv_bfloat16 bh = __float2bfloat16(b);
    __nv_bfloat16 al = __float2bfloat16(a - __bfloat162float(ah));
    __nv_bfloat16 bl = __float2bfloat16(b - __bfloat162float(bh));
    __nv_bfloat162 hp, lp;
    hp.x = ah; hp.y = bh; lp.x = al; lp.y = bl;
    hip = *(uint32_t*)&hp;
    lop = *(uint32_t*)&lp;
}

// One 64-deep K window: 3-pass hi/lo emulation, fp32 accumulate.
__device__ __forceinline__ void mma_win64(uint32_t aH, uint32_t aL,
                                          uint32_t bH, uint32_t bL,
                                          float (*d)[4]) {
#pragma unroll
    for (int kk = 0; kk < 4; kk++) {
        uint32_t ah[4], al[4];
        ldsm4(ah, aH + kk * 32);
        ldsm4(al, aL + kk * 32);
#pragma unroll
        for (int np = 0; np < 8; np++) {
            uint32_t bh[4], bl[4];
            ldsm4(bh, bH + np * (16 * 144) + kk * 32);
            ldsm4(bl, bL + np * (16 * 144) + kk * 32);
            mma_bf16(d[2 * np],     ah, bh[0], bh[1]);
            mma_bf16(d[2 * np],     ah, bl[0], bl[1]);
            mma_bf16(d[2 * np],     al, bh[0], bh[1]);
            mma_bf16(d[2 * np + 1], ah, bh[2], bh[3]);
            mma_bf16(d[2 * np + 1], ah, bl[2], bl[3]);
            mma_bf16(d[2 * np + 1], al, bh[2], bh[3]);
        }
    }
}

// ---------------------------------------------------------------------------
// Prep kernels
// ---------------------------------------------------------------------------
__global__ void zero_kernel(int n_agg, int n_pacc) {
    int i = blockIdx.x * blockDim.x + threadIdx.x;
    int stride = gridDim.x * blockDim.x;
    for (int k = i; k < n_agg; k += stride) g_agg[k] = 0.f;
    for (int k = i; k < n_pacc; k += stride) g_pacc[k] = 0.f;
}

__global__ void prep_kernel(const float* __restrict__ h,
                            const float* __restrict__ eW1,
                            const float* __restrict__ eW2,
                            const float* __restrict__ pW1, int N) {
    int i = blockIdx.x * blockDim.x + threadIdx.x;
    int stride = gridDim.x * blockDim.x;
    for (int k = i; k < N * 128; k += stride) {
        float v = h[k];
        __nv_bfloat16 hi = __float2bfloat16(v);
        g_h_hi[k] = hi;
        g_h_lo[k] = __float2bfloat16(v - __bfloat162float(hi));
    }
    for (int k = i; k < 128 * 256; k += stride) {
        int n = k >> 8, kk = k & 255;
        float v = eW1[kk * 128 + n];
        __nv_bfloat16 hi = __float2bfloat16(v);
        g_eW1t_hi[k] = hi;
        g_eW1t_lo[k] = __float2bfloat16(v - __bfloat162float(hi));
    }
    for (int k = i; k < 128 * 128; k += stride) {
        int n = k >> 7, kk = k & 127;
        float v = eW2[kk * 128 + n];
        __nv_bfloat16 hi = __float2bfloat16(v);
        g_eW2t_hi[k] = hi;
        g_eW2t_lo[k] = __float2bfloat16(v - __bfloat162float(hi));
        float w = pW1[kk * 128 + n];
        __nv_bfloat16 wh = __float2bfloat16(w);
        g_pW1t_hi[k] = wh;
        g_pW1t_lo[k] = __float2bfloat16(w - __bfloat162float(wh));
    }
}

// ---------------------------------------------------------------------------
// Edge kernel: 128 edges/block, 256 threads (8 warps x 16 edge-rows).
// Double-buffered cp.async pipeline on A/B window tiles; stage-2/3 weight
// loads overlap the preceding epilogue. 144B/272B row pads -> conflict-free
// ldmatrix.
// ---------------------------------------------------------------------------
#define OFF_A0H 0
#define OFF_A0L 18432
#define OFF_A1H 36864
#define OFF_A1L 55296
#define OFF_B0H 73728
#define OFF_B0L 92160
#define OFF_B1H 110592
#define OFF_B1L 129024
#define OFF_MH  147456
#define OFF_ML  182272
#define OFF_SE  217088
#define OFF_RE  217600
#define OFF_RAD 218112
#define OFF_CD  218624
#define OFF_EB1 220160
#define OFF_EB2 220672
#define OFF_PB1 221184
#define OFF_PW2 221696
#define OFF_W1R 222208
#define SM_TOTAL 222720

__global__ __launch_bounds__(256, 1)
void edge_kernel(const float* __restrict__ pos,
                 const int* __restrict__ snd, const int* __restrict__ rcv,
                 const float* __restrict__ eW1, const float* __restrict__ eb1,
                 const float* __restrict__ eb2,
                 const float* __restrict__ pb1, const float* __restrict__ pW2,
                 int E)
{
    extern __shared__ char sm[];
    const uint32_t smb = smem_u32(sm);
    const int tid = threadIdx.x;
    const int lane = tid & 31, w = tid >> 5;
    const int ebase = blockIdx.x * 128;

    int* se = (int*)(sm + OFF_SE);
    int* re = (int*)(sm + OFF_RE);
    float* rad = (float*)(sm + OFF_RAD);
    float* cd = (float*)(sm + OFF_CD);
    float* s_eb1 = (float*)(sm + OFF_EB1);
    float* s_eb2 = (float*)(sm + OFF_EB2);
    float* s_pb1 = (float*)(sm + OFF_PB1);
    float* s_pw2 = (float*)(sm + OFF_PW2);
    float* s_w1r = (float*)(sm + OFF_W1R);

    if (tid < 128) {
        int ge = ebase + tid; if (ge >= E) ge = E - 1;
        int s = snd[ge], r = rcv[ge];
        se[tid] = s; re[tid] = r;
        float dx = pos[s * 3 + 0] - pos[r * 3 + 0];
        float dy = pos[s * 3 + 1] - pos[r * 3 + 1];
        float dz = pos[s * 3 + 2] - pos[r * 3 + 2];
        cd[tid * 3 + 0] = dx; cd[tid * 3 + 1] = dy; cd[tid * 3 + 2] = dz;
        rad[tid] = dx * dx + dy * dy + dz * dz;
        s_eb1[tid] = eb1[tid];
        s_eb2[tid] = eb2[tid];
        s_pb1[tid] = pb1[tid];
        s_pw2[tid] = pW2[tid];
        s_w1r[tid] = eW1[256 * 128 + tid];  // radial row of eW1 (kept fp32)
    }
    __syncthreads();

    // ldmatrix lane-address bake (same fragment mapping as R11).
    const int arow = lane & 15;
    const int akb = (lane >> 4) * 16;
    const int bn = (lane & 7) + ((lane >> 4) << 3);
    const int bkb = ((lane >> 3) & 1) * 16;

    const uint32_t aA_h[2] = {smb + OFF_A0H + (w * 16 + arow) * 144 + akb,
                              smb + OFF_A1H + (w * 16 + arow) * 144 + akb};
    const uint32_t aA_l[2] = {smb + OFF_A0L + (w * 16 + arow) * 144 + akb,
                              smb + OFF_A1L + (w * 16 + arow) * 144 + akb};
    const uint32_t aB_h[2] = {smb + OFF_B0H + bn * 144 + bkb,
                              smb + OFF_B1H + bn * 144 + bkb};
    const uint32_t aB_l[2] = {smb + OFF_B0L + bn * 144 + bkb,
                              smb + OFF_B1L + bn * 144 + bkb};
    const uint32_t aM_h = smb + OFF_MH + (w * 16 + arow) * 272 + akb;
    const uint32_t aM_l = smb + OFF_ML + (w * 16 + arow) * 272 + akb;

    const int r0 = w * 16 + (lane >> 2);
    const int r1 = r0 + 8;
    const int row2 = tid >> 1, half = tid & 1;

    // copy-issue destinations per buffer (this thread's half-row)
    const uint32_t dstAH[2] = {smb + OFF_A0H + row2 * 144 + half * 64,
                               smb + OFF_A1H + row2 * 144 + half * 64};
    const uint32_t dstAL[2] = {smb + OFF_A0L + row2 * 144 + half * 64,
                               smb + OFF_A1L + row2 * 144 + half * 64};
    const uint32_t dstBH[2] = {smb + OFF_B0H + row2 * 144 + half * 64,
                               smb + OFF_B1H + row2 * 144 + half * 64};
    const uint32_t dstBL[2] = {smb + OFF_B0L + row2 * 144 + half * 64,
                               smb + OFF_B1L + row2 * 144 + half * 64};

    float d[16][4];
#pragma unroll
    for (int nt = 0; nt < 16; nt++)
#pragma unroll
        for (int q = 0; q < 4; q++) d[nt][q] = 0.f;

    // ================= stage 1: K=256 (sender | receiver features) =========
    // pipelined: issue window c+1 while MMAing window c
    {
        // issue window 0
        {
            int node = se[row2];
            const __nv_bfloat16* shh = g_h_hi + node * 128 + half * 32;
            const __nv_bfloat16* shl = g_h_lo + node * 128 + half * 32;
            const __nv_bfloat16* swh = g_eW1t_hi + row2 * 256 + half * 32;
            const __nv_bfloat16* swl = g_eW1t_lo + row2 * 256 + half * 32;
#pragma unroll
            for (int t = 0; t < 4; t++) {
                cpa16(dstAH[0] + t * 16, shh + t * 8);
                cpa16(dstAL[0] + t * 16, shl + t * 8);
                cpa16(dstBH[0] + t * 16, swh + t * 8);
                cpa16(dstBL[0] + t * 16, swl + t * 8);
            }
            CPA_COMMIT();
        }
#pragma unroll 1
        for (int c = 0; c < 4; c++) {
            if (c < 3) {
                int cn = c + 1;
                int buf = cn & 1;
                int node = (cn < 2) ? se[row2] : re[row2];
                const __nv_bfloat16* shh = g_h_hi + node * 128 + (cn & 1) * 64 + half * 32;
                const __nv_bfloat16* shl = g_h_lo + node * 128 + (cn & 1) * 64 + half * 32;
                const __nv_bfloat16* swh = g_eW1t_hi + row2 * 256 + cn * 64 + half * 32;
                const __nv_bfloat16* swl = g_eW1t_lo + row2 * 256 + cn * 64 + half * 32;
#pragma unroll
                for (int t = 0; t < 4; t++) {
                    cpa16(dstAH[buf] + t * 16, shh + t * 8);
                    cpa16(dstAL[buf] + t * 16, shl + t * 8);
                    cpa16(dstBH[buf] + t * 16, swh + t * 8);
                    cpa16(dstBL[buf] + t * 16, swl + t * 8);
                }
                CPA_COMMIT();
                CPA_WAIT(1);
            } else {
                CPA_WAIT(0);
            }
            __syncthreads();
            int b = c & 1;
            mma_win64(aA_h[b], aA_l[b], aB_h[b], aB_l[b], d);
            __syncthreads();
        }
    }

    // prefetch stage-2 B (eW2t, both windows) -- overlaps epilogue 1
    {
#pragma unroll
        for (int c = 0; c < 2; c++) {
            const __nv_bfloat16* swh = g_eW2t_hi + row2 * 128 + c * 64 + half * 32;
            const __nv_bfloat16* swl = g_eW2t_lo + row2 * 128 + c * 64 + half * 32;
#pragma unroll
            for (int t = 0; t < 4; t++) {
                cpa16(dstBH[c] + t * 16, swh + t * 8);
                cpa16(dstBL[c] + t * 16, swl + t * 8);
            }
        }
        CPA_COMMIT();
    }

    // epilogue 1: + radial*w_r + bias, silu -> msg1 bf16 hi/lo in MH/ML
    {
        float rd0 = rad[r0], rd1 = rad[r1];
#pragma unroll
        for (int nt = 0; nt < 16; nt++) {
            int j = nt * 8 + (lane & 3) * 2;
            float v00 = silu_f(d[nt][0] + rd0 * s_w1r[j] + s_eb1[j]);
            float v01 = silu_f(d[nt][1] + rd0 * s_w1r[j + 1] + s_eb1[j + 1]);
            float v10 = silu_f(d[nt][2] + rd1 * s_w1r[j] + s_eb1[j]);
            float v11 = silu_f(d[nt][3] + rd1 * s_w1r[j + 1] + s_eb1[j + 1]);
            uint32_t hp, lp;
            split_pack(v00, v01, hp, lp);
            *(uint32_t*)(sm + OFF_MH + r0 * 272 + j * 2) = hp;
            *(uint32_t*)(sm + OFF_ML + r0 * 272 + j * 2) = lp;
            split_pack(v10, v11, hp, lp);
            *(uint32_t*)(sm + OFF_MH + r1 * 272 + j * 2) = hp;
            *(uint32_t*)(sm + OFF_ML + r1 * 272 + j * 2) = lp;
        }
    }
    CPA_WAIT(0);
    __syncthreads();

    // ================= stage 2: msg2 = silu(msg1 @ eW2 + eb2) ==============
#pragma unroll
    for (int nt = 0; nt < 16; nt++)
#pragma unroll
        for (int q = 0; q < 4; q++) d[nt][q] = 0.f;
    mma_win64(aM_h,       aM_l,       aB_h[0], aB_l[0], d);
    mma_win64(aM_h + 128, aM_l + 128, aB_h[1], aB_l[1], d);
    __syncthreads();   // all reads of MH/ML + B bufs done

    // prefetch stage-3 B (pW1t) -- overlaps epilogue 2
    {
#pragma unroll
        for (int c = 0; c < 2; c++) {
            const __nv_bfloat16* swh = g_pW1t_hi + row2 * 128 + c * 64 + half * 32;
            const __nv_bfloat16* swl = g_pW1t_lo + row2 * 128 + c * 64 + half * 32;
#pragma unroll
            for (int t = 0; t < 4; t++) {
                cpa16(dstBH[c] + t * 16, swh + t * 8);
                cpa16(dstBL[c] + t * 16, swl + t * 8);
            }
        }
        CPA_COMMIT();
    }

    // epilogue 2: silu -> vector-red into agg[receiver], msg2 back to MH/ML
    {
        bool val0 = (ebase + r0) < E, val1 = (ebase + r1) < E;
        int rn0 = re[r0], rn1 = re[r1];
#pragma unroll
        for (int nt = 0; nt < 16; nt++) {
            int j = nt * 8 + (lane & 3) * 2;
            float v00 = silu_f(d[nt][0] + s_eb2[j]);
            float v01 = silu_f(d[nt][1] + s_eb2[j + 1]);
            float v10 = silu_f(d[nt][2] + s_eb2[j]);
            float v11 = silu_f(d[nt][3] + s_eb2[j + 1]);
            uint32_t hp, lp;
            split_pack(v00, v01, hp, lp);
            *(uint32_t*)(sm + OFF_MH + r0 * 272 + j * 2) = hp;
            *(uint32_t*)(sm + OFF_ML + r0 * 272 + j * 2) = lp;
            split_pack(v10, v11, hp, lp);
            *(uint32_t*)(sm + OFF_MH + r1 * 272 + j * 2) = hp;
            *(uint32_t*)(sm + OFF_ML + r1 * 272 + j * 2) = lp;
            if (val0) red2(&g_agg[rn0 * 128 + j], v00, v01);
            if (val1) red2(&g_agg[rn1 * 128 + j], v10, v11);
        }
    }
    CPA_WAIT(0);
    __syncthreads();

    // ================= stage 3: pc = silu(msg2 @ pW1 + pb1) . pW2 ==========
#pragma unroll
    for (int nt = 0; nt < 16; nt++)
#pragma unroll
        for (int q = 0; q < 4; q++) d[nt][q] = 0.f;
    mma_win64(aM_h,       aM_l,       aB_h[0], aB_l[0], d);
    mma_win64(aM_h + 128, aM_l + 128, aB_h[1], aB_l[1], d);

    // epilogue 3: quad-reduce pc, scatter position correction
    {
        float p0 = 0.f, p1 = 0.f;
#pragma unroll
        for (int nt = 0; nt < 16; nt++) {
            int j = nt * 8 + (lane & 3) * 2;
            p0 += silu_f(d[nt][0] + s_pb1[j]) * s_pw2[j]
                + silu_f(d[nt][1] + s_pb1[j + 1]) * s_pw2[j + 1];
            p1 += silu_f(d[nt][2] + s_pb1[j]) * s_pw2[j]
                + silu_f(d[nt][3] + s_pb1[j + 1]) * s_pw2[j + 1];
        }
        p0 += __shfl_xor_sync(0xffffffffu, p0, 1);
        p0 += __shfl_xor_sync(0xffffffffu, p0, 2);
        p1 += __shfl_xor_sync(0xffffffffu, p1, 1);
        p1 += __shfl_xor_sync(0xffffffffu, p1, 2);
        float* redpc = (float*)(sm + OFF_A0H);  // A buffers dead after stage 1
        __syncthreads();
        if ((lane & 3) == 0) { redpc[r0] = p0; redpc[r1] = p1; }
        __syncthreads();
        if (tid < 128 && (ebase + tid) < E) {
            int s = se[tid];
            float pc = redpc[tid];
#pragma unroll
            for (int dd = 0; dd < 3; dd++) {
                float v = cd[tid * 3 + dd] * pc;
                v = fminf(fmaxf(v, -100.f), 100.f);
                atomicAdd(&g_pacc[s * 3 + dd], v);
            }
        }
    }
}

// ---------------------------------------------------------------------------
// Node kernel (fp32 SIMT, unchanged): per tile of 128 nodes
// ---------------------------------------------------------------------------
__device__ __forceinline__ void mm_chunk16(const float* __restrict__ As,
                                           const float* __restrict__ Bs,
                                           int e0, int j0,
                                           unsigned long long acc2[8][4]) {
#pragma unroll
    for (int kk = 0; kk < 16; kk++) {
        float4 a03 = *(const float4*)&As[kk * 128 + e0];
        float4 a47 = *(const float4*)&As[kk * 128 + e0 + 4];
        ulonglong2 bq0 = *(const ulonglong2*)&Bs[kk * 128 + j0];
        ulonglong2 bq1 = *(const ulonglong2*)&Bs[kk * 128 + j0 + 4];
        unsigned long long b2[4] = {bq0.x, bq0.y, bq1.x, bq1.y};
        float av[8] = {a03.x, a03.y, a03.z, a03.w, a47.x, a47.y, a47.z, a47.w};
#pragma unroll
        for (int i = 0; i < 8; i++) {
            unsigned long long ad = dup2(av[i]);
#pragma unroll
            for (int t = 0; t < 4; t++) fma2(acc2[i][t], ad, b2[t]);
        }
    }
}

__global__ __launch_bounds__(256, 1)
void node_kernel(const float* __restrict__ h, const float* __restrict__ pos,
                 const float* __restrict__ nW1, const float* __restrict__ nb1,
                 const float* __restrict__ nW2, const float* __restrict__ nb2,
                 float* __restrict__ out, int N)
{
    extern __shared__ float smf[];
    float* As = smf;          // [16][128]
    float* Bs = As + 2048;    // [16][128]
    float* T1 = Bs + 2048;    // [128][128] k-major

    const int tid = threadIdx.x;
    const int tx = tid & 15, ty = tid >> 4;
    const int e0 = tx * 8, j0 = ty * 8;
    const int nb = blockIdx.x * 128;

    unsigned long long acc2[8][4];
#pragma unroll
    for (int i = 0; i < 8; i++)
#pragma unroll
        for (int t = 0; t < 4; t++) acc2[i][t] = 0ull;

    float ra[8], rb[8];
#pragma unroll
    for (int t = 0; t < 8; t++) {
        int idx = tid + t * 256;
        int kk = idx >> 7, col = idx & 127;
        int node = nb + col; if (node >= N) node = N - 1;
        ra[t] = h[node * 128 + kk];
        rb[t] = nW1[kk * 128 + col];
    }
#pragma unroll 1
    for (int c = 0; c < 16; c++) {
        __syncthreads();
#pragma unroll
        for (int t = 0; t < 8; t++) {
            int idx = tid + t * 256;
            As[idx] = ra[t];
            Bs[idx] = rb[t];
        }
        __syncthreads();
        if (c + 1 < 16) {
            int kb = (c + 1) * 16;
#pragma unroll
            for (int t = 0; t < 8; t++) {
                int idx = tid + t * 256;
                int kk = idx >> 7, col = idx & 127;
                int k = kb + kk;
                int node = nb + col; if (node >= N) node = N - 1;
                ra[t] = (k < 128) ? h[node * 128 + k]
                                  : g_agg[node * 128 + (k - 128)];
                rb[t] = nW1[k * 128 + col];
            }
        }
        mm_chunk16(As, Bs, e0, j0, acc2);
    }
    {
        float bj[8];
#pragma unroll
        for (int j = 0; j < 8; j++) bj[j] = nb1[j0 + j];
#pragma unroll
        for (int i = 0; i < 8; i++)
#pragma unroll
            for (int t = 0; t < 4; t++) {
                float2 v = unpack2(acc2[i][t]);
                T1[(j0 + 2 * t) * 128 + e0 + i]     = silu_f(v.x + bj[2 * t]);
                T1[(j0 + 2 * t + 1) * 128 + e0 + i] = silu_f(v.y + bj[2 * t + 1]);
            }
    }

#pragma unroll
    for (int i = 0; i < 8; i++)
#pragma unroll
        for (int t = 0; t < 4; t++) acc2[i][t] = 0ull;
#pragma unroll
    for (int t = 0; t < 8; t++) rb[t] = nW2[tid + t * 256];
#pragma unroll 1
    for (int c = 0; c < 8; c++) {
        __syncthreads();
#pragma unroll
        for (int t = 0; t < 8; t++) Bs[tid + t * 256] = rb[t];
        __syncthreads();
        if (c + 1 < 8) {
#pragma unroll
            for (int t = 0; t < 8; t++) rb[t] = nW2[(c + 1) * 2048 + tid + t * 256];
        }
        mm_chunk16(T1 + c * 16 * 128, Bs, e0, j0, acc2);
    }
    {
        float bj[8];
#pragma unroll
        for (int j = 0; j < 8; j++) bj[j] = nb2[j0 + j];
#pragma unroll
        for (int i = 0; i < 8; i++) {
            int node = nb + e0 + i;
            if (node < N) {
#pragma unroll
                for (int t = 0; t < 4; t++) {
                    float2 v = unpack2(acc2[i][t]);
                    out[node * 128 + j0 + 2 * t] =
                        v.x + bj[2 * t] + h[node * 128 + j0 + 2 * t];
                    out[node * 128 + j0 + 2 * t + 1] =
                        v.y + bj[2 * t + 1] + h[node * 128 + j0 + 2 * t + 1];
                }
            }
        }
    }

    if (tid < 128) {
        int node = nb + tid;
        if (node < N) {
#pragma unroll
            for (int dd = 0; dd < 3; dd++)
                out[N * 128 + node * 3 + dd] =
                    pos[node * 3 + dd] + g_pacc[node * 3 + dd];
        }
    }
}

extern "C" void kernel_launch(void* const* d_in, const int* in_sizes, int n_in,
                              void* d_out, int out_size)
{
    const float* h   = (const float*)d_in[0];
    const float* pos = (const float*)d_in[1];
    const int*   snd = (const int*)d_in[2];
    const int*   rcv = (const int*)d_in[3];
    const float* eW1 = (const float*)d_in[4];
    const float* eb1 = (const float*)d_in[5];
    const float* eW2 = (const float*)d_in[6];
    const float* eb2 = (const float*)d_in[7];
    const float* nW1 = (const float*)d_in[8];
    const float* nb1 = (const float*)d_in[9];
    const float* nW2 = (const float*)d_in[10];
    const float* nb2 = (const float*)d_in[11];
    const float* pW1 = (const float*)d_in[12];
    const float* pb1 = (const float*)d_in[13];
    const float* pW2 = (const float*)d_in[14];
    float* out = (float*)d_out;

    int N = in_sizes[0] / 128;
    int E = in_sizes[2];

    const int smN = (2048 + 2048 + 16384) * 4;
    cudaFuncSetAttribute(edge_kernel, cudaFuncAttributeMaxDynamicSharedMemorySize, SM_TOTAL);
    cudaFuncSetAttribute(node_kernel, cudaFuncAttributeMaxDynamicSharedMemorySize, smN);

    zero_kernel<<<256, 256>>>(N * 128, N * 3);
    prep_kernel<<<512, 256>>>(h, eW1, eW2, pW1, N);
    edge_kernel<<<(E + 127) / 128, 256, SM_TOTAL>>>(pos, snd, rcv,
                                                    eW1, eb1, eb2,
                                                    pb1, pW2, E);
    node_kernel<<<(N + 127) / 128, 256, smN>>>(h, pos, nW1, nb1, nW2, nb2, out, N);
}

// round 13
// speedup vs baseline: 2.7216x; 1.1529x over previous
#include <cuda_runtime.h>
#include <cuda_bf16.h>
#include <math.h>
#include <cstdint>

#define NMAX 50000

// ---------------------------------------------------------------------------
// Device scratch (allocation-free rule)
// ---------------------------------------------------------------------------
__device__ float g_agg[NMAX * 128];   // per-node aggregated messages (fp32)
__device__ float g_pacc[NMAX * 3];    // per-node position correction
__device__ __nv_bfloat16 g_agg_hi[NMAX * 128];
__device__ __nv_bfloat16 g_agg_lo[NMAX * 128];
__device__ __nv_bfloat16 g_h_hi[NMAX * 128];
__device__ __nv_bfloat16 g_h_lo[NMAX * 128];
__device__ __nv_bfloat16 g_eW1t_hi[128 * 256];  // [n][k] transposed
__device__ __nv_bfloat16 g_eW1t_lo[128 * 256];
__device__ __nv_bfloat16 g_eW2t_hi[128 * 128];
__device__ __nv_bfloat16 g_eW2t_lo[128 * 128];
__device__ __nv_bfloat16 g_pW1t_hi[128 * 128];
__device__ __nv_bfloat16 g_pW1t_lo[128 * 128];
__device__ __nv_bfloat16 g_nW1t_hi[128 * 256];
__device__ __nv_bfloat16 g_nW1t_lo[128 * 256];
__device__ __nv_bfloat16 g_nW2t_hi[128 * 128];
__device__ __nv_bfloat16 g_nW2t_lo[128 * 128];

__device__ __forceinline__ float silu_f(float x) {
    return x * __fdividef(1.0f, 1.0f + __expf(-x));
}

__device__ __forceinline__ uint32_t smem_u32(const void* p) {
    uint32_t a;
    asm("{ .reg .u64 t; cvta.to.shared.u64 t, %1; cvt.u32.u64 %0, t; }"
        : "=r"(a) : "l"(p));
    return a;
}

// ---- base-ISA async copy + vector reduction ----
__device__ __forceinline__ void cpa16(uint32_t smem, const void* g) {
    asm volatile("cp.async.cg.shared.global [%0], [%1], 16;"
                 :: "r"(smem), "l"(g) : "memory");
}
#define CPA_COMMIT() asm volatile("cp.async.commit_group;" ::: "memory")
#define CPA_WAIT(n)  asm volatile("cp.async.wait_group %0;" :: "n"(n) : "memory")

__device__ __forceinline__ void red2(float* addr, float a, float b) {
    asm volatile("red.global.add.v2.f32 [%0], {%1, %2};"
                 :: "l"(addr), "f"(a), "f"(b) : "memory");
}

// ---- warp MMA primitives ----
__device__ __forceinline__ void ldsm4(uint32_t r[4], uint32_t addr) {
    asm volatile("ldmatrix.sync.aligned.m8n8.x4.shared.b16 {%0,%1,%2,%3}, [%4];"
                 : "=r"(r[0]), "=r"(r[1]), "=r"(r[2]), "=r"(r[3]) : "r"(addr));
}
__device__ __forceinline__ void mma_bf16(float d[4], const uint32_t a[4],
                                         uint32_t b0, uint32_t b1) {
    asm volatile(
        "mma.sync.aligned.m16n8k16.row.col.f32.bf16.bf16.f32 "
        "{%0,%1,%2,%3}, {%4,%5,%6,%7}, {%8,%9}, {%0,%1,%2,%3};"
        : "+f"(d[0]), "+f"(d[1]), "+f"(d[2]), "+f"(d[3])
        : "r"(a[0]), "r"(a[1]), "r"(a[2]), "r"(a[3]), "r"(b0), "r"(b1));
}

__device__ __forceinline__ void split_pack(float a, float b,
                                           uint32_t& hip, uint32_t& lop) {
    __nv_bfloat16 ah = __float2bfloat16(a);
    __nv_bfloat16 bh = __float2bfloat16(b);
    __nv_bfloat16 al = __float2bfloat16(a - __bfloat162float(ah));
    __nv_bfloat16 bl = __float2bfloat16(b - __bfloat162float(bh));
    __nv_bfloat162 hp, lp;
    hp.x = ah; hp.y = bh; lp.x = al; lp.y = bl;
    hip = *(uint32_t*)&hp;
    lop = *(uint32_t*)&lp;
}

// One 64-deep K window, A from SMEM via ldmatrix: 3-pass hi/lo emulation.
__device__ __forceinline__ void mma_win64(uint32_t aH, uint32_t aL,
                                          uint32_t bH, uint32_t bL,
                                          float (*d)[4]) {
#pragma unroll
    for (int kk = 0; kk < 4; kk++) {
        uint32_t ah[4], al[4];
        ldsm4(ah, aH + kk * 32);
        ldsm4(al, aL + kk * 32);
#pragma unroll
        for (int np = 0; np < 8; np++) {
            uint32_t bh[4], bl[4];
            ldsm4(bh, bH + np * (16 * 144) + kk * 32);
            ldsm4(bl, bL + np * (16 * 144) + kk * 32);
            mma_bf16(d[2 * np],     ah, bh[0], bh[1]);
            mma_bf16(d[2 * np],     ah, bl[0], bl[1]);
            mma_bf16(d[2 * np],     al, bh[0], bh[1]);
            mma_bf16(d[2 * np + 1], ah, bh[2], bh[3]);
            mma_bf16(d[2 * np + 1], ah, bl[2], bl[3]);
            mma_bf16(d[2 * np + 1], al, bh[2], bh[3]);
        }
    }
}

// K=128 GEMM with A already in register fragments (D->A identity layout).
__device__ __forceinline__ void mma_regA128(const uint32_t ahi[8][4],
                                            const uint32_t alo[8][4],
                                            const uint32_t bHbase[2],
                                            const uint32_t bLbase[2],
                                            float (*d)[4]) {
#pragma unroll
    for (int c = 0; c < 8; c++) {
        uint32_t bh0 = bHbase[c >> 2] + (c & 3) * 32;
        uint32_t bl0 = bLbase[c >> 2] + (c & 3) * 32;
#pragma unroll
        for (int np = 0; np < 8; np++) {
            uint32_t bh[4], bl[4];
            ldsm4(bh, bh0 + np * (16 * 144));
            ldsm4(bl, bl0 + np * (16 * 144));
            mma_bf16(d[2 * np],     ahi[c], bh[0], bh[1]);
            mma_bf16(d[2 * np],     ahi[c], bl[0], bl[1]);
            mma_bf16(d[2 * np],     alo[c], bh[0], bh[1]);
            mma_bf16(d[2 * np + 1], ahi[c], bh[2], bh[3]);
            mma_bf16(d[2 * np + 1], ahi[c], bl[2], bl[3]);
            mma_bf16(d[2 * np + 1], alo[c], bh[2], bh[3]);
        }
    }
}

// ---------------------------------------------------------------------------
// Prep kernels
// ---------------------------------------------------------------------------
__global__ void zero_kernel(int n_agg, int n_pacc) {
    int i = blockIdx.x * blockDim.x + threadIdx.x;
    int stride = gridDim.x * blockDim.x;
    for (int k = i; k < n_agg; k += stride) g_agg[k] = 0.f;
    for (int k = i; k < n_pacc; k += stride) g_pacc[k] = 0.f;
}

__global__ void prep_kernel(const float* __restrict__ h,
                            const float* __restrict__ eW1,
                            const float* __restrict__ eW2,
                            const float* __restrict__ pW1,
                            const float* __restrict__ nW1,
                            const float* __restrict__ nW2, int N) {
    int i = blockIdx.x * blockDim.x + threadIdx.x;
    int stride = gridDim.x * blockDim.x;
    for (int k = i; k < N * 128; k += stride) {
        float v = h[k];
        __nv_bfloat16 hi = __float2bfloat16(v);
        g_h_hi[k] = hi;
        g_h_lo[k] = __float2bfloat16(v - __bfloat162float(hi));
    }
    for (int k = i; k < 128 * 256; k += stride) {
        int n = k >> 8, kk = k & 255;
        float v = eW1[kk * 128 + n];
        __nv_bfloat16 hi = __float2bfloat16(v);
        g_eW1t_hi[k] = hi;
        g_eW1t_lo[k] = __float2bfloat16(v - __bfloat162float(hi));
        float w = nW1[kk * 128 + n];
        __nv_bfloat16 wh = __float2bfloat16(w);
        g_nW1t_hi[k] = wh;
        g_nW1t_lo[k] = __float2bfloat16(w - __bfloat162float(wh));
    }
    for (int k = i; k < 128 * 128; k += stride) {
        int n = k >> 7, kk = k & 127;
        float v = eW2[kk * 128 + n];
        __nv_bfloat16 hi = __float2bfloat16(v);
        g_eW2t_hi[k] = hi;
        g_eW2t_lo[k] = __float2bfloat16(v - __bfloat162float(hi));
        float w = pW1[kk * 128 + n];
        __nv_bfloat16 wh = __float2bfloat16(w);
        g_pW1t_hi[k] = wh;
        g_pW1t_lo[k] = __float2bfloat16(w - __bfloat162float(wh));
        float u = nW2[kk * 128 + n];
        __nv_bfloat16 uh = __float2bfloat16(u);
        g_nW2t_hi[k] = uh;
        g_nW2t_lo[k] = __float2bfloat16(u - __bfloat162float(uh));
    }
}

__global__ void split_agg_kernel(int n) {
    int i = blockIdx.x * blockDim.x + threadIdx.x;
    int stride = gridDim.x * blockDim.x;
    for (int k = i; k < n; k += stride) {
        float v = g_agg[k];
        __nv_bfloat16 hi = __float2bfloat16(v);
        g_agg_hi[k] = hi;
        g_agg_lo[k] = __float2bfloat16(v - __bfloat162float(hi));
    }
}

// ---------------------------------------------------------------------------
// Edge kernel: 128 edges/block, 256 threads (8 warps x 16 edge-rows).
// Stage 1 A/B from SMEM (cp.async pipelined); stages 2/3 take A directly
// from register fragments (D->A layout identity) — no msg SMEM round-trip.
// ---------------------------------------------------------------------------
#define OFF_A0H 0
#define OFF_A0L 18432
#define OFF_A1H 36864
#define OFF_A1L 55296
#define OFF_B0H 73728
#define OFF_B0L 92160
#define OFF_B1H 110592
#define OFF_B1L 129024
#define OFF_SE  147456
#define OFF_RE  147968
#define OFF_RAD 148480
#define OFF_CD  148992
#define OFF_EB1 150528
#define OFF_EB2 151040
#define OFF_PB1 151552
#define OFF_PW2 152064
#define OFF_W1R 152576
#define OFF_RPC 153088
#define SM_TOTAL 153600

__global__ __launch_bounds__(256, 1)
void edge_kernel(const float* __restrict__ pos,
                 const int* __restrict__ snd, const int* __restrict__ rcv,
                 const float* __restrict__ eW1, const float* __restrict__ eb1,
                 const float* __restrict__ eb2,
                 const float* __restrict__ pb1, const float* __restrict__ pW2,
                 int E)
{
    extern __shared__ char sm[];
    const uint32_t smb = smem_u32(sm);
    const int tid = threadIdx.x;
    const int lane = tid & 31, w = tid >> 5;
    const int ebase = blockIdx.x * 128;

    int* se = (int*)(sm + OFF_SE);
    int* re = (int*)(sm + OFF_RE);
    float* rad = (float*)(sm + OFF_RAD);
    float* cd = (float*)(sm + OFF_CD);
    float* s_eb1 = (float*)(sm + OFF_EB1);
    float* s_eb2 = (float*)(sm + OFF_EB2);
    float* s_pb1 = (float*)(sm + OFF_PB1);
    float* s_pw2 = (float*)(sm + OFF_PW2);
    float* s_w1r = (float*)(sm + OFF_W1R);

    if (tid < 128) {
        int ge = ebase + tid; if (ge >= E) ge = E - 1;
        int s = snd[ge], r = rcv[ge];
        se[tid] = s; re[tid] = r;
        float dx = pos[s * 3 + 0] - pos[r * 3 + 0];
        float dy = pos[s * 3 + 1] - pos[r * 3 + 1];
        float dz = pos[s * 3 + 2] - pos[r * 3 + 2];
        cd[tid * 3 + 0] = dx; cd[tid * 3 + 1] = dy; cd[tid * 3 + 2] = dz;
        rad[tid] = dx * dx + dy * dy + dz * dz;
        s_eb1[tid] = eb1[tid];
        s_eb2[tid] = eb2[tid];
        s_pb1[tid] = pb1[tid];
        s_pw2[tid] = pW2[tid];
        s_w1r[tid] = eW1[256 * 128 + tid];
    }
    __syncthreads();

    const int arow = lane & 15;
    const int akb = (lane >> 4) * 16;
    const int bn = (lane & 7) + ((lane >> 4) << 3);
    const int bkb = ((lane >> 3) & 1) * 16;

    const uint32_t aA_h[2] = {smb + OFF_A0H + (w * 16 + arow) * 144 + akb,
                              smb + OFF_A1H + (w * 16 + arow) * 144 + akb};
    const uint32_t aA_l[2] = {smb + OFF_A0L + (w * 16 + arow) * 144 + akb,
                              smb + OFF_A1L + (w * 16 + arow) * 144 + akb};
    const uint32_t aB_h[2] = {smb + OFF_B0H + bn * 144 + bkb,
                              smb + OFF_B1H + bn * 144 + bkb};
    const uint32_t aB_l[2] = {smb + OFF_B0L + bn * 144 + bkb,
                              smb + OFF_B1L + bn * 144 + bkb};

    const int r0 = w * 16 + (lane >> 2);
    const int r1 = r0 + 8;
    const int row2 = tid >> 1, half = tid & 1;

    const uint32_t dstAH[2] = {smb + OFF_A0H + row2 * 144 + half * 64,
                               smb + OFF_A1H + row2 * 144 + half * 64};
    const uint32_t dstAL[2] = {smb + OFF_A0L + row2 * 144 + half * 64,
                               smb + OFF_A1L + row2 * 144 + half * 64};
    const uint32_t dstBH[2] = {smb + OFF_B0H + row2 * 144 + half * 64,
                               smb + OFF_B1H + row2 * 144 + half * 64};
    const uint32_t dstBL[2] = {smb + OFF_B0L + row2 * 144 + half * 64,
                               smb + OFF_B1L + row2 * 144 + half * 64};

    float d[16][4];
#pragma unroll
    for (int nt = 0; nt < 16; nt++)
#pragma unroll
        for (int q = 0; q < 4; q++) d[nt][q] = 0.f;

    // ================= stage 1: K=256 (sender | receiver features) =========
    {
        {
            int node = se[row2];
            const __nv_bfloat16* shh = g_h_hi + node * 128 + half * 32;
            const __nv_bfloat16* shl = g_h_lo + node * 128 + half * 32;
            const __nv_bfloat16* swh = g_eW1t_hi + row2 * 256 + half * 32;
            const __nv_bfloat16* swl = g_eW1t_lo + row2 * 256 + half * 32;
#pragma unroll
            for (int t = 0; t < 4; t++) {
                cpa16(dstAH[0] + t * 16, shh + t * 8);
                cpa16(dstAL[0] + t * 16, shl + t * 8);
                cpa16(dstBH[0] + t * 16, swh + t * 8);
                cpa16(dstBL[0] + t * 16, swl + t * 8);
            }
            CPA_COMMIT();
        }
#pragma unroll 1
        for (int c = 0; c < 4; c++) {
            if (c < 3) {
                int cn = c + 1;
                int buf = cn & 1;
                int node = (cn < 2) ? se[row2] : re[row2];
                const __nv_bfloat16* shh = g_h_hi + node * 128 + (cn & 1) * 64 + half * 32;
                const __nv_bfloat16* shl = g_h_lo + node * 128 + (cn & 1) * 64 + half * 32;
                const __nv_bfloat16* swh = g_eW1t_hi + row2 * 256 + cn * 64 + half * 32;
                const __nv_bfloat16* swl = g_eW1t_lo + row2 * 256 + cn * 64 + half * 32;
#pragma unroll
                for (int t = 0; t < 4; t++) {
                    cpa16(dstAH[buf] + t * 16, shh + t * 8);
                    cpa16(dstAL[buf] + t * 16, shl + t * 8);
                    cpa16(dstBH[buf] + t * 16, swh + t * 8);
                    cpa16(dstBL[buf] + t * 16, swl + t * 8);
                }
                CPA_COMMIT();
                CPA_WAIT(1);
            } else {
                CPA_WAIT(0);
            }
            __syncthreads();
            int b = c & 1;
            mma_win64(aA_h[b], aA_l[b], aB_h[b], aB_l[b], d);
            __syncthreads();
        }
    }

    // prefetch stage-2 B (eW2t) -- overlaps epilogue 1
    {
#pragma unroll
        for (int c = 0; c < 2; c++) {
            const __nv_bfloat16* swh = g_eW2t_hi + row2 * 128 + c * 64 + half * 32;
            const __nv_bfloat16* swl = g_eW2t_lo + row2 * 128 + c * 64 + half * 32;
#pragma unroll
            for (int t = 0; t < 4; t++) {
                cpa16(dstBH[c] + t * 16, swh + t * 8);
                cpa16(dstBL[c] + t * 16, swl + t * 8);
            }
        }
        CPA_COMMIT();
    }

    // epilogue 1: msg1 = silu(d + rad*w_r + eb1) -> register A-fragments
    uint32_t ahi[8][4], alo[8][4];
    {
        float rd0 = rad[r0], rd1 = rad[r1];
#pragma unroll
        for (int c = 0; c < 8; c++) {
#pragma unroll
            for (int s = 0; s < 2; s++) {
                int nt = 2 * c + s;
                int j = nt * 8 + (lane & 3) * 2;
                float v00 = silu_f(d[nt][0] + rd0 * s_w1r[j] + s_eb1[j]);
                float v01 = silu_f(d[nt][1] + rd0 * s_w1r[j + 1] + s_eb1[j + 1]);
                float v10 = silu_f(d[nt][2] + rd1 * s_w1r[j] + s_eb1[j]);
                float v11 = silu_f(d[nt][3] + rd1 * s_w1r[j + 1] + s_eb1[j + 1]);
                split_pack(v00, v01, ahi[c][2 * s], alo[c][2 * s]);
                split_pack(v10, v11, ahi[c][2 * s + 1], alo[c][2 * s + 1]);
            }
        }
    }
    CPA_WAIT(0);
    __syncthreads();

    // ================= stage 2: msg2 = silu(msg1 @ eW2 + eb2) ==============
#pragma unroll
    for (int nt = 0; nt < 16; nt++)
#pragma unroll
        for (int q = 0; q < 4; q++) d[nt][q] = 0.f;
    mma_regA128(ahi, alo, aB_h, aB_l, d);
    __syncthreads();   // B reads done before overwrite

    // prefetch stage-3 B (pW1t) -- overlaps epilogue 2
    {
#pragma unroll
        for (int c = 0; c < 2; c++) {
            const __nv_bfloat16* swh = g_pW1t_hi + row2 * 128 + c * 64 + half * 32;
            const __nv_bfloat16* swl = g_pW1t_lo + row2 * 128 + c * 64 + half * 32;
#pragma unroll
            for (int t = 0; t < 4; t++) {
                cpa16(dstBH[c] + t * 16, swh + t * 8);
                cpa16(dstBL[c] + t * 16, swl + t * 8);
            }
        }
        CPA_COMMIT();
    }

    // epilogue 2: silu -> vector-red agg[receiver] + register A-fragments
    {
        bool val0 = (ebase + r0) < E, val1 = (ebase + r1) < E;
        int rn0 = re[r0], rn1 = re[r1];
#pragma unroll
        for (int c = 0; c < 8; c++) {
#pragma unroll
            for (int s = 0; s < 2; s++) {
                int nt = 2 * c + s;
                int j = nt * 8 + (lane & 3) * 2;
                float v00 = silu_f(d[nt][0] + s_eb2[j]);
                float v01 = silu_f(d[nt][1] + s_eb2[j + 1]);
                float v10 = silu_f(d[nt][2] + s_eb2[j]);
                float v11 = silu_f(d[nt][3] + s_eb2[j + 1]);
                split_pack(v00, v01, ahi[c][2 * s], alo[c][2 * s]);
                split_pack(v10, v11, ahi[c][2 * s + 1], alo[c][2 * s + 1]);
                if (val0) red2(&g_agg[rn0 * 128 + j], v00, v01);
                if (val1) red2(&g_agg[rn1 * 128 + j], v10, v11);
            }
        }
    }
    CPA_WAIT(0);
    __syncthreads();

    // ================= stage 3: pc = silu(msg2 @ pW1 + pb1) . pW2 ==========
#pragma unroll
    for (int nt = 0; nt < 16; nt++)
#pragma unroll
        for (int q = 0; q < 4; q++) d[nt][q] = 0.f;
    mma_regA128(ahi, alo, aB_h, aB_l, d);

    // epilogue 3: quad-reduce pc, scatter position correction
    {
        float p0 = 0.f, p1 = 0.f;
#pragma unroll
        for (int nt = 0; nt < 16; nt++) {
            int j = nt * 8 + (lane & 3) * 2;
            p0 += silu_f(d[nt][0] + s_pb1[j]) * s_pw2[j]
                + silu_f(d[nt][1] + s_pb1[j + 1]) * s_pw2[j + 1];
            p1 += silu_f(d[nt][2] + s_pb1[j]) * s_pw2[j]
                + silu_f(d[nt][3] + s_pb1[j + 1]) * s_pw2[j + 1];
        }
        p0 += __shfl_xor_sync(0xffffffffu, p0, 1);
        p0 += __shfl_xor_sync(0xffffffffu, p0, 2);
        p1 += __shfl_xor_sync(0xffffffffu, p1, 1);
        p1 += __shfl_xor_sync(0xffffffffu, p1, 2);
        float* redpc = (float*)(sm + OFF_RPC);
        if ((lane & 3) == 0) { redpc[r0] = p0; redpc[r1] = p1; }
        __syncthreads();
        if (tid < 128 && (ebase + tid) < E) {
            int s = se[tid];
            float pc = redpc[tid];
#pragma unroll
            for (int dd = 0; dd < 3; dd++) {
                float v = cd[tid * 3 + dd] * pc;
                v = fminf(fmaxf(v, -100.f), 100.f);
                atomicAdd(&g_pacc[s * 3 + dd], v);
            }
        }
    }
}

// ---------------------------------------------------------------------------
// Node kernel (bf16x3 HMMA): 128 nodes/block, 256 threads.
//   x = silu(concat(h, agg) @ nW1 + nb1) @ nW2 + nb2; h_new = h + x
// ---------------------------------------------------------------------------
#define NOD_NB1 147456
#define NOD_NB2 147968
#define NOD_TOTAL 148480

__global__ __launch_bounds__(256, 1)
void node_kernel(const float* __restrict__ h, const float* __restrict__ pos,
                 const float* __restrict__ nb1, const float* __restrict__ nb2,
                 float* __restrict__ out, int N)
{
    extern __shared__ char sm[];
    const uint32_t smb = smem_u32(sm);
    const int tid = threadIdx.x;
    const int lane = tid & 31, w = tid >> 5;
    const int nb = blockIdx.x * 128;

    float* s_nb1 = (float*)(sm + NOD_NB1);
    float* s_nb2 = (float*)(sm + NOD_NB2);
    if (tid < 128) {
        s_nb1[tid] = nb1[tid];
        s_nb2[tid] = nb2[tid];
    }
    __syncthreads();

    const int arow = lane & 15;
    const int akb = (lane >> 4) * 16;
    const int bn = (lane & 7) + ((lane >> 4) << 3);
    const int bkb = ((lane >> 3) & 1) * 16;

    const uint32_t aA_h[2] = {smb + OFF_A0H + (w * 16 + arow) * 144 + akb,
                              smb + OFF_A1H + (w * 16 + arow) * 144 + akb};
    const uint32_t aA_l[2] = {smb + OFF_A0L + (w * 16 + arow) * 144 + akb,
                              smb + OFF_A1L + (w * 16 + arow) * 144 + akb};
    const uint32_t aB_h[2] = {smb + OFF_B0H + bn * 144 + bkb,
                              smb + OFF_B1H + bn * 144 + bkb};
    const uint32_t aB_l[2] = {smb + OFF_B0L + bn * 144 + bkb,
                              smb + OFF_B1L + bn * 144 + bkb};

    const int r0 = w * 16 + (lane >> 2);
    const int r1 = r0 + 8;
    const int row2 = tid >> 1, half = tid & 1;

    const uint32_t dstAH[2] = {smb + OFF_A0H + row2 * 144 + half * 64,
                               smb + OFF_A1H + row2 * 144 + half * 64};
    const uint32_t dstAL[2] = {smb + OFF_A0L + row2 * 144 + half * 64,
                               smb + OFF_A1L + row2 * 144 + half * 64};
    const uint32_t dstBH[2] = {smb + OFF_B0H + row2 * 144 + half * 64,
                               smb + OFF_B1H + row2 * 144 + half * 64};
    const uint32_t dstBL[2] = {smb + OFF_B0L + row2 * 144 + half * 64,
                               smb + OFF_B1L + row2 * 144 + half * 64};

    int nodeA = nb + row2; if (nodeA >= N) nodeA = N - 1;

    float d[16][4];
#pragma unroll
    for (int nt = 0; nt < 16; nt++)
#pragma unroll
        for (int q = 0; q < 4; q++) d[nt][q] = 0.f;

    // stage 1: K=256 (h | agg), windows of 64
    {
        {
            const __nv_bfloat16* shh = g_h_hi + nodeA * 128 + half * 32;
            const __nv_bfloat16* shl = g_h_lo + nodeA * 128 + half * 32;
            const __nv_bfloat16* swh = g_nW1t_hi + row2 * 256 + half * 32;
            const __nv_bfloat16* swl = g_nW1t_lo + row2 * 256 + half * 32;
#pragma unroll
            for (int t = 0; t < 4; t++) {
                cpa16(dstAH[0] + t * 16, shh + t * 8);
                cpa16(dstAL[0] + t * 16, shl + t * 8);
                cpa16(dstBH[0] + t * 16, swh + t * 8);
                cpa16(dstBL[0] + t * 16, swl + t * 8);
            }
            CPA_COMMIT();
        }
#pragma unroll 1
        for (int c = 0; c < 4; c++) {
            if (c < 3) {
                int cn = c + 1;
                int buf = cn & 1;
                const __nv_bfloat16* shh = (cn < 2)
                    ? g_h_hi + nodeA * 128 + 64 + half * 32
                    : g_agg_hi + nodeA * 128 + (cn - 2) * 64 + half * 32;
                const __nv_bfloat16* shl = (cn < 2)
                    ? g_h_lo + nodeA * 128 + 64 + half * 32
                    : g_agg_lo + nodeA * 128 + (cn - 2) * 64 + half * 32;
                const __nv_bfloat16* swh = g_nW1t_hi + row2 * 256 + cn * 64 + half * 32;
                const __nv_bfloat16* swl = g_nW1t_lo + row2 * 256 + cn * 64 + half * 32;
#pragma unroll
                for (int t = 0; t < 4; t++) {
                    cpa16(dstAH[buf] + t * 16, shh + t * 8);
                    cpa16(dstAL[buf] + t * 16, shl + t * 8);
                    cpa16(dstBH[buf] + t * 16, swh + t * 8);
                    cpa16(dstBL[buf] + t * 16, swl + t * 8);
                }
                CPA_COMMIT();
                CPA_WAIT(1);
            } else {
                CPA_WAIT(0);
            }
            __syncthreads();
            int b = c & 1;
            mma_win64(aA_h[b], aA_l[b], aB_h[b], aB_l[b], d);
            __syncthreads();
        }
    }

    // prefetch stage-2 B (nW2t) -- overlaps epilogue 1
    {
#pragma unroll
        for (int c = 0; c < 2; c++) {
            const __nv_bfloat16* swh = g_nW2t_hi + row2 * 128 + c * 64 + half * 32;
            const __nv_bfloat16* swl = g_nW2t_lo + row2 * 128 + c * 64 + half * 32;
#pragma unroll
            for (int t = 0; t < 4; t++) {
                cpa16(dstBH[c] + t * 16, swh + t * 8);
                cpa16(dstBL[c] + t * 16, swl + t * 8);
            }
        }
        CPA_COMMIT();
    }

    // epilogue 1: silu -> register A-fragments
    uint32_t ahi[8][4], alo[8][4];
#pragma unroll
    for (int c = 0; c < 8; c++) {
#pragma unroll
        for (int s = 0; s < 2; s++) {
            int nt = 2 * c + s;
            int j = nt * 8 + (lane & 3) * 2;
            float v00 = silu_f(d[nt][0] + s_nb1[j]);
            float v01 = silu_f(d[nt][1] + s_nb1[j + 1]);
            float v10 = silu_f(d[nt][2] + s_nb1[j]);
            float v11 = silu_f(d[nt][3] + s_nb1[j + 1]);
            split_pack(v00, v01, ahi[c][2 * s], alo[c][2 * s]);
            split_pack(v10, v11, ahi[c][2 * s + 1], alo[c][2 * s + 1]);
        }
    }
    CPA_WAIT(0);
    __syncthreads();

    // stage 2: x = msg @ nW2 + nb2; out = h + x
#pragma unroll
    for (int nt = 0; nt < 16; nt++)
#pragma unroll
        for (int q = 0; q < 4; q++) d[nt][q] = 0.f;
    mma_regA128(ahi, alo, aB_h, aB_l, d);

    {
        int n0 = nb + r0, n1 = nb + r1;
        bool v0 = n0 < N, v1 = n1 < N;
#pragma unroll
        for (int nt = 0; nt < 16; nt++) {
            int j = nt * 8 + (lane & 3) * 2;
            if (v0) {
                out[n0 * 128 + j]     = d[nt][0] + s_nb2[j] + h[n0 * 128 + j];
                out[n0 * 128 + j + 1] = d[nt][1] + s_nb2[j + 1] + h[n0 * 128 + j + 1];
            }
            if (v1) {
                out[n1 * 128 + j]     = d[nt][2] + s_nb2[j] + h[n1 * 128 + j];
                out[n1 * 128 + j + 1] = d[nt][3] + s_nb2[j + 1] + h[n1 * 128 + j + 1];
            }
        }
    }

    // pos_new = pos + pacc
    if (tid < 128) {
        int node = nb + tid;
        if (node < N) {
#pragma unroll
            for (int dd = 0; dd < 3; dd++)
                out[N * 128 + node * 3 + dd] =
                    pos[node * 3 + dd] + g_pacc[node * 3 + dd];
        }
    }
}

extern "C" void kernel_launch(void* const* d_in, const int* in_sizes, int n_in,
                              void* d_out, int out_size)
{
    const float* h   = (const float*)d_in[0];
    const float* pos = (const float*)d_in[1];
    const int*   snd = (const int*)d_in[2];
    const int*   rcv = (const int*)d_in[3];
    const float* eW1 = (const float*)d_in[4];
    const float* eb1 = (const float*)d_in[5];
    const float* eW2 = (const float*)d_in[6];
    const float* eb2 = (const float*)d_in[7];
    const float* nW1 = (const float*)d_in[8];
    const float* nb1 = (const float*)d_in[9];
    const float* nW2 = (const float*)d_in[10];
    const float* nb2 = (const float*)d_in[11];
    const float* pW1 = (const float*)d_in[12];
    const float* pb1 = (const float*)d_in[13];
    const float* pW2 = (const float*)d_in[14];
    float* out = (float*)d_out;

    int N = in_sizes[0] / 128;
    int E = in_sizes[2];

    cudaFuncSetAttribute(edge_kernel, cudaFuncAttributeMaxDynamicSharedMemorySize, SM_TOTAL);
    cudaFuncSetAttribute(node_kernel, cudaFuncAttributeMaxDynamicSharedMemorySize, NOD_TOTAL);

    zero_kernel<<<256, 256>>>(N * 128, N * 3);
    prep_kernel<<<512, 256>>>(h, eW1, eW2, pW1, nW1, nW2, N);
    edge_kernel<<<(E + 127) / 128, 256, SM_TOTAL>>>(pos, snd, rcv,
                                                    eW1, eb1, eb2,
                                                    pb1, pW2, E);
    split_agg_kernel<<<512, 256>>>(N * 128);
    node_kernel<<<(N + 127) / 128, 256, NOD_TOTAL>>>(h, pos, nb1, nb2, out, N);
}

// round 14
// speedup vs baseline: 3.4245x; 1.2583x over previous
#include <cuda_runtime.h>
#include <cuda_bf16.h>
#include <math.h>
#include <cstdint>

#define NMAX 50000

// ---------------------------------------------------------------------------
// Device scratch (allocation-free rule)
// ---------------------------------------------------------------------------
__device__ float g_agg[NMAX * 128];   // per-node aggregated messages (fp32)
__device__ float g_pacc[NMAX * 3];    // per-node position correction
__device__ __nv_bfloat16 g_agg_hi[NMAX * 128];
__device__ __nv_bfloat16 g_agg_lo[NMAX * 128];
__device__ __nv_bfloat16 g_h_hi[NMAX * 128];
__device__ __nv_bfloat16 g_h_lo[NMAX * 128];
__device__ __nv_bfloat16 g_eW1t_hi[128 * 256];  // [n][k] transposed
__device__ __nv_bfloat16 g_eW1t_lo[128 * 256];
__device__ __nv_bfloat16 g_eW2t_hi[128 * 128];
__device__ __nv_bfloat16 g_eW2t_lo[128 * 128];
__device__ __nv_bfloat16 g_pW1t_hi[128 * 128];  // stage-3 is hh-only: no lo
__device__ __nv_bfloat16 g_nW1t_hi[128 * 256];
__device__ __nv_bfloat16 g_nW1t_lo[128 * 256];
__device__ __nv_bfloat16 g_nW2t_hi[128 * 128];
__device__ __nv_bfloat16 g_nW2t_lo[128 * 128];

__device__ __forceinline__ float silu_f(float x) {
    return x * __fdividef(1.0f, 1.0f + __expf(-x));
}

__device__ __forceinline__ uint32_t smem_u32(const void* p) {
    uint32_t a;
    asm("{ .reg .u64 t; cvta.to.shared.u64 t, %1; cvt.u32.u64 %0, t; }"
        : "=r"(a) : "l"(p));
    return a;
}

// ---- base-ISA async copy + vector reduction ----
__device__ __forceinline__ void cpa16(uint32_t smem, const void* g) {
    asm volatile("cp.async.cg.shared.global [%0], [%1], 16;"
                 :: "r"(smem), "l"(g) : "memory");
}
#define CPA_COMMIT() asm volatile("cp.async.commit_group;" ::: "memory")
#define CPA_WAIT(n)  asm volatile("cp.async.wait_group %0;" :: "n"(n) : "memory")

__device__ __forceinline__ void red2(float* addr, float a, float b) {
    asm volatile("red.global.add.v2.f32 [%0], {%1, %2};"
                 :: "l"(addr), "f"(a), "f"(b) : "memory");
}

// ---- warp MMA primitives ----
__device__ __forceinline__ void ldsm4(uint32_t r[4], uint32_t addr) {
    asm volatile("ldmatrix.sync.aligned.m8n8.x4.shared.b16 {%0,%1,%2,%3}, [%4];"
                 : "=r"(r[0]), "=r"(r[1]), "=r"(r[2]), "=r"(r[3]) : "r"(addr));
}
__device__ __forceinline__ void mma_bf16(float d[4], const uint32_t a[4],
                                         uint32_t b0, uint32_t b1) {
    asm volatile(
        "mma.sync.aligned.m16n8k16.row.col.f32.bf16.bf16.f32 "
        "{%0,%1,%2,%3}, {%4,%5,%6,%7}, {%8,%9}, {%0,%1,%2,%3};"
        : "+f"(d[0]), "+f"(d[1]), "+f"(d[2]), "+f"(d[3])
        : "r"(a[0]), "r"(a[1]), "r"(a[2]), "r"(a[3]), "r"(b0), "r"(b1));
}

__device__ __forceinline__ void split_pack(float a, float b,
                                           uint32_t& hip, uint32_t& lop) {
    __nv_bfloat16 ah = __float2bfloat16(a);
    __nv_bfloat16 bh = __float2bfloat16(b);
    __nv_bfloat16 al = __float2bfloat16(a - __bfloat162float(ah));
    __nv_bfloat16 bl = __float2bfloat16(b - __bfloat162float(bh));
    __nv_bfloat162 hp, lp;
    hp.x = ah; hp.y = bh; lp.x = al; lp.y = bl;
    hip = *(uint32_t*)&hp;
    lop = *(uint32_t*)&lp;
}
__device__ __forceinline__ uint32_t pack_hi(float a, float b) {
    __nv_bfloat162 hp;
    hp.x = __float2bfloat16(a); hp.y = __float2bfloat16(b);
    return *(uint32_t*)&hp;
}

// One 64-deep K window, A from SMEM via ldmatrix: 3-pass hi/lo emulation.
__device__ __forceinline__ void mma_win64(uint32_t aH, uint32_t aL,
                                          uint32_t bH, uint32_t bL,
                                          float (*d)[4]) {
#pragma unroll
    for (int kk = 0; kk < 4; kk++) {
        uint32_t ah[4], al[4];
        ldsm4(ah, aH + kk * 32);
        ldsm4(al, aL + kk * 32);
#pragma unroll
        for (int np = 0; np < 8; np++) {
            uint32_t bh[4], bl[4];
            ldsm4(bh, bH + np * (16 * 144) + kk * 32);
            ldsm4(bl, bL + np * (16 * 144) + kk * 32);
            mma_bf16(d[2 * np],     ah, bh[0], bh[1]);
            mma_bf16(d[2 * np],     ah, bl[0], bl[1]);
            mma_bf16(d[2 * np],     al, bh[0], bh[1]);
            mma_bf16(d[2 * np + 1], ah, bh[2], bh[3]);
            mma_bf16(d[2 * np + 1], ah, bl[2], bl[3]);
            mma_bf16(d[2 * np + 1], al, bh[2], bh[3]);
        }
    }
}

// One K=16 chunk with register A fragments: 3-pass (hh+hl+lh)
__device__ __forceinline__ void mma_chunk3(const uint32_t ah[4], const uint32_t al[4],
                                           uint32_t bh0, uint32_t bl0,
                                           float (*e)[4]) {
#pragma unroll
    for (int np = 0; np < 8; np++) {
        uint32_t bh[4], bl[4];
        ldsm4(bh, bh0 + np * (16 * 144));
        ldsm4(bl, bl0 + np * (16 * 144));
        mma_bf16(e[2 * np],     ah, bh[0], bh[1]);
        mma_bf16(e[2 * np],     ah, bl[0], bl[1]);
        mma_bf16(e[2 * np],     al, bh[0], bh[1]);
        mma_bf16(e[2 * np + 1], ah, bh[2], bh[3]);
        mma_bf16(e[2 * np + 1], ah, bl[2], bl[3]);
        mma_bf16(e[2 * np + 1], al, bh[2], bh[3]);
    }
}
// One K=16 chunk, hh-only (stage 3)
__device__ __forceinline__ void mma_chunk1(const uint32_t ah[4], uint32_t bh0,
                                           float (*e)[4]) {
#pragma unroll
    for (int np = 0; np < 8; np++) {
        uint32_t bh[4];
        ldsm4(bh, bh0 + np * (16 * 144));
        mma_bf16(e[2 * np],     ah, bh[0], bh[1]);
        mma_bf16(e[2 * np + 1], ah, bh[2], bh[3]);
    }
}

// ---------------------------------------------------------------------------
// Prep kernels
// ---------------------------------------------------------------------------
__global__ void zero_kernel(int n_agg, int n_pacc) {
    int i = blockIdx.x * blockDim.x + threadIdx.x;
    int stride = gridDim.x * blockDim.x;
    for (int k = i; k < n_agg; k += stride) g_agg[k] = 0.f;
    for (int k = i; k < n_pacc; k += stride) g_pacc[k] = 0.f;
}

__global__ void prep_kernel(const float* __restrict__ h,
                            const float* __restrict__ eW1,
                            const float* __restrict__ eW2,
                            const float* __restrict__ pW1,
                            const float* __restrict__ nW1,
                            const float* __restrict__ nW2, int N) {
    int i = blockIdx.x * blockDim.x + threadIdx.x;
    int stride = gridDim.x * blockDim.x;
    for (int k = i; k < N * 128; k += stride) {
        float v = h[k];
        __nv_bfloat16 hi = __float2bfloat16(v);
        g_h_hi[k] = hi;
        g_h_lo[k] = __float2bfloat16(v - __bfloat162float(hi));
    }
    for (int k = i; k < 128 * 256; k += stride) {
        int n = k >> 8, kk = k & 255;
        float v = eW1[kk * 128 + n];
        __nv_bfloat16 hi = __float2bfloat16(v);
        g_eW1t_hi[k] = hi;
        g_eW1t_lo[k] = __float2bfloat16(v - __bfloat162float(hi));
        float w = nW1[kk * 128 + n];
        __nv_bfloat16 wh = __float2bfloat16(w);
        g_nW1t_hi[k] = wh;
        g_nW1t_lo[k] = __float2bfloat16(w - __bfloat162float(wh));
    }
    for (int k = i; k < 128 * 128; k += stride) {
        int n = k >> 7, kk = k & 127;
        float v = eW2[kk * 128 + n];
        __nv_bfloat16 hi = __float2bfloat16(v);
        g_eW2t_hi[k] = hi;
        g_eW2t_lo[k] = __float2bfloat16(v - __bfloat162float(hi));
        g_pW1t_hi[k] = __float2bfloat16(pW1[kk * 128 + n]);
        float u = nW2[kk * 128 + n];
        __nv_bfloat16 uh = __float2bfloat16(u);
        g_nW2t_hi[k] = uh;
        g_nW2t_lo[k] = __float2bfloat16(u - __bfloat162float(uh));
    }
}

__global__ void split_agg_kernel(int n) {
    int i = blockIdx.x * blockDim.x + threadIdx.x;
    int stride = gridDim.x * blockDim.x;
    for (int k = i; k < n; k += stride) {
        float v = g_agg[k];
        __nv_bfloat16 hi = __float2bfloat16(v);
        g_agg_hi[k] = hi;
        g_agg_lo[k] = __float2bfloat16(v - __bfloat162float(hi));
    }
}

// ---------------------------------------------------------------------------
// SMEM layout (shared by edge/node kernels)
// ---------------------------------------------------------------------------
#define OFF_A0H 0
#define OFF_A0L 18432
#define OFF_A1H 36864
#define OFF_A1L 55296
#define OFF_B0H 73728
#define OFF_B0L 92160
#define OFF_B1H 110592
#define OFF_B1L 129024
#define OFF_B2H 147456
#define OFF_B2L 165888
#define OFF_SE  184320
#define OFF_RE  184832
#define OFF_RAD 185344
#define OFF_CD  185856
#define OFF_EB1 187392
#define OFF_EB2 187904
#define OFF_PB1 188416
#define OFF_PW2 188928
#define OFF_W1R 189440
#define OFF_RPC 189952
#define SM_TOTAL 190464

#define NOD_NB1 184320
#define NOD_NB2 184832
#define NOD_TOTAL 185344

// ---------------------------------------------------------------------------
// Edge kernel: 128 edges/block, 256 threads (8 warps x 16 edge-rows).
// Fully fused: stage1 windows pipelined via cp.async; epilogues interleaved
// chunk-wise with the following stage's MMAs (MUFU/LSU overlap tensor).
// ---------------------------------------------------------------------------
__global__ __launch_bounds__(256, 1)
void edge_kernel(const float* __restrict__ pos,
                 const int* __restrict__ snd, const int* __restrict__ rcv,
                 const float* __restrict__ eW1, const float* __restrict__ eb1,
                 const float* __restrict__ eb2,
                 const float* __restrict__ pb1, const float* __restrict__ pW2,
                 int E)
{
    extern __shared__ char sm[];
    const uint32_t smb = smem_u32(sm);
    const int tid = threadIdx.x;
    const int lane = tid & 31, w = tid >> 5;
    const int ebase = blockIdx.x * 128;

    int* se = (int*)(sm + OFF_SE);
    int* re = (int*)(sm + OFF_RE);
    float* rad = (float*)(sm + OFF_RAD);
    float* cd = (float*)(sm + OFF_CD);
    float* s_eb1 = (float*)(sm + OFF_EB1);
    float* s_eb2 = (float*)(sm + OFF_EB2);
    float* s_pb1 = (float*)(sm + OFF_PB1);
    float* s_pw2 = (float*)(sm + OFF_PW2);
    float* s_w1r = (float*)(sm + OFF_W1R);

    if (tid < 128) {
        int ge = ebase + tid; if (ge >= E) ge = E - 1;
        int s = snd[ge], r = rcv[ge];
        se[tid] = s; re[tid] = r;
        float dx = pos[s * 3 + 0] - pos[r * 3 + 0];
        float dy = pos[s * 3 + 1] - pos[r * 3 + 1];
        float dz = pos[s * 3 + 2] - pos[r * 3 + 2];
        cd[tid * 3 + 0] = dx; cd[tid * 3 + 1] = dy; cd[tid * 3 + 2] = dz;
        rad[tid] = dx * dx + dy * dy + dz * dz;
        s_eb1[tid] = eb1[tid];
        s_eb2[tid] = eb2[tid];
        s_pb1[tid] = pb1[tid];
        s_pw2[tid] = pW2[tid];
        s_w1r[tid] = eW1[256 * 128 + tid];
    }
    __syncthreads();

    const int arow = lane & 15;
    const int akb = (lane >> 4) * 16;
    const int bn = (lane & 7) + ((lane >> 4) << 3);
    const int bkb = ((lane >> 3) & 1) * 16;

    const uint32_t aA_h[2] = {smb + OFF_A0H + (w * 16 + arow) * 144 + akb,
                              smb + OFF_A1H + (w * 16 + arow) * 144 + akb};
    const uint32_t aA_l[2] = {smb + OFF_A0L + (w * 16 + arow) * 144 + akb,
                              smb + OFF_A1L + (w * 16 + arow) * 144 + akb};
    const uint32_t aB_h[2] = {smb + OFF_B0H + bn * 144 + bkb,
                              smb + OFF_B1H + bn * 144 + bkb};
    const uint32_t aB_l[2] = {smb + OFF_B0L + bn * 144 + bkb,
                              smb + OFF_B1L + bn * 144 + bkb};
    // stage-2 B windows live in [B2, B0]; stage-3 (hh) windows in [A0H, A0L]
    const uint32_t s2H[2] = {smb + OFF_B2H + bn * 144 + bkb,
                             smb + OFF_B0H + bn * 144 + bkb};
    const uint32_t s2L[2] = {smb + OFF_B2L + bn * 144 + bkb,
                             smb + OFF_B0L + bn * 144 + bkb};
    const uint32_t s3H[2] = {smb + OFF_A0H + bn * 144 + bkb,
                             smb + OFF_A0L + bn * 144 + bkb};

    const int r0 = w * 16 + (lane >> 2);
    const int r1 = r0 + 8;
    const int row2 = tid >> 1, half = tid & 1;

    const uint32_t dstAH[2] = {smb + OFF_A0H + row2 * 144 + half * 64,
                               smb + OFF_A1H + row2 * 144 + half * 64};
    const uint32_t dstAL[2] = {smb + OFF_A0L + row2 * 144 + half * 64,
                               smb + OFF_A1L + row2 * 144 + half * 64};
    const uint32_t dstBH[2] = {smb + OFF_B0H + row2 * 144 + half * 64,
                               smb + OFF_B1H + row2 * 144 + half * 64};
    const uint32_t dstBL[2] = {smb + OFF_B0L + row2 * 144 + half * 64,
                               smb + OFF_B1L + row2 * 144 + half * 64};
    const uint32_t dstB2H = smb + OFF_B2H + row2 * 144 + half * 64;
    const uint32_t dstB2L = smb + OFF_B2L + row2 * 144 + half * 64;

    // stage-1 window issue helper (A = gathered h, B = eW1t)
    auto issue_win = [&](int cn) {
        int buf = cn & 1;
        int node = (cn < 2) ? se[row2] : re[row2];
        const __nv_bfloat16* shh = g_h_hi + node * 128 + (cn & 1) * 64 + half * 32;
        const __nv_bfloat16* shl = g_h_lo + node * 128 + (cn & 1) * 64 + half * 32;
        const __nv_bfloat16* swh = g_eW1t_hi + row2 * 256 + cn * 64 + half * 32;
        const __nv_bfloat16* swl = g_eW1t_lo + row2 * 256 + cn * 64 + half * 32;
#pragma unroll
        for (int t = 0; t < 4; t++) {
            cpa16(dstAH[buf] + t * 16, shh + t * 8);
            cpa16(dstAL[buf] + t * 16, shl + t * 8);
            cpa16(dstBH[buf] + t * 16, swh + t * 8);
            cpa16(dstBL[buf] + t * 16, swl + t * 8);
        }
        CPA_COMMIT();
    };

    float d[16][4];
#pragma unroll
    for (int nt = 0; nt < 16; nt++)
#pragma unroll
        for (int q = 0; q < 4; q++) d[nt][q] = 0.f;

    // ===== stage 1 with deep prefetch schedule =====
    issue_win(0);                                  // G1
    issue_win(1);                                  // G2
    {   // G3: stage-2 B window 0 -> B2
        const __nv_bfloat16* swh = g_eW2t_hi + row2 * 128 + half * 32;
        const __nv_bfloat16* swl = g_eW2t_lo + row2 * 128 + half * 32;
#pragma unroll
        for (int t = 0; t < 4; t++) {
            cpa16(dstB2H + t * 16, swh + t * 8);
            cpa16(dstB2L + t * 16, swl + t * 8);
        }
        CPA_COMMIT();
    }
    CPA_WAIT(2); __syncthreads();
    mma_win64(aA_h[0], aA_l[0], aB_h[0], aB_l[0], d);
    __syncthreads();
    issue_win(2);                                  // G4
    CPA_WAIT(2); __syncthreads();
    mma_win64(aA_h[1], aA_l[1], aB_h[1], aB_l[1], d);
    __syncthreads();
    issue_win(3);                                  // G5
    CPA_WAIT(1); __syncthreads();
    mma_win64(aA_h[0], aA_l[0], aB_h[0], aB_l[0], d);
    __syncthreads();
    {   // G6: stage-2 B window 1 -> B0
        const __nv_bfloat16* swh = g_eW2t_hi + row2 * 128 + 64 + half * 32;
        const __nv_bfloat16* swl = g_eW2t_lo + row2 * 128 + 64 + half * 32;
#pragma unroll
        for (int t = 0; t < 4; t++) {
            cpa16(dstBH[0] + t * 16, swh + t * 8);
            cpa16(dstBL[0] + t * 16, swl + t * 8);
        }
        CPA_COMMIT();
    }
    {   // G7: stage-3 B (hh-only) both windows -> A0H, A0L
#pragma unroll
        for (int cwin = 0; cwin < 2; cwin++) {
            const __nv_bfloat16* swh = g_pW1t_hi + row2 * 128 + cwin * 64 + half * 32;
            uint32_t dstb = (cwin ? dstAL[0] : dstAH[0]);
#pragma unroll
            for (int t = 0; t < 4; t++) cpa16(dstb + t * 16, swh + t * 8);
        }
        CPA_COMMIT();
    }
    CPA_WAIT(2); __syncthreads();
    mma_win64(aA_h[1], aA_l[1], aB_h[1], aB_l[1], d);
    CPA_WAIT(0); __syncthreads();

    // ===== fused ep1 + stage2 (chunk-wise; MUFU overlaps tensor) =====
    float e[16][4];
#pragma unroll
    for (int nt = 0; nt < 16; nt++)
#pragma unroll
        for (int q = 0; q < 4; q++) e[nt][q] = 0.f;
    {
        float rd0 = rad[r0], rd1 = rad[r1];
#pragma unroll
        for (int c = 0; c < 8; c++) {
            int nt0 = 2 * c, nt1 = 2 * c + 1;
            int j0 = nt0 * 8 + (lane & 3) * 2;
            int j1 = j0 + 8;
            uint32_t ah[4], al[4];
            float v00 = silu_f(d[nt0][0] + rd0 * s_w1r[j0] + s_eb1[j0]);
            float v01 = silu_f(d[nt0][1] + rd0 * s_w1r[j0 + 1] + s_eb1[j0 + 1]);
            float v10 = silu_f(d[nt0][2] + rd1 * s_w1r[j0] + s_eb1[j0]);
            float v11 = silu_f(d[nt0][3] + rd1 * s_w1r[j0 + 1] + s_eb1[j0 + 1]);
            split_pack(v00, v01, ah[0], al[0]);
            split_pack(v10, v11, ah[1], al[1]);
            float w00 = silu_f(d[nt1][0] + rd0 * s_w1r[j1] + s_eb1[j1]);
            float w01 = silu_f(d[nt1][1] + rd0 * s_w1r[j1 + 1] + s_eb1[j1 + 1]);
            float w10 = silu_f(d[nt1][2] + rd1 * s_w1r[j1] + s_eb1[j1]);
            float w11 = silu_f(d[nt1][3] + rd1 * s_w1r[j1 + 1] + s_eb1[j1 + 1]);
            split_pack(w00, w01, ah[2], al[2]);
            split_pack(w10, w11, ah[3], al[3]);
            mma_chunk3(ah, al, s2H[c >> 2] + (c & 3) * 32,
                       s2L[c >> 2] + (c & 3) * 32, e);
        }
    }

    // ===== fused ep2 + red2 + stage3 (hh-only) =====
#pragma unroll
    for (int nt = 0; nt < 16; nt++)
#pragma unroll
        for (int q = 0; q < 4; q++) d[nt][q] = 0.f;
    {
        bool val0 = (ebase + r0) < E, val1 = (ebase + r1) < E;
        int rn0 = re[r0], rn1 = re[r1];
#pragma unroll
        for (int c = 0; c < 8; c++) {
            int nt0 = 2 * c, nt1 = 2 * c + 1;
            int j0 = nt0 * 8 + (lane & 3) * 2;
            int j1 = j0 + 8;
            uint32_t ah[4];
            float v00 = silu_f(e[nt0][0] + s_eb2[j0]);
            float v01 = silu_f(e[nt0][1] + s_eb2[j0 + 1]);
            float v10 = silu_f(e[nt0][2] + s_eb2[j0]);
            float v11 = silu_f(e[nt0][3] + s_eb2[j0 + 1]);
            float w00 = silu_f(e[nt1][0] + s_eb2[j1]);
            float w01 = silu_f(e[nt1][1] + s_eb2[j1 + 1]);
            float w10 = silu_f(e[nt1][2] + s_eb2[j1]);
            float w11 = silu_f(e[nt1][3] + s_eb2[j1 + 1]);
            ah[0] = pack_hi(v00, v01);
            ah[1] = pack_hi(v10, v11);
            ah[2] = pack_hi(w00, w01);
            ah[3] = pack_hi(w10, w11);
            if (val0) {
                red2(&g_agg[rn0 * 128 + j0], v00, v01);
                red2(&g_agg[rn0 * 128 + j1], w00, w01);
            }
            if (val1) {
                red2(&g_agg[rn1 * 128 + j0], v10, v11);
                red2(&g_agg[rn1 * 128 + j1], w10, w11);
            }
            mma_chunk1(ah, s3H[c >> 2] + (c & 3) * 32, d);
        }
    }

    // ===== epilogue 3: pc reduction + position scatter =====
    {
        float p0 = 0.f, p1 = 0.f;
#pragma unroll
        for (int nt = 0; nt < 16; nt++) {
            int j = nt * 8 + (lane & 3) * 2;
            p0 += silu_f(d[nt][0] + s_pb1[j]) * s_pw2[j]
                + silu_f(d[nt][1] + s_pb1[j + 1]) * s_pw2[j + 1];
            p1 += silu_f(d[nt][2] + s_pb1[j]) * s_pw2[j]
                + silu_f(d[nt][3] + s_pb1[j + 1]) * s_pw2[j + 1];
        }
        p0 += __shfl_xor_sync(0xffffffffu, p0, 1);
        p0 += __shfl_xor_sync(0xffffffffu, p0, 2);
        p1 += __shfl_xor_sync(0xffffffffu, p1, 1);
        p1 += __shfl_xor_sync(0xffffffffu, p1, 2);
        float* redpc = (float*)(sm + OFF_RPC);
        if ((lane & 3) == 0) { redpc[r0] = p0; redpc[r1] = p1; }
        __syncthreads();
        if (tid < 128 && (ebase + tid) < E) {
            int s = se[tid];
            float pc = redpc[tid];
#pragma unroll
            for (int dd = 0; dd < 3; dd++) {
                float v = cd[tid * 3 + dd] * pc;
                v = fminf(fmaxf(v, -100.f), 100.f);
                atomicAdd(&g_pacc[s * 3 + dd], v);
            }
        }
    }
}

// ---------------------------------------------------------------------------
// Node kernel (bf16x3, fused): 128 nodes/block, 256 threads.
// ---------------------------------------------------------------------------
__global__ __launch_bounds__(256, 1)
void node_kernel(const float* __restrict__ h, const float* __restrict__ pos,
                 const float* __restrict__ nb1, const float* __restrict__ nb2,
                 float* __restrict__ out, int N)
{
    extern __shared__ char sm[];
    const uint32_t smb = smem_u32(sm);
    const int tid = threadIdx.x;
    const int lane = tid & 31, w = tid >> 5;
    const int nb = blockIdx.x * 128;

    float* s_nb1 = (float*)(sm + NOD_NB1);
    float* s_nb2 = (float*)(sm + NOD_NB2);
    if (tid < 128) {
        s_nb1[tid] = nb1[tid];
        s_nb2[tid] = nb2[tid];
    }
    __syncthreads();

    const int arow = lane & 15;
    const int akb = (lane >> 4) * 16;
    const int bn = (lane & 7) + ((lane >> 4) << 3);
    const int bkb = ((lane >> 3) & 1) * 16;

    const uint32_t aA_h[2] = {smb + OFF_A0H + (w * 16 + arow) * 144 + akb,
                              smb + OFF_A1H + (w * 16 + arow) * 144 + akb};
    const uint32_t aA_l[2] = {smb + OFF_A0L + (w * 16 + arow) * 144 + akb,
                              smb + OFF_A1L + (w * 16 + arow) * 144 + akb};
    const uint32_t aB_h[2] = {smb + OFF_B0H + bn * 144 + bkb,
                              smb + OFF_B1H + bn * 144 + bkb};
    const uint32_t aB_l[2] = {smb + OFF_B0L + bn * 144 + bkb,
                              smb + OFF_B1L + bn * 144 + bkb};
    const uint32_t s2H[2] = {smb + OFF_B2H + bn * 144 + bkb,
                             smb + OFF_B0H + bn * 144 + bkb};
    const uint32_t s2L[2] = {smb + OFF_B2L + bn * 144 + bkb,
                             smb + OFF_B0L + bn * 144 + bkb};

    const int r0 = w * 16 + (lane >> 2);
    const int r1 = r0 + 8;
    const int row2 = tid >> 1, half = tid & 1;

    const uint32_t dstAH[2] = {smb + OFF_A0H + row2 * 144 + half * 64,
                               smb + OFF_A1H + row2 * 144 + half * 64};
    const uint32_t dstAL[2] = {smb + OFF_A0L + row2 * 144 + half * 64,
                               smb + OFF_A1L + row2 * 144 + half * 64};
    const uint32_t dstBH[2] = {smb + OFF_B0H + row2 * 144 + half * 64,
                               smb + OFF_B1H + row2 * 144 + half * 64};
    const uint32_t dstBL[2] = {smb + OFF_B0L + row2 * 144 + half * 64,
                               smb + OFF_B1L + row2 * 144 + half * 64};
    const uint32_t dstB2H = smb + OFF_B2H + row2 * 144 + half * 64;
    const uint32_t dstB2L = smb + OFF_B2L + row2 * 144 + half * 64;

    int nodeA = nb + row2; if (nodeA >= N) nodeA = N - 1;

    auto issue_win = [&](int cn) {
        int buf = cn & 1;
        const __nv_bfloat16* shh = (cn < 2)
            ? g_h_hi + nodeA * 128 + cn * 64 + half * 32
            : g_agg_hi + nodeA * 128 + (cn - 2) * 64 + half * 32;
        const __nv_bfloat16* shl = (cn < 2)
            ? g_h_lo + nodeA * 128 + cn * 64 + half * 32
            : g_agg_lo + nodeA * 128 + (cn - 2) * 64 + half * 32;
        const __nv_bfloat16* swh = g_nW1t_hi + row2 * 256 + cn * 64 + half * 32;
        const __nv_bfloat16* swl = g_nW1t_lo + row2 * 256 + cn * 64 + half * 32;
#pragma unroll
        for (int t = 0; t < 4; t++) {
            cpa16(dstAH[buf] + t * 16, shh + t * 8);
            cpa16(dstAL[buf] + t * 16, shl + t * 8);
            cpa16(dstBH[buf] + t * 16, swh + t * 8);
            cpa16(dstBL[buf] + t * 16, swl + t * 8);
        }
        CPA_COMMIT();
    };

    float d[16][4];
#pragma unroll
    for (int nt = 0; nt < 16; nt++)
#pragma unroll
        for (int q = 0; q < 4; q++) d[nt][q] = 0.f;

    issue_win(0);                                  // G1
    issue_win(1);                                  // G2
    {   // G3: stage-2 B window0 (nW2t) -> B2
        const __nv_bfloat16* swh = g_nW2t_hi + row2 * 128 + half * 32;
        const __nv_bfloat16* swl = g_nW2t_lo + row2 * 128 + half * 32;
#pragma unroll
        for (int t = 0; t < 4; t++) {
            cpa16(dstB2H + t * 16, swh + t * 8);
            cpa16(dstB2L + t * 16, swl + t * 8);
        }
        CPA_COMMIT();
    }
    CPA_WAIT(2); __syncthreads();
    mma_win64(aA_h[0], aA_l[0], aB_h[0], aB_l[0], d);
    __syncthreads();
    issue_win(2);                                  // G4
    CPA_WAIT(2); __syncthreads();
    mma_win64(aA_h[1], aA_l[1], aB_h[1], aB_l[1], d);
    __syncthreads();
    issue_win(3);                                  // G5
    CPA_WAIT(1); __syncthreads();
    mma_win64(aA_h[0], aA_l[0], aB_h[0], aB_l[0], d);
    __syncthreads();
    {   // G6: stage-2 B window1 -> B0
        const __nv_bfloat16* swh = g_nW2t_hi + row2 * 128 + 64 + half * 32;
        const __nv_bfloat16* swl = g_nW2t_lo + row2 * 128 + 64 + half * 32;
#pragma unroll
        for (int t = 0; t < 4; t++) {
            cpa16(dstBH[0] + t * 16, swh + t * 8);
            cpa16(dstBL[0] + t * 16, swl + t * 8);
        }
        CPA_COMMIT();
    }
    CPA_WAIT(1); __syncthreads();
    mma_win64(aA_h[1], aA_l[1], aB_h[1], aB_l[1], d);
    CPA_WAIT(0); __syncthreads();

    // fused ep1 + stage2 (3-pass)
    float e[16][4];
#pragma unroll
    for (int nt = 0; nt < 16; nt++)
#pragma unroll
        for (int q = 0; q < 4; q++) e[nt][q] = 0.f;
#pragma unroll
    for (int c = 0; c < 8; c++) {
        int nt0 = 2 * c, nt1 = 2 * c + 1;
        int j0 = nt0 * 8 + (lane & 3) * 2;
        int j1 = j0 + 8;
        uint32_t ah[4], al[4];
        float v00 = silu_f(d[nt0][0] + s_nb1[j0]);
        float v01 = silu_f(d[nt0][1] + s_nb1[j0 + 1]);
        float v10 = silu_f(d[nt0][2] + s_nb1[j0]);
        float v11 = silu_f(d[nt0][3] + s_nb1[j0 + 1]);
        split_pack(v00, v01, ah[0], al[0]);
        split_pack(v10, v11, ah[1], al[1]);
        float w00 = silu_f(d[nt1][0] + s_nb1[j1]);
        float w01 = silu_f(d[nt1][1] + s_nb1[j1 + 1]);
        float w10 = silu_f(d[nt1][2] + s_nb1[j1]);
        float w11 = silu_f(d[nt1][3] + s_nb1[j1 + 1]);
        split_pack(w00, w01, ah[2], al[2]);
        split_pack(w10, w11, ah[3], al[3]);
        mma_chunk3(ah, al, s2H[c >> 2] + (c & 3) * 32,
                   s2L[c >> 2] + (c & 3) * 32, e);
    }

    // epilogue: h_new = h + x
    {
        int n0 = nb + r0, n1 = nb + r1;
        bool v0 = n0 < N, v1 = n1 < N;
#pragma unroll
        for (int nt = 0; nt < 16; nt++) {
            int j = nt * 8 + (lane & 3) * 2;
            if (v0) {
                out[n0 * 128 + j]     = e[nt][0] + s_nb2[j] + h[n0 * 128 + j];
                out[n0 * 128 + j + 1] = e[nt][1] + s_nb2[j + 1] + h[n0 * 128 + j + 1];
            }
            if (v1) {
                out[n1 * 128 + j]     = e[nt][2] + s_nb2[j] + h[n1 * 128 + j];
                out[n1 * 128 + j + 1] = e[nt][3] + s_nb2[j + 1] + h[n1 * 128 + j + 1];
            }
        }
    }

    // pos_new = pos + pacc
    if (tid < 128) {
        int node = nb + tid;
        if (node < N) {
#pragma unroll
            for (int dd = 0; dd < 3; dd++)
                out[N * 128 + node * 3 + dd] =
                    pos[node * 3 + dd] + g_pacc[node * 3 + dd];
        }
    }
}

extern "C" void kernel_launch(void* const* d_in, const int* in_sizes, int n_in,
                              void* d_out, int out_size)
{
    const float* h   = (const float*)d_in[0];
    const float* pos = (const float*)d_in[1];
    const int*   snd = (const int*)d_in[2];
    const int*   rcv = (const int*)d_in[3];
    const float* eW1 = (const float*)d_in[4];
    const float* eb1 = (const float*)d_in[5];
    const float* eW2 = (const float*)d_in[6];
    const float* eb2 = (const float*)d_in[7];
    const float* nW1 = (const float*)d_in[8];
    const float* nb1 = (const float*)d_in[9];
    const float* nW2 = (const float*)d_in[10];
    const float* nb2 = (const float*)d_in[11];
    const float* pW1 = (const float*)d_in[12];
    const float* pb1 = (const float*)d_in[13];
    const float* pW2 = (const float*)d_in[14];
    float* out = (float*)d_out;

    int N = in_sizes[0] / 128;
    int E = in_sizes[2];

    cudaFuncSetAttribute(edge_kernel, cudaFuncAttributeMaxDynamicSharedMemorySize, SM_TOTAL);
    cudaFuncSetAttribute(node_kernel, cudaFuncAttributeMaxDynamicSharedMemorySize, NOD_TOTAL);

    zero_kernel<<<256, 256>>>(N * 128, N * 3);
    prep_kernel<<<512, 256>>>(h, eW1, eW2, pW1, nW1, nW2, N);
    edge_kernel<<<(E + 127) / 128, 256, SM_TOTAL>>>(pos, snd, rcv,
                                                    eW1, eb1, eb2,
                                                    pb1, pW2, E);
    split_agg_kernel<<<512, 256>>>(N * 128);
    node_kernel<<<(N + 127) / 128, 256, NOD_TOTAL>>>(h, pos, nb1, nb2, out, N);
}

// round 15
// speedup vs baseline: 3.8220x; 1.1161x over previous
#include <cuda_runtime.h>
#include <cuda_bf16.h>
#include <math.h>
#include <cstdint>

#define NMAX 50000

// ---------------------------------------------------------------------------
// Device scratch (allocation-free rule)
// ---------------------------------------------------------------------------
__device__ float g_agg[NMAX * 128];   // per-node aggregated messages (fp32)
__device__ float g_pacc[NMAX * 3];    // per-node position correction
__device__ __nv_bfloat16 g_agg_hi[NMAX * 128];
__device__ __nv_bfloat16 g_agg_lo[NMAX * 128];
__device__ __nv_bfloat16 g_h_hi[NMAX * 128];
__device__ __nv_bfloat16 g_h_lo[NMAX * 128];
__device__ __nv_bfloat16 g_eW1t_hi[128 * 256];  // [n][k] transposed
__device__ __nv_bfloat16 g_eW1t_lo[128 * 256];
__device__ __nv_bfloat16 g_eW2t_hi[128 * 128];
__device__ __nv_bfloat16 g_eW2t_lo[128 * 128];
__device__ __nv_bfloat16 g_pW1t_hi[128 * 128];  // stage-3 is hh-only: no lo
__device__ __nv_bfloat16 g_nW1t_hi[128 * 256];
__device__ __nv_bfloat16 g_nW1t_lo[128 * 256];
__device__ __nv_bfloat16 g_nW2t_hi[128 * 128];
__device__ __nv_bfloat16 g_nW2t_lo[128 * 128];

__device__ __forceinline__ float silu_f(float x) {
    return x * __fdividef(1.0f, 1.0f + __expf(-x));
}

__device__ __forceinline__ uint32_t smem_u32(const void* p) {
    uint32_t a;
    asm("{ .reg .u64 t; cvta.to.shared.u64 t, %1; cvt.u32.u64 %0, t; }"
        : "=r"(a) : "l"(p));
    return a;
}

// ---- base-ISA async copy + vector reduction ----
__device__ __forceinline__ void cpa16(uint32_t smem, const void* g) {
    asm volatile("cp.async.cg.shared.global [%0], [%1], 16;"
                 :: "r"(smem), "l"(g) : "memory");
}
#define CPA_COMMIT() asm volatile("cp.async.commit_group;" ::: "memory")
#define CPA_WAIT(n)  asm volatile("cp.async.wait_group %0;" :: "n"(n) : "memory")

__device__ __forceinline__ void red2(float* addr, float a, float b) {
    asm volatile("red.global.add.v2.f32 [%0], {%1, %2};"
                 :: "l"(addr), "f"(a), "f"(b) : "memory");
}

// ---- warp MMA primitives ----
__device__ __forceinline__ void ldsm4(uint32_t r[4], uint32_t addr) {
    asm volatile("ldmatrix.sync.aligned.m8n8.x4.shared.b16 {%0,%1,%2,%3}, [%4];"
                 : "=r"(r[0]), "=r"(r[1]), "=r"(r[2]), "=r"(r[3]) : "r"(addr));
}
__device__ __forceinline__ void mma_bf16(float d[4], const uint32_t a[4],
                                         uint32_t b0, uint32_t b1) {
    asm volatile(
        "mma.sync.aligned.m16n8k16.row.col.f32.bf16.bf16.f32 "
        "{%0,%1,%2,%3}, {%4,%5,%6,%7}, {%8,%9}, {%0,%1,%2,%3};"
        : "+f"(d[0]), "+f"(d[1]), "+f"(d[2]), "+f"(d[3])
        : "r"(a[0]), "r"(a[1]), "r"(a[2]), "r"(a[3]), "r"(b0), "r"(b1));
}

__device__ __forceinline__ void split_pack(float a, float b,
                                           uint32_t& hip, uint32_t& lop) {
    __nv_bfloat16 ah = __float2bfloat16(a);
    __nv_bfloat16 bh = __float2bfloat16(b);
    __nv_bfloat16 al = __float2bfloat16(a - __bfloat162float(ah));
    __nv_bfloat16 bl = __float2bfloat16(b - __bfloat162float(bh));
    __nv_bfloat162 hp, lp;
    hp.x = ah; hp.y = bh; lp.x = al; lp.y = bl;
    hip = *(uint32_t*)&hp;
    lop = *(uint32_t*)&lp;
}
__device__ __forceinline__ uint32_t pack_hi(float a, float b) {
    __nv_bfloat162 hp;
    hp.x = __float2bfloat16(a); hp.y = __float2bfloat16(b);
    return *(uint32_t*)&hp;
}

// One 64-deep K window, A from SMEM via ldmatrix: 3-pass hi/lo emulation.
__device__ __forceinline__ void mma_win64(uint32_t aH, uint32_t aL,
                                          uint32_t bH, uint32_t bL,
                                          float (*d)[4]) {
#pragma unroll
    for (int kk = 0; kk < 4; kk++) {
        uint32_t ah[4], al[4];
        ldsm4(ah, aH + kk * 32);
        ldsm4(al, aL + kk * 32);
#pragma unroll
        for (int np = 0; np < 8; np++) {
            uint32_t bh[4], bl[4];
            ldsm4(bh, bH + np * (16 * 144) + kk * 32);
            ldsm4(bl, bL + np * (16 * 144) + kk * 32);
            mma_bf16(d[2 * np],     ah, bh[0], bh[1]);
            mma_bf16(d[2 * np],     ah, bl[0], bl[1]);
            mma_bf16(d[2 * np],     al, bh[0], bh[1]);
            mma_bf16(d[2 * np + 1], ah, bh[2], bh[3]);
            mma_bf16(d[2 * np + 1], ah, bl[2], bl[3]);
            mma_bf16(d[2 * np + 1], al, bh[2], bh[3]);
        }
    }
}

// One K=16 chunk with register A fragments: 3-pass (hh+hl+lh)
__device__ __forceinline__ void mma_chunk3(const uint32_t ah[4], const uint32_t al[4],
                                           uint32_t bh0, uint32_t bl0,
                                           float (*e)[4]) {
#pragma unroll
    for (int np = 0; np < 8; np++) {
        uint32_t bh[4], bl[4];
        ldsm4(bh, bh0 + np * (16 * 144));
        ldsm4(bl, bl0 + np * (16 * 144));
        mma_bf16(e[2 * np],     ah, bh[0], bh[1]);
        mma_bf16(e[2 * np],     ah, bl[0], bl[1]);
        mma_bf16(e[2 * np],     al, bh[0], bh[1]);
        mma_bf16(e[2 * np + 1], ah, bh[2], bh[3]);
        mma_bf16(e[2 * np + 1], ah, bl[2], bl[3]);
        mma_bf16(e[2 * np + 1], al, bh[2], bh[3]);
    }
}
// One K=16 chunk, hh-only (stage 3)
__device__ __forceinline__ void mma_chunk1(const uint32_t ah[4], uint32_t bh0,
                                           float (*e)[4]) {
#pragma unroll
    for (int np = 0; np < 8; np++) {
        uint32_t bh[4];
        ldsm4(bh, bh0 + np * (16 * 144));
        mma_bf16(e[2 * np],     ah, bh[0], bh[1]);
        mma_bf16(e[2 * np + 1], ah, bh[2], bh[3]);
    }
}

// ---------------------------------------------------------------------------
// Prep kernels (zeroing fused into prep)
// ---------------------------------------------------------------------------
__global__ void prep_kernel(const float* __restrict__ h,
                            const float* __restrict__ eW1,
                            const float* __restrict__ eW2,
                            const float* __restrict__ pW1,
                            const float* __restrict__ nW1,
                            const float* __restrict__ nW2, int N) {
    int i = blockIdx.x * blockDim.x + threadIdx.x;
    int stride = gridDim.x * blockDim.x;
    for (int k = i; k < N * 128; k += stride) {
        float v = h[k];
        __nv_bfloat16 hi = __float2bfloat16(v);
        g_h_hi[k] = hi;
        g_h_lo[k] = __float2bfloat16(v - __bfloat162float(hi));
        g_agg[k] = 0.f;
    }
    for (int k = i; k < N * 3; k += stride) g_pacc[k] = 0.f;
    for (int k = i; k < 128 * 256; k += stride) {
        int n = k >> 8, kk = k & 255;
        float v = eW1[kk * 128 + n];
        __nv_bfloat16 hi = __float2bfloat16(v);
        g_eW1t_hi[k] = hi;
        g_eW1t_lo[k] = __float2bfloat16(v - __bfloat162float(hi));
        float w = nW1[kk * 128 + n];
        __nv_bfloat16 wh = __float2bfloat16(w);
        g_nW1t_hi[k] = wh;
        g_nW1t_lo[k] = __float2bfloat16(w - __bfloat162float(wh));
    }
    for (int k = i; k < 128 * 128; k += stride) {
        int n = k >> 7, kk = k & 127;
        float v = eW2[kk * 128 + n];
        __nv_bfloat16 hi = __float2bfloat16(v);
        g_eW2t_hi[k] = hi;
        g_eW2t_lo[k] = __float2bfloat16(v - __bfloat162float(hi));
        g_pW1t_hi[k] = __float2bfloat16(pW1[kk * 128 + n]);
        float u = nW2[kk * 128 + n];
        __nv_bfloat16 uh = __float2bfloat16(u);
        g_nW2t_hi[k] = uh;
        g_nW2t_lo[k] = __float2bfloat16(u - __bfloat162float(uh));
    }
}

__global__ void split_agg_kernel(int n4) {
    int i = blockIdx.x * blockDim.x + threadIdx.x;
    int stride = gridDim.x * blockDim.x;
    const float4* src = (const float4*)g_agg;
    uint2* dhi = (uint2*)g_agg_hi;
    uint2* dlo = (uint2*)g_agg_lo;
    for (int k = i; k < n4; k += stride) {
        float4 v = src[k];
        uint32_t h0, l0, h1, l1;
        split_pack(v.x, v.y, h0, l0);
        split_pack(v.z, v.w, h1, l1);
        dhi[k] = make_uint2(h0, h1);
        dlo[k] = make_uint2(l0, l1);
    }
}

// ---------------------------------------------------------------------------
// Edge kernel SMEM layout: resident eW1t (4 windows hi+lo) + A double-buffer.
// Stage-2/3 weights staged into dead A buffers per tile.
// ---------------------------------------------------------------------------
#define RW1H 0
#define RW1L 73728
#define EA0H 147456
#define EA0L 165888
#define EA1H 184320
#define EA1L 202752
#define EOFF_SE  221184
#define EOFF_RE  221696
#define EOFF_RAD 222208
#define EOFF_CD  222720
#define EOFF_EB1 224256
#define EOFF_EB2 224768
#define EOFF_PB1 225280
#define EOFF_PW2 225792
#define EOFF_W1R 226304
#define EOFF_RPC 226816
#define ESM_TOTAL 227328

__global__ __launch_bounds__(256, 1)
void edge_kernel(const float* __restrict__ pos,
                 const int* __restrict__ snd, const int* __restrict__ rcv,
                 const float* __restrict__ eW1, const float* __restrict__ eb1,
                 const float* __restrict__ eb2,
                 const float* __restrict__ pb1, const float* __restrict__ pW2,
                 int E, int nTiles)
{
    extern __shared__ char sm[];
    const uint32_t smb = smem_u32(sm);
    const int tid = threadIdx.x;
    const int lane = tid & 31, w = tid >> 5;

    int* se = (int*)(sm + EOFF_SE);
    int* re = (int*)(sm + EOFF_RE);
    float* rad = (float*)(sm + EOFF_RAD);
    float* cd = (float*)(sm + EOFF_CD);
    float* s_eb1 = (float*)(sm + EOFF_EB1);
    float* s_eb2 = (float*)(sm + EOFF_EB2);
    float* s_pb1 = (float*)(sm + EOFF_PB1);
    float* s_pw2 = (float*)(sm + EOFF_PW2);
    float* s_w1r = (float*)(sm + EOFF_W1R);
    float* redpc = (float*)(sm + EOFF_RPC);

    // once-per-CTA constants
    if (tid < 128) {
        s_eb1[tid] = eb1[tid];
        s_eb2[tid] = eb2[tid];
        s_pb1[tid] = pb1[tid];
        s_pw2[tid] = pW2[tid];
        s_w1r[tid] = eW1[256 * 128 + tid];
    }

    const int arow = lane & 15;
    const int akb = (lane >> 4) * 16;
    const int bn = (lane & 7) + ((lane >> 4) << 3);
    const int bkb = ((lane >> 3) & 1) * 16;

    // resident stage-1 B operand addresses (4 windows)
    uint32_t rBh[4], rBl[4];
#pragma unroll
    for (int cw = 0; cw < 4; cw++) {
        rBh[cw] = smb + RW1H + cw * 18432 + bn * 144 + bkb;
        rBl[cw] = smb + RW1L + cw * 18432 + bn * 144 + bkb;
    }
    const uint32_t aA_h[2] = {smb + EA0H + (w * 16 + arow) * 144 + akb,
                              smb + EA1H + (w * 16 + arow) * 144 + akb};
    const uint32_t aA_l[2] = {smb + EA0L + (w * 16 + arow) * 144 + akb,
                              smb + EA1L + (w * 16 + arow) * 144 + akb};
    const uint32_t s2H[2] = {smb + EA0H + bn * 144 + bkb,
                             smb + EA1H + bn * 144 + bkb};
    const uint32_t s2L[2] = {smb + EA0L + bn * 144 + bkb,
                             smb + EA1L + bn * 144 + bkb};
    const uint32_t s3B[2] = {smb + EA0H + bn * 144 + bkb,
                             smb + EA0L + bn * 144 + bkb};

    const int r0 = w * 16 + (lane >> 2);
    const int r1 = r0 + 8;
    const int row2 = tid >> 1, half = tid & 1;

    const uint32_t dstAH[2] = {smb + EA0H + row2 * 144 + half * 64,
                               smb + EA1H + row2 * 144 + half * 64};
    const uint32_t dstAL[2] = {smb + EA0L + row2 * 144 + half * 64,
                               smb + EA1L + row2 * 144 + half * 64};

    // load resident eW1t (hi+lo, 4 windows) once
    {
#pragma unroll
        for (int cw = 0; cw < 4; cw++) {
            const __nv_bfloat16* swh = g_eW1t_hi + row2 * 256 + cw * 64 + half * 32;
            const __nv_bfloat16* swl = g_eW1t_lo + row2 * 256 + cw * 64 + half * 32;
            uint32_t dh = smb + RW1H + cw * 18432 + row2 * 144 + half * 64;
            uint32_t dl = smb + RW1L + cw * 18432 + row2 * 144 + half * 64;
#pragma unroll
            for (int t = 0; t < 4; t++) {
                cpa16(dh + t * 16, swh + t * 8);
                cpa16(dl + t * 16, swl + t * 8);
            }
        }
        CPA_COMMIT();
    }
    __syncthreads();

    for (int tile = blockIdx.x; tile < nTiles; tile += gridDim.x) {
        const int ebase = tile * 128;
        if (tid < 128) {
            int ge = ebase + tid; if (ge >= E) ge = E - 1;
            int s = snd[ge], r = rcv[ge];
            se[tid] = s; re[tid] = r;
            float dx = pos[s * 3 + 0] - pos[r * 3 + 0];
            float dy = pos[s * 3 + 1] - pos[r * 3 + 1];
            float dz = pos[s * 3 + 2] - pos[r * 3 + 2];
            cd[tid * 3 + 0] = dx; cd[tid * 3 + 1] = dy; cd[tid * 3 + 2] = dz;
            rad[tid] = dx * dx + dy * dy + dz * dz;
        }
        __syncthreads();

        auto issueA = [&](int cn) {
            int buf = cn & 1;
            int node = (cn < 2) ? se[row2] : re[row2];
            const __nv_bfloat16* shh = g_h_hi + node * 128 + (cn & 1) * 64 + half * 32;
            const __nv_bfloat16* shl = g_h_lo + node * 128 + (cn & 1) * 64 + half * 32;
#pragma unroll
            for (int t = 0; t < 4; t++) {
                cpa16(dstAH[buf] + t * 16, shh + t * 8);
                cpa16(dstAL[buf] + t * 16, shl + t * 8);
            }
            CPA_COMMIT();
        };

        float d[16][4];
#pragma unroll
        for (int nt = 0; nt < 16; nt++)
#pragma unroll
            for (int q = 0; q < 4; q++) d[nt][q] = 0.f;

        // ===== stage 1: 4 windows, A double-buffered, B resident =====
        issueA(0);
        issueA(1);
        CPA_WAIT(1); __syncthreads();
        mma_win64(aA_h[0], aA_l[0], rBh[0], rBl[0], d);
        __syncthreads();
        issueA(2);
        CPA_WAIT(1); __syncthreads();
        mma_win64(aA_h[1], aA_l[1], rBh[1], rBl[1], d);
        __syncthreads();
        issueA(3);
        CPA_WAIT(1); __syncthreads();
        mma_win64(aA_h[0], aA_l[0], rBh[2], rBl[2], d);
        __syncthreads();
        {   // stage-2 w0 weights -> EA0 (dead)
            const __nv_bfloat16* swh = g_eW2t_hi + row2 * 128 + half * 32;
            const __nv_bfloat16* swl = g_eW2t_lo + row2 * 128 + half * 32;
#pragma unroll
            for (int t = 0; t < 4; t++) {
                cpa16(dstAH[0] + t * 16, swh + t * 8);
                cpa16(dstAL[0] + t * 16, swl + t * 8);
            }
            CPA_COMMIT();
        }
        CPA_WAIT(1); __syncthreads();
        mma_win64(aA_h[1], aA_l[1], rBh[3], rBl[3], d);
        __syncthreads();
        {   // stage-2 w1 weights -> EA1 (dead)
            const __nv_bfloat16* swh = g_eW2t_hi + row2 * 128 + 64 + half * 32;
            const __nv_bfloat16* swl = g_eW2t_lo + row2 * 128 + 64 + half * 32;
#pragma unroll
            for (int t = 0; t < 4; t++) {
                cpa16(dstAH[1] + t * 16, swh + t * 8);
                cpa16(dstAL[1] + t * 16, swl + t * 8);
            }
            CPA_COMMIT();
        }
        CPA_WAIT(1); __syncthreads();   // stage-2 w0 ready

        // ===== fused ep1 + stage2 =====
        float e[16][4];
#pragma unroll
        for (int nt = 0; nt < 16; nt++)
#pragma unroll
            for (int q = 0; q < 4; q++) e[nt][q] = 0.f;
        const float rd0 = rad[r0], rd1 = rad[r1];

        auto ep1_chunk = [&](int c) {
            int nt0 = 2 * c, nt1 = 2 * c + 1;
            int j0 = nt0 * 8 + (lane & 3) * 2;
            int j1 = j0 + 8;
            uint32_t ah[4], al[4];
            float v00 = silu_f(d[nt0][0] + rd0 * s_w1r[j0] + s_eb1[j0]);
            float v01 = silu_f(d[nt0][1] + rd0 * s_w1r[j0 + 1] + s_eb1[j0 + 1]);
            float v10 = silu_f(d[nt0][2] + rd1 * s_w1r[j0] + s_eb1[j0]);
            float v11 = silu_f(d[nt0][3] + rd1 * s_w1r[j0 + 1] + s_eb1[j0 + 1]);
            split_pack(v00, v01, ah[0], al[0]);
            split_pack(v10, v11, ah[1], al[1]);
            float w00 = silu_f(d[nt1][0] + rd0 * s_w1r[j1] + s_eb1[j1]);
            float w01 = silu_f(d[nt1][1] + rd0 * s_w1r[j1 + 1] + s_eb1[j1 + 1]);
            float w10 = silu_f(d[nt1][2] + rd1 * s_w1r[j1] + s_eb1[j1]);
            float w11 = silu_f(d[nt1][3] + rd1 * s_w1r[j1 + 1] + s_eb1[j1 + 1]);
            split_pack(w00, w01, ah[2], al[2]);
            split_pack(w10, w11, ah[3], al[3]);
            mma_chunk3(ah, al, s2H[c >> 2] + (c & 3) * 32,
                       s2L[c >> 2] + (c & 3) * 32, e);
        };
#pragma unroll
        for (int c = 0; c < 4; c++) ep1_chunk(c);
        CPA_WAIT(0); __syncthreads();   // w1 ready; all warps done with EA0 reads
        {   // stage-3 hh weights (both windows) -> EA0H, EA0L
            const __nv_bfloat16* sw0 = g_pW1t_hi + row2 * 128 + half * 32;
            const __nv_bfloat16* sw1 = g_pW1t_hi + row2 * 128 + 64 + half * 32;
#pragma unroll
            for (int t = 0; t < 4; t++) {
                cpa16(dstAH[0] + t * 16, sw0 + t * 8);
                cpa16(dstAL[0] + t * 16, sw1 + t * 8);
            }
            CPA_COMMIT();
        }
#pragma unroll
        for (int c = 4; c < 8; c++) ep1_chunk(c);
        CPA_WAIT(0); __syncthreads();   // stage-3 B ready

        // ===== fused ep2 + red2 + stage3 (hh-only) =====
#pragma unroll
        for (int nt = 0; nt < 16; nt++)
#pragma unroll
            for (int q = 0; q < 4; q++) d[nt][q] = 0.f;
        {
            bool val0 = (ebase + r0) < E, val1 = (ebase + r1) < E;
            int rn0 = re[r0], rn1 = re[r1];
#pragma unroll
            for (int c = 0; c < 8; c++) {
                int nt0 = 2 * c, nt1 = 2 * c + 1;
                int j0 = nt0 * 8 + (lane & 3) * 2;
                int j1 = j0 + 8;
                uint32_t ah[4];
                float v00 = silu_f(e[nt0][0] + s_eb2[j0]);
                float v01 = silu_f(e[nt0][1] + s_eb2[j0 + 1]);
                float v10 = silu_f(e[nt0][2] + s_eb2[j0]);
                float v11 = silu_f(e[nt0][3] + s_eb2[j0 + 1]);
                float w00 = silu_f(e[nt1][0] + s_eb2[j1]);
                float w01 = silu_f(e[nt1][1] + s_eb2[j1 + 1]);
                float w10 = silu_f(e[nt1][2] + s_eb2[j1]);
                float w11 = silu_f(e[nt1][3] + s_eb2[j1 + 1]);
                ah[0] = pack_hi(v00, v01);
                ah[1] = pack_hi(v10, v11);
                ah[2] = pack_hi(w00, w01);
                ah[3] = pack_hi(w10, w11);
                if (val0) {
                    red2(&g_agg[rn0 * 128 + j0], v00, v01);
                    red2(&g_agg[rn0 * 128 + j1], w00, w01);
                }
                if (val1) {
                    red2(&g_agg[rn1 * 128 + j0], v10, v11);
                    red2(&g_agg[rn1 * 128 + j1], w10, w11);
                }
                mma_chunk1(ah, s3B[c >> 2] + (c & 3) * 32, d);
            }
        }

        // ===== ep3: pc reduction + position scatter =====
        {
            float p0 = 0.f, p1 = 0.f;
#pragma unroll
            for (int nt = 0; nt < 16; nt++) {
                int j = nt * 8 + (lane & 3) * 2;
                p0 += silu_f(d[nt][0] + s_pb1[j]) * s_pw2[j]
                    + silu_f(d[nt][1] + s_pb1[j + 1]) * s_pw2[j + 1];
                p1 += silu_f(d[nt][2] + s_pb1[j]) * s_pw2[j]
                    + silu_f(d[nt][3] + s_pb1[j + 1]) * s_pw2[j + 1];
            }
            p0 += __shfl_xor_sync(0xffffffffu, p0, 1);
            p0 += __shfl_xor_sync(0xffffffffu, p0, 2);
            p1 += __shfl_xor_sync(0xffffffffu, p1, 1);
            p1 += __shfl_xor_sync(0xffffffffu, p1, 2);
            if ((lane & 3) == 0) { redpc[r0] = p0; redpc[r1] = p1; }
            __syncthreads();
            if (tid < 128 && (ebase + tid) < E) {
                int s = se[tid];
                float pc = redpc[tid];
#pragma unroll
                for (int dd = 0; dd < 3; dd++) {
                    float v = cd[tid * 3 + dd] * pc;
                    v = fminf(fmaxf(v, -100.f), 100.f);
                    atomicAdd(&g_pacc[s * 3 + dd], v);
                }
            }
        }
        __syncthreads();   // se/re/rad/cd reuse safety for next tile
    }
}

// ---------------------------------------------------------------------------
// Node kernel (bf16x3, fused): 128 nodes/block, 256 threads. (R14 layout)
// ---------------------------------------------------------------------------
#define OFF_A0H 0
#define OFF_A0L 18432
#define OFF_A1H 36864
#define OFF_A1L 55296
#define OFF_B0H 73728
#define OFF_B0L 92160
#define OFF_B1H 110592
#define OFF_B1L 129024
#define OFF_B2H 147456
#define OFF_B2L 165888
#define NOD_NB1 184320
#define NOD_NB2 184832
#define NOD_TOTAL 185344

__global__ __launch_bounds__(256, 1)
void node_kernel(const float* __restrict__ h, const float* __restrict__ pos,
                 const float* __restrict__ nb1, const float* __restrict__ nb2,
                 float* __restrict__ out, int N)
{
    extern __shared__ char sm[];
    const uint32_t smb = smem_u32(sm);
    const int tid = threadIdx.x;
    const int lane = tid & 31, w = tid >> 5;
    const int nb = blockIdx.x * 128;

    float* s_nb1 = (float*)(sm + NOD_NB1);
    float* s_nb2 = (float*)(sm + NOD_NB2);
    if (tid < 128) {
        s_nb1[tid] = nb1[tid];
        s_nb2[tid] = nb2[tid];
    }
    __syncthreads();

    const int arow = lane & 15;
    const int akb = (lane >> 4) * 16;
    const int bn = (lane & 7) + ((lane >> 4) << 3);
    const int bkb = ((lane >> 3) & 1) * 16;

    const uint32_t aA_h[2] = {smb + OFF_A0H + (w * 16 + arow) * 144 + akb,
                              smb + OFF_A1H + (w * 16 + arow) * 144 + akb};
    const uint32_t aA_l[2] = {smb + OFF_A0L + (w * 16 + arow) * 144 + akb,
                              smb + OFF_A1L + (w * 16 + arow) * 144 + akb};
    const uint32_t aB_h[2] = {smb + OFF_B0H + bn * 144 + bkb,
                              smb + OFF_B1H + bn * 144 + bkb};
    const uint32_t aB_l[2] = {smb + OFF_B0L + bn * 144 + bkb,
                              smb + OFF_B1L + bn * 144 + bkb};
    const uint32_t s2H[2] = {smb + OFF_B2H + bn * 144 + bkb,
                             smb + OFF_B0H + bn * 144 + bkb};
    const uint32_t s2L[2] = {smb + OFF_B2L + bn * 144 + bkb,
                             smb + OFF_B0L + bn * 144 + bkb};

    const int r0 = w * 16 + (lane >> 2);
    const int r1 = r0 + 8;
    const int row2 = tid >> 1, half = tid & 1;

    const uint32_t dstAH[2] = {smb + OFF_A0H + row2 * 144 + half * 64,
                               smb + OFF_A1H + row2 * 144 + half * 64};
    const uint32_t dstAL[2] = {smb + OFF_A0L + row2 * 144 + half * 64,
                               smb + OFF_A1L + row2 * 144 + half * 64};
    const uint32_t dstBH[2] = {smb + OFF_B0H + row2 * 144 + half * 64,
                               smb + OFF_B1H + row2 * 144 + half * 64};
    const uint32_t dstBL[2] = {smb + OFF_B0L + row2 * 144 + half * 64,
                               smb + OFF_B1L + row2 * 144 + half * 64};
    const uint32_t dstB2H = smb + OFF_B2H + row2 * 144 + half * 64;
    const uint32_t dstB2L = smb + OFF_B2L + row2 * 144 + half * 64;

    int nodeA = nb + row2; if (nodeA >= N) nodeA = N - 1;

    auto issue_win = [&](int cn) {
        int buf = cn & 1;
        const __nv_bfloat16* shh = (cn < 2)
            ? g_h_hi + nodeA * 128 + cn * 64 + half * 32
            : g_agg_hi + nodeA * 128 + (cn - 2) * 64 + half * 32;
        const __nv_bfloat16* shl = (cn < 2)
            ? g_h_lo + nodeA * 128 + cn * 64 + half * 32
            : g_agg_lo + nodeA * 128 + (cn - 2) * 64 + half * 32;
        const __nv_bfloat16* swh = g_nW1t_hi + row2 * 256 + cn * 64 + half * 32;
        const __nv_bfloat16* swl = g_nW1t_lo + row2 * 256 + cn * 64 + half * 32;
#pragma unroll
        for (int t = 0; t < 4; t++) {
            cpa16(dstAH[buf] + t * 16, shh + t * 8);
            cpa16(dstAL[buf] + t * 16, shl + t * 8);
            cpa16(dstBH[buf] + t * 16, swh + t * 8);
            cpa16(dstBL[buf] + t * 16, swl + t * 8);
        }
        CPA_COMMIT();
    };

    float d[16][4];
#pragma unroll
    for (int nt = 0; nt < 16; nt++)
#pragma unroll
        for (int q = 0; q < 4; q++) d[nt][q] = 0.f;

    issue_win(0);
    issue_win(1);
    {   // stage-2 B window0 (nW2t) -> B2
        const __nv_bfloat16* swh = g_nW2t_hi + row2 * 128 + half * 32;
        const __nv_bfloat16* swl = g_nW2t_lo + row2 * 128 + half * 32;
#pragma unroll
        for (int t = 0; t < 4; t++) {
            cpa16(dstB2H + t * 16, swh + t * 8);
            cpa16(dstB2L + t * 16, swl + t * 8);
        }
        CPA_COMMIT();
    }
    CPA_WAIT(2); __syncthreads();
    mma_win64(aA_h[0], aA_l[0], aB_h[0], aB_l[0], d);
    __syncthreads();
    issue_win(2);
    CPA_WAIT(2); __syncthreads();
    mma_win64(aA_h[1], aA_l[1], aB_h[1], aB_l[1], d);
    __syncthreads();
    issue_win(3);
    CPA_WAIT(1); __syncthreads();
    mma_win64(aA_h[0], aA_l[0], aB_h[0], aB_l[0], d);
    __syncthreads();
    {   // stage-2 B window1 -> B0
        const __nv_bfloat16* swh = g_nW2t_hi + row2 * 128 + 64 + half * 32;
        const __nv_bfloat16* swl = g_nW2t_lo + row2 * 128 + 64 + half * 32;
#pragma unroll
        for (int t = 0; t < 4; t++) {
            cpa16(dstBH[0] + t * 16, swh + t * 8);
            cpa16(dstBL[0] + t * 16, swl + t * 8);
        }
        CPA_COMMIT();
    }
    CPA_WAIT(1); __syncthreads();
    mma_win64(aA_h[1], aA_l[1], aB_h[1], aB_l[1], d);
    CPA_WAIT(0); __syncthreads();

    // fused ep1 + stage2 (3-pass)
    float e[16][4];
#pragma unroll
    for (int nt = 0; nt < 16; nt++)
#pragma unroll
        for (int q = 0; q < 4; q++) e[nt][q] = 0.f;
#pragma unroll
    for (int c = 0; c < 8; c++) {
        int nt0 = 2 * c, nt1 = 2 * c + 1;
        int j0 = nt0 * 8 + (lane & 3) * 2;
        int j1 = j0 + 8;
        uint32_t ah[4], al[4];
        float v00 = silu_f(d[nt0][0] + s_nb1[j0]);
        float v01 = silu_f(d[nt0][1] + s_nb1[j0 + 1]);
        float v10 = silu_f(d[nt0][2] + s_nb1[j0]);
        float v11 = silu_f(d[nt0][3] + s_nb1[j0 + 1]);
        split_pack(v00, v01, ah[0], al[0]);
        split_pack(v10, v11, ah[1], al[1]);
        float w00 = silu_f(d[nt1][0] + s_nb1[j1]);
        float w01 = silu_f(d[nt1][1] + s_nb1[j1 + 1]);
        float w10 = silu_f(d[nt1][2] + s_nb1[j1]);
        float w11 = silu_f(d[nt1][3] + s_nb1[j1 + 1]);
        split_pack(w00, w01, ah[2], al[2]);
        split_pack(w10, w11, ah[3], al[3]);
        mma_chunk3(ah, al, s2H[c >> 2] + (c & 3) * 32,
                   s2L[c >> 2] + (c & 3) * 32, e);
    }

    // epilogue: h_new = h + x
    {
        int n0 = nb + r0, n1 = nb + r1;
        bool v0 = n0 < N, v1 = n1 < N;
#pragma unroll
        for (int nt = 0; nt < 16; nt++) {
            int j = nt * 8 + (lane & 3) * 2;
            if (v0) {
                out[n0 * 128 + j]     = e[nt][0] + s_nb2[j] + h[n0 * 128 + j];
                out[n0 * 128 + j + 1] = e[nt][1] + s_nb2[j + 1] + h[n0 * 128 + j + 1];
            }
            if (v1) {
                out[n1 * 128 + j]     = e[nt][2] + s_nb2[j] + h[n1 * 128 + j];
                out[n1 * 128 + j + 1] = e[nt][3] + s_nb2[j + 1] + h[n1 * 128 + j + 1];
            }
        }
    }

    // pos_new = pos + pacc
    if (tid < 128) {
        int node = nb + tid;
        if (node < N) {
#pragma unroll
            for (int dd = 0; dd < 3; dd++)
                out[N * 128 + node * 3 + dd] =
                    pos[node * 3 + dd] + g_pacc[node * 3 + dd];
        }
    }
}

extern "C" void kernel_launch(void* const* d_in, const int* in_sizes, int n_in,
                              void* d_out, int out_size)
{
    const float* h   = (const float*)d_in[0];
    const float* pos = (const float*)d_in[1];
    const int*   snd = (const int*)d_in[2];
    const int*   rcv = (const int*)d_in[3];
    const float* eW1 = (const float*)d_in[4];
    const float* eb1 = (const float*)d_in[5];
    const float* eW2 = (const float*)d_in[6];
    const float* eb2 = (const float*)d_in[7];
    const float* nW1 = (const float*)d_in[8];
    const float* nb1 = (const float*)d_in[9];
    const float* nW2 = (const float*)d_in[10];
    const float* nb2 = (const float*)d_in[11];
    const float* pW1 = (const float*)d_in[12];
    const float* pb1 = (const float*)d_in[13];
    const float* pW2 = (const float*)d_in[14];
    float* out = (float*)d_out;

    int N = in_sizes[0] / 128;
    int E = in_sizes[2];
    int nTiles = (E + 127) / 128;

    cudaFuncSetAttribute(edge_kernel, cudaFuncAttributeMaxDynamicSharedMemorySize, ESM_TOTAL);
    cudaFuncSetAttribute(node_kernel, cudaFuncAttributeMaxDynamicSharedMemorySize, NOD_TOTAL);

    prep_kernel<<<512, 256>>>(h, eW1, eW2, pW1, nW1, nW2, N);
    int grid = nTiles < 152 ? nTiles : 152;
    edge_kernel<<<grid, 256, ESM_TOTAL>>>(pos, snd, rcv, eW1, eb1, eb2,
                                          pb1, pW2, E, nTiles);
    split_agg_kernel<<<512, 256>>>(N * 32);
    node_kernel<<<(N + 127) / 128, 256, NOD_TOTAL>>>(h, pos, nb1, nb2, out, N);
}

// round 16
// speedup vs baseline: 6.5192x; 1.7057x over previous
#include <cuda_runtime.h>
#include <cuda_bf16.h>
#include <math.h>
#include <cstdint>

#define NMAX 50000

// ---------------------------------------------------------------------------
// Device scratch (allocation-free rule)
// ---------------------------------------------------------------------------
__device__ float g_agg[NMAX * 128];   // per-node aggregated messages (fp32)
__device__ float g_pacc[NMAX * 3];    // per-node position correction
__device__ float g_H1a[NMAX * 128];   // h @ W1a (sender half of edge stage-1)
__device__ float g_H1b[NMAX * 128];   // h @ W1b (receiver half)
__device__ __nv_bfloat16 g_agg_hi[NMAX * 128];
__device__ __nv_bfloat16 g_agg_lo[NMAX * 128];
__device__ __nv_bfloat16 g_h_hi[NMAX * 128];
__device__ __nv_bfloat16 g_h_lo[NMAX * 128];
__device__ __nv_bfloat16 g_eW1t_hi[128 * 256];  // [n][k] transposed
__device__ __nv_bfloat16 g_eW1t_lo[128 * 256];
__device__ __nv_bfloat16 g_eW2t_hi[128 * 128];
__device__ __nv_bfloat16 g_eW2t_lo[128 * 128];
__device__ __nv_bfloat16 g_pW1t_hi[128 * 128];  // stage-3 is hh-only: no lo
__device__ __nv_bfloat16 g_nW1t_hi[128 * 256];
__device__ __nv_bfloat16 g_nW1t_lo[128 * 256];
__device__ __nv_bfloat16 g_nW2t_hi[128 * 128];
__device__ __nv_bfloat16 g_nW2t_lo[128 * 128];

__device__ __forceinline__ float silu_f(float x) {
    return x * __fdividef(1.0f, 1.0f + __expf(-x));
}

__device__ __forceinline__ uint32_t smem_u32(const void* p) {
    uint32_t a;
    asm("{ .reg .u64 t; cvta.to.shared.u64 t, %1; cvt.u32.u64 %0, t; }"
        : "=r"(a) : "l"(p));
    return a;
}

// ---- base-ISA async copy + vector reduction ----
__device__ __forceinline__ void cpa16(uint32_t smem, const void* g) {
    asm volatile("cp.async.cg.shared.global [%0], [%1], 16;"
                 :: "r"(smem), "l"(g) : "memory");
}
#define CPA_COMMIT() asm volatile("cp.async.commit_group;" ::: "memory")
#define CPA_WAIT(n)  asm volatile("cp.async.wait_group %0;" :: "n"(n) : "memory")

__device__ __forceinline__ void red2(float* addr, float a, float b) {
    asm volatile("red.global.add.v2.f32 [%0], {%1, %2};"
                 :: "l"(addr), "f"(a), "f"(b) : "memory");
}

// ---- warp MMA primitives ----
__device__ __forceinline__ void ldsm4(uint32_t r[4], uint32_t addr) {
    asm volatile("ldmatrix.sync.aligned.m8n8.x4.shared.b16 {%0,%1,%2,%3}, [%4];"
                 : "=r"(r[0]), "=r"(r[1]), "=r"(r[2]), "=r"(r[3]) : "r"(addr));
}
__device__ __forceinline__ void mma_bf16(float d[4], const uint32_t a[4],
                                         uint32_t b0, uint32_t b1) {
    asm volatile(
        "mma.sync.aligned.m16n8k16.row.col.f32.bf16.bf16.f32 "
        "{%0,%1,%2,%3}, {%4,%5,%6,%7}, {%8,%9}, {%0,%1,%2,%3};"
        : "+f"(d[0]), "+f"(d[1]), "+f"(d[2]), "+f"(d[3])
        : "r"(a[0]), "r"(a[1]), "r"(a[2]), "r"(a[3]), "r"(b0), "r"(b1));
}

__device__ __forceinline__ void split_pack(float a, float b,
                                           uint32_t& hip, uint32_t& lop) {
    __nv_bfloat16 ah = __float2bfloat16(a);
    __nv_bfloat16 bh = __float2bfloat16(b);
    __nv_bfloat16 al = __float2bfloat16(a - __bfloat162float(ah));
    __nv_bfloat16 bl = __float2bfloat16(b - __bfloat162float(bh));
    __nv_bfloat162 hp, lp;
    hp.x = ah; hp.y = bh; lp.x = al; lp.y = bl;
    hip = *(uint32_t*)&hp;
    lop = *(uint32_t*)&lp;
}
__device__ __forceinline__ uint32_t pack_hi(float a, float b) {
    __nv_bfloat162 hp;
    hp.x = __float2bfloat16(a); hp.y = __float2bfloat16(b);
    return *(uint32_t*)&hp;
}

// One 64-deep K window, A from SMEM via ldmatrix: 3-pass hi/lo emulation.
__device__ __forceinline__ void mma_win64(uint32_t aH, uint32_t aL,
                                          uint32_t bH, uint32_t bL,
                                          float (*d)[4]) {
#pragma unroll
    for (int kk = 0; kk < 4; kk++) {
        uint32_t ah[4], al[4];
        ldsm4(ah, aH + kk * 32);
        ldsm4(al, aL + kk * 32);
#pragma unroll
        for (int np = 0; np < 8; np++) {
            uint32_t bh[4], bl[4];
            ldsm4(bh, bH + np * (16 * 144) + kk * 32);
            ldsm4(bl, bL + np * (16 * 144) + kk * 32);
            mma_bf16(d[2 * np],     ah, bh[0], bh[1]);
            mma_bf16(d[2 * np],     ah, bl[0], bl[1]);
            mma_bf16(d[2 * np],     al, bh[0], bh[1]);
            mma_bf16(d[2 * np + 1], ah, bh[2], bh[3]);
            mma_bf16(d[2 * np + 1], ah, bl[2], bl[3]);
            mma_bf16(d[2 * np + 1], al, bh[2], bh[3]);
        }
    }
}

// One K=16 chunk with register A fragments: 3-pass (hh+hl+lh)
__device__ __forceinline__ void mma_chunk3(const uint32_t ah[4], const uint32_t al[4],
                                           uint32_t bh0, uint32_t bl0,
                                           float (*e)[4]) {
#pragma unroll
    for (int np = 0; np < 8; np++) {
        uint32_t bh[4], bl[4];
        ldsm4(bh, bh0 + np * (16 * 144));
        ldsm4(bl, bl0 + np * (16 * 144));
        mma_bf16(e[2 * np],     ah, bh[0], bh[1]);
        mma_bf16(e[2 * np],     ah, bl[0], bl[1]);
        mma_bf16(e[2 * np],     al, bh[0], bh[1]);
        mma_bf16(e[2 * np + 1], ah, bh[2], bh[3]);
        mma_bf16(e[2 * np + 1], ah, bl[2], bl[3]);
        mma_bf16(e[2 * np + 1], al, bh[2], bh[3]);
    }
}
// One K=16 chunk, hh-only (stage 3)
__device__ __forceinline__ void mma_chunk1(const uint32_t ah[4], uint32_t bh0,
                                           float (*e)[4]) {
#pragma unroll
    for (int np = 0; np < 8; np++) {
        uint32_t bh[4];
        ldsm4(bh, bh0 + np * (16 * 144));
        mma_bf16(e[2 * np],     ah, bh[0], bh[1]);
        mma_bf16(e[2 * np + 1], ah, bh[2], bh[3]);
    }
}

// ---------------------------------------------------------------------------
// Prep kernel (zeroing fused)
// ---------------------------------------------------------------------------
__global__ void prep_kernel(const float* __restrict__ h,
                            const float* __restrict__ eW1,
                            const float* __restrict__ eW2,
                            const float* __restrict__ pW1,
                            const float* __restrict__ nW1,
                            const float* __restrict__ nW2, int N) {
    int i = blockIdx.x * blockDim.x + threadIdx.x;
    int stride = gridDim.x * blockDim.x;
    for (int k = i; k < N * 128; k += stride) {
        float v = h[k];
        __nv_bfloat16 hi = __float2bfloat16(v);
        g_h_hi[k] = hi;
        g_h_lo[k] = __float2bfloat16(v - __bfloat162float(hi));
        g_agg[k] = 0.f;
    }
    for (int k = i; k < N * 3; k += stride) g_pacc[k] = 0.f;
    for (int k = i; k < 128 * 256; k += stride) {
        int n = k >> 8, kk = k & 255;
        float v = eW1[kk * 128 + n];
        __nv_bfloat16 hi = __float2bfloat16(v);
        g_eW1t_hi[k] = hi;
        g_eW1t_lo[k] = __float2bfloat16(v - __bfloat162float(hi));
        float w = nW1[kk * 128 + n];
        __nv_bfloat16 wh = __float2bfloat16(w);
        g_nW1t_hi[k] = wh;
        g_nW1t_lo[k] = __float2bfloat16(w - __bfloat162float(wh));
    }
    for (int k = i; k < 128 * 128; k += stride) {
        int n = k >> 7, kk = k & 127;
        float v = eW2[kk * 128 + n];
        __nv_bfloat16 hi = __float2bfloat16(v);
        g_eW2t_hi[k] = hi;
        g_eW2t_lo[k] = __float2bfloat16(v - __bfloat162float(hi));
        g_pW1t_hi[k] = __float2bfloat16(pW1[kk * 128 + n]);
        float u = nW2[kk * 128 + n];
        __nv_bfloat16 uh = __float2bfloat16(u);
        g_nW2t_hi[k] = uh;
        g_nW2t_lo[k] = __float2bfloat16(u - __bfloat162float(uh));
    }
}

__global__ void split_agg_kernel(int n4) {
    int i = blockIdx.x * blockDim.x + threadIdx.x;
    int stride = gridDim.x * blockDim.x;
    const float4* src = (const float4*)g_agg;
    uint2* dhi = (uint2*)g_agg_hi;
    uint2* dlo = (uint2*)g_agg_lo;
    for (int k = i; k < n4; k += stride) {
        float4 v = src[k];
        uint32_t h0, l0, h1, l1;
        split_pack(v.x, v.y, h0, l0);
        split_pack(v.z, v.w, h1, l1);
        dhi[k] = make_uint2(h0, h1);
        dlo[k] = make_uint2(l0, l1);
    }
}

// ---------------------------------------------------------------------------
// h1_kernel: H1a = h @ W1a, H1b = h @ W1b (dense, 128 nodes/block)
// ---------------------------------------------------------------------------
#define H1_A0H 0
#define H1_A0L 18432
#define H1_A1H 36864
#define H1_A1L 55296
#define H1_B0H 73728
#define H1_B0L 92160
#define H1_B1H 110592
#define H1_B1L 129024
#define H1_TOTAL 147456

__global__ __launch_bounds__(256, 1)
void h1_kernel(int N)
{
    extern __shared__ char sm[];
    const uint32_t smb = smem_u32(sm);
    const int tid = threadIdx.x;
    const int lane = tid & 31, w = tid >> 5;
    const int nb = blockIdx.x * 128;

    const int arow = lane & 15;
    const int akb = (lane >> 4) * 16;
    const int bn = (lane & 7) + ((lane >> 4) << 3);
    const int bkb = ((lane >> 3) & 1) * 16;

    const uint32_t aA_h[2] = {smb + H1_A0H + (w * 16 + arow) * 144 + akb,
                              smb + H1_A1H + (w * 16 + arow) * 144 + akb};
    const uint32_t aA_l[2] = {smb + H1_A0L + (w * 16 + arow) * 144 + akb,
                              smb + H1_A1L + (w * 16 + arow) * 144 + akb};
    const uint32_t aB_h[2] = {smb + H1_B0H + bn * 144 + bkb,
                              smb + H1_B1H + bn * 144 + bkb};
    const uint32_t aB_l[2] = {smb + H1_B0L + bn * 144 + bkb,
                              smb + H1_B1L + bn * 144 + bkb};

    const int r0 = w * 16 + (lane >> 2);
    const int r1 = r0 + 8;
    const int row2 = tid >> 1, half = tid & 1;

    const uint32_t dstAH[2] = {smb + H1_A0H + row2 * 144 + half * 64,
                               smb + H1_A1H + row2 * 144 + half * 64};
    const uint32_t dstAL[2] = {smb + H1_A0L + row2 * 144 + half * 64,
                               smb + H1_A1L + row2 * 144 + half * 64};
    const uint32_t dstBH[2] = {smb + H1_B0H + row2 * 144 + half * 64,
                               smb + H1_B1H + row2 * 144 + half * 64};
    const uint32_t dstBL[2] = {smb + H1_B0L + row2 * 144 + half * 64,
                               smb + H1_B1L + row2 * 144 + half * 64};

    int nodeA = nb + row2; if (nodeA >= N) nodeA = N - 1;

    // B-window issuer: which ∈ {0=W1a,1=W1b}, cw = K window, buf ∈ {0,1}
    auto issueB = [&](int which, int cw, int buf) {
        const __nv_bfloat16* swh = g_eW1t_hi + row2 * 256 + which * 128 + cw * 64 + half * 32;
        const __nv_bfloat16* swl = g_eW1t_lo + row2 * 256 + which * 128 + cw * 64 + half * 32;
#pragma unroll
        for (int t = 0; t < 4; t++) {
            cpa16(dstBH[buf] + t * 16, swh + t * 8);
            cpa16(dstBL[buf] + t * 16, swl + t * 8);
        }
        CPA_COMMIT();
    };

    // G1: A windows (both) + W1a k-win0 -> B0
    {
#pragma unroll
        for (int cw = 0; cw < 2; cw++) {
            const __nv_bfloat16* shh = g_h_hi + nodeA * 128 + cw * 64 + half * 32;
            const __nv_bfloat16* shl = g_h_lo + nodeA * 128 + cw * 64 + half * 32;
#pragma unroll
            for (int t = 0; t < 4; t++) {
                cpa16(dstAH[cw] + t * 16, shh + t * 8);
                cpa16(dstAL[cw] + t * 16, shl + t * 8);
            }
        }
        const __nv_bfloat16* swh = g_eW1t_hi + row2 * 256 + half * 32;
        const __nv_bfloat16* swl = g_eW1t_lo + row2 * 256 + half * 32;
#pragma unroll
        for (int t = 0; t < 4; t++) {
            cpa16(dstBH[0] + t * 16, swh + t * 8);
            cpa16(dstBL[0] + t * 16, swl + t * 8);
        }
        CPA_COMMIT();
    }
    issueB(0, 1, 1);                // G2: W1a k-win1 -> B1

    float da[16][4], db[16][4];
#pragma unroll
    for (int nt = 0; nt < 16; nt++)
#pragma unroll
        for (int q = 0; q < 4; q++) { da[nt][q] = 0.f; db[nt][q] = 0.f; }

    CPA_WAIT(1); __syncthreads();
    mma_win64(aA_h[0], aA_l[0], aB_h[0], aB_l[0], da);
    __syncthreads();
    issueB(1, 0, 0);                // G3: W1b k-win0 -> B0
    CPA_WAIT(1); __syncthreads();
    mma_win64(aA_h[1], aA_l[1], aB_h[1], aB_l[1], da);
    __syncthreads();
    issueB(1, 1, 1);                // G4: W1b k-win1 -> B1
    CPA_WAIT(1); __syncthreads();
    mma_win64(aA_h[0], aA_l[0], aB_h[0], aB_l[0], db);
    CPA_WAIT(0); __syncthreads();
    mma_win64(aA_h[1], aA_l[1], aB_h[1], aB_l[1], db);

    // write H1a / H1b
    {
        int n0 = nb + r0, n1 = nb + r1;
        bool v0 = n0 < N, v1 = n1 < N;
#pragma unroll
        for (int nt = 0; nt < 16; nt++) {
            int j = nt * 8 + (lane & 3) * 2;
            if (v0) {
                *(float2*)&g_H1a[n0 * 128 + j] = make_float2(da[nt][0], da[nt][1]);
                *(float2*)&g_H1b[n0 * 128 + j] = make_float2(db[nt][0], db[nt][1]);
            }
            if (v1) {
                *(float2*)&g_H1a[n1 * 128 + j] = make_float2(da[nt][2], da[nt][3]);
                *(float2*)&g_H1b[n1 * 128 + j] = make_float2(db[nt][2], db[nt][3]);
            }
        }
    }
}

// ---------------------------------------------------------------------------
// Edge kernel (persistent): 128 edges/tile, 256 threads.
// Stage 1 = gather H1a[s]+H1b[r] straight into D fragments (no MMA).
// eW2t (hi/lo) and pW1t (hh) fully SMEM-resident; zero per-tile cp.async.
// ---------------------------------------------------------------------------
#define R2H 0
#define R2L 36864
#define R3H 73728
#define EOFF_SE  110592
#define EOFF_RE  111104
#define EOFF_RAD 111616
#define EOFF_CD  112128
#define EOFF_EB1 113664
#define EOFF_EB2 114176
#define EOFF_PB1 114688
#define EOFF_PW2 115200
#define EOFF_W1R 115712
#define EOFF_RPC 116224
#define ESM_TOTAL 116736

__global__ __launch_bounds__(256, 1)
void edge_kernel(const float* __restrict__ pos,
                 const int* __restrict__ snd, const int* __restrict__ rcv,
                 const float* __restrict__ eW1, const float* __restrict__ eb1,
                 const float* __restrict__ eb2,
                 const float* __restrict__ pb1, const float* __restrict__ pW2,
                 int E, int nTiles)
{
    extern __shared__ char sm[];
    const uint32_t smb = smem_u32(sm);
    const int tid = threadIdx.x;
    const int lane = tid & 31, w = tid >> 5;

    int* se = (int*)(sm + EOFF_SE);
    int* re = (int*)(sm + EOFF_RE);
    float* rad = (float*)(sm + EOFF_RAD);
    float* cd = (float*)(sm + EOFF_CD);
    float* s_eb1 = (float*)(sm + EOFF_EB1);
    float* s_eb2 = (float*)(sm + EOFF_EB2);
    float* s_pb1 = (float*)(sm + EOFF_PB1);
    float* s_pw2 = (float*)(sm + EOFF_PW2);
    float* s_w1r = (float*)(sm + EOFF_W1R);
    float* redpc = (float*)(sm + EOFF_RPC);

    if (tid < 128) {
        s_eb1[tid] = eb1[tid];
        s_eb2[tid] = eb2[tid];
        s_pb1[tid] = pb1[tid];
        s_pw2[tid] = pW2[tid];
        s_w1r[tid] = eW1[256 * 128 + tid];
    }

    const int lane3 = lane & 3;
    const int bn = (lane & 7) + ((lane >> 4) << 3);
    const int bkb = ((lane >> 3) & 1) * 16;

    const uint32_t s2H[2] = {smb + R2H + bn * 144 + bkb,
                             smb + R2H + 18432 + bn * 144 + bkb};
    const uint32_t s2L[2] = {smb + R2L + bn * 144 + bkb,
                             smb + R2L + 18432 + bn * 144 + bkb};
    const uint32_t s3B[2] = {smb + R3H + bn * 144 + bkb,
                             smb + R3H + 18432 + bn * 144 + bkb};

    const int r0 = w * 16 + (lane >> 2);
    const int r1 = r0 + 8;
    const int row2 = tid >> 1, half = tid & 1;

    // resident weight load (once per CTA)
    {
#pragma unroll
        for (int cw = 0; cw < 2; cw++) {
            const __nv_bfloat16* s2h = g_eW2t_hi + row2 * 128 + cw * 64 + half * 32;
            const __nv_bfloat16* s2l = g_eW2t_lo + row2 * 128 + cw * 64 + half * 32;
            const __nv_bfloat16* s3h = g_pW1t_hi + row2 * 128 + cw * 64 + half * 32;
            uint32_t d2h = smb + R2H + cw * 18432 + row2 * 144 + half * 64;
            uint32_t d2l = smb + R2L + cw * 18432 + row2 * 144 + half * 64;
            uint32_t d3h = smb + R3H + cw * 18432 + row2 * 144 + half * 64;
#pragma unroll
            for (int t = 0; t < 4; t++) {
                cpa16(d2h + t * 16, s2h + t * 8);
                cpa16(d2l + t * 16, s2l + t * 8);
                cpa16(d3h + t * 16, s3h + t * 8);
            }
        }
        CPA_COMMIT();
        CPA_WAIT(0);
    }
    __syncthreads();

    for (int tile = blockIdx.x; tile < nTiles; tile += gridDim.x) {
        const int ebase = tile * 128;
        if (tid < 128) {
            int ge = ebase + tid; if (ge >= E) ge = E - 1;
            int s = snd[ge], r = rcv[ge];
            se[tid] = s; re[tid] = r;
            float dx = pos[s * 3 + 0] - pos[r * 3 + 0];
            float dy = pos[s * 3 + 1] - pos[r * 3 + 1];
            float dz = pos[s * 3 + 2] - pos[r * 3 + 2];
            cd[tid * 3 + 0] = dx; cd[tid * 3 + 1] = dy; cd[tid * 3 + 2] = dz;
            rad[tid] = dx * dx + dy * dy + dz * dz;
        }
        __syncthreads();

        // ===== stage 1: gather H1a[s] + H1b[r] into D fragments =====
        const int s0 = se[r0], s1 = se[r1];
        const int q0 = re[r0], q1 = re[r1];
        float d[16][4];
#pragma unroll
        for (int nt = 0; nt < 16; nt++) {
            int j = nt * 8 + lane3 * 2;
            float2 a0 = *(const float2*)&g_H1a[s0 * 128 + j];
            float2 b0 = *(const float2*)&g_H1b[q0 * 128 + j];
            float2 a1 = *(const float2*)&g_H1a[s1 * 128 + j];
            float2 b1 = *(const float2*)&g_H1b[q1 * 128 + j];
            d[nt][0] = a0.x + b0.x; d[nt][1] = a0.y + b0.y;
            d[nt][2] = a1.x + b1.x; d[nt][3] = a1.y + b1.y;
        }

        // ===== fused ep1 + stage2 =====
        float e[16][4];
#pragma unroll
        for (int nt = 0; nt < 16; nt++)
#pragma unroll
            for (int q = 0; q < 4; q++) e[nt][q] = 0.f;
        const float rd0 = rad[r0], rd1 = rad[r1];
#pragma unroll
        for (int c = 0; c < 8; c++) {
            int nt0 = 2 * c, nt1 = 2 * c + 1;
            int j0 = nt0 * 8 + lane3 * 2;
            int j1 = j0 + 8;
            uint32_t ah[4], al[4];
            float v00 = silu_f(d[nt0][0] + rd0 * s_w1r[j0] + s_eb1[j0]);
            float v01 = silu_f(d[nt0][1] + rd0 * s_w1r[j0 + 1] + s_eb1[j0 + 1]);
            float v10 = silu_f(d[nt0][2] + rd1 * s_w1r[j0] + s_eb1[j0]);
            float v11 = silu_f(d[nt0][3] + rd1 * s_w1r[j0 + 1] + s_eb1[j0 + 1]);
            split_pack(v00, v01, ah[0], al[0]);
            split_pack(v10, v11, ah[1], al[1]);
            float w00 = silu_f(d[nt1][0] + rd0 * s_w1r[j1] + s_eb1[j1]);
            float w01 = silu_f(d[nt1][1] + rd0 * s_w1r[j1 + 1] + s_eb1[j1 + 1]);
            float w10 = silu_f(d[nt1][2] + rd1 * s_w1r[j1] + s_eb1[j1]);
            float w11 = silu_f(d[nt1][3] + rd1 * s_w1r[j1 + 1] + s_eb1[j1 + 1]);
            split_pack(w00, w01, ah[2], al[2]);
            split_pack(w10, w11, ah[3], al[3]);
            mma_chunk3(ah, al, s2H[c >> 2] + (c & 3) * 32,
                       s2L[c >> 2] + (c & 3) * 32, e);
        }

        // ===== fused ep2 + red2 + stage3 (hh-only) =====
#pragma unroll
        for (int nt = 0; nt < 16; nt++)
#pragma unroll
            for (int q = 0; q < 4; q++) d[nt][q] = 0.f;
        {
            bool val0 = (ebase + r0) < E, val1 = (ebase + r1) < E;
#pragma unroll
            for (int c = 0; c < 8; c++) {
                int nt0 = 2 * c, nt1 = 2 * c + 1;
                int j0 = nt0 * 8 + lane3 * 2;
                int j1 = j0 + 8;
                uint32_t ah[4];
                float v00 = silu_f(e[nt0][0] + s_eb2[j0]);
                float v01 = silu_f(e[nt0][1] + s_eb2[j0 + 1]);
                float v10 = silu_f(e[nt0][2] + s_eb2[j0]);
                float v11 = silu_f(e[nt0][3] + s_eb2[j0 + 1]);
                float w00 = silu_f(e[nt1][0] + s_eb2[j1]);
                float w01 = silu_f(e[nt1][1] + s_eb2[j1 + 1]);
                float w10 = silu_f(e[nt1][2] + s_eb2[j1]);
                float w11 = silu_f(e[nt1][3] + s_eb2[j1 + 1]);
                ah[0] = pack_hi(v00, v01);
                ah[1] = pack_hi(v10, v11);
                ah[2] = pack_hi(w00, w01);
                ah[3] = pack_hi(w10, w11);
                if (val0) {
                    red2(&g_agg[q0 * 128 + j0], v00, v01);
                    red2(&g_agg[q0 * 128 + j1], w00, w01);
                }
                if (val1) {
                    red2(&g_agg[q1 * 128 + j0], v10, v11);
                    red2(&g_agg[q1 * 128 + j1], w10, w11);
                }
                mma_chunk1(ah, s3B[c >> 2] + (c & 3) * 32, d);
            }
        }

        // ===== ep3: pc reduction + position scatter =====
        {
            float p0 = 0.f, p1 = 0.f;
#pragma unroll
            for (int nt = 0; nt < 16; nt++) {
                int j = nt * 8 + lane3 * 2;
                p0 += silu_f(d[nt][0] + s_pb1[j]) * s_pw2[j]
                    + silu_f(d[nt][1] + s_pb1[j + 1]) * s_pw2[j + 1];
                p1 += silu_f(d[nt][2] + s_pb1[j]) * s_pw2[j]
                    + silu_f(d[nt][3] + s_pb1[j + 1]) * s_pw2[j + 1];
            }
            p0 += __shfl_xor_sync(0xffffffffu, p0, 1);
            p0 += __shfl_xor_sync(0xffffffffu, p0, 2);
            p1 += __shfl_xor_sync(0xffffffffu, p1, 1);
            p1 += __shfl_xor_sync(0xffffffffu, p1, 2);
            if ((lane & 3) == 0) { redpc[r0] = p0; redpc[r1] = p1; }
            __syncthreads();
            if (tid < 128 && (ebase + tid) < E) {
                int s = se[tid];
                float pc = redpc[tid];
#pragma unroll
                for (int dd = 0; dd < 3; dd++) {
                    float v = cd[tid * 3 + dd] * pc;
                    v = fminf(fmaxf(v, -100.f), 100.f);
                    atomicAdd(&g_pacc[s * 3 + dd], v);
                }
            }
        }
        __syncthreads();   // se/re/rad/cd/redpc reuse safety
    }
}

// ---------------------------------------------------------------------------
// Node kernel (bf16x3, fused): 128 nodes/block, 256 threads. (R15 layout)
// ---------------------------------------------------------------------------
#define OFF_A0H 0
#define OFF_A0L 18432
#define OFF_A1H 36864
#define OFF_A1L 55296
#define OFF_B0H 73728
#define OFF_B0L 92160
#define OFF_B1H 110592
#define OFF_B1L 129024
#define OFF_B2H 147456
#define OFF_B2L 165888
#define NOD_NB1 184320
#define NOD_NB2 184832
#define NOD_TOTAL 185344

__global__ __launch_bounds__(256, 1)
void node_kernel(const float* __restrict__ h, const float* __restrict__ pos,
                 const float* __restrict__ nb1, const float* __restrict__ nb2,
                 float* __restrict__ out, int N)
{
    extern __shared__ char sm[];
    const uint32_t smb = smem_u32(sm);
    const int tid = threadIdx.x;
    const int lane = tid & 31, w = tid >> 5;
    const int nb = blockIdx.x * 128;

    float* s_nb1 = (float*)(sm + NOD_NB1);
    float* s_nb2 = (float*)(sm + NOD_NB2);
    if (tid < 128) {
        s_nb1[tid] = nb1[tid];
        s_nb2[tid] = nb2[tid];
    }
    __syncthreads();

    const int arow = lane & 15;
    const int akb = (lane >> 4) * 16;
    const int bn = (lane & 7) + ((lane >> 4) << 3);
    const int bkb = ((lane >> 3) & 1) * 16;

    const uint32_t aA_h[2] = {smb + OFF_A0H + (w * 16 + arow) * 144 + akb,
                              smb + OFF_A1H + (w * 16 + arow) * 144 + akb};
    const uint32_t aA_l[2] = {smb + OFF_A0L + (w * 16 + arow) * 144 + akb,
                              smb + OFF_A1L + (w * 16 + arow) * 144 + akb};
    const uint32_t aB_h[2] = {smb + OFF_B0H + bn * 144 + bkb,
                              smb + OFF_B1H + bn * 144 + bkb};
    const uint32_t aB_l[2] = {smb + OFF_B0L + bn * 144 + bkb,
                              smb + OFF_B1L + bn * 144 + bkb};
    const uint32_t s2H[2] = {smb + OFF_B2H + bn * 144 + bkb,
                             smb + OFF_B0H + bn * 144 + bkb};
    const uint32_t s2L[2] = {smb + OFF_B2L + bn * 144 + bkb,
                             smb + OFF_B0L + bn * 144 + bkb};

    const int r0 = w * 16 + (lane >> 2);
    const int r1 = r0 + 8;
    const int row2 = tid >> 1, half = tid & 1;

    const uint32_t dstAH[2] = {smb + OFF_A0H + row2 * 144 + half * 64,
                               smb + OFF_A1H + row2 * 144 + half * 64};
    const uint32_t dstAL[2] = {smb + OFF_A0L + row2 * 144 + half * 64,
                               smb + OFF_A1L + row2 * 144 + half * 64};
    const uint32_t dstBH[2] = {smb + OFF_B0H + row2 * 144 + half * 64,
                               smb + OFF_B1H + row2 * 144 + half * 64};
    const uint32_t dstBL[2] = {smb + OFF_B0L + row2 * 144 + half * 64,
                               smb + OFF_B1L + row2 * 144 + half * 64};
    const uint32_t dstB2H = smb + OFF_B2H + row2 * 144 + half * 64;
    const uint32_t dstB2L = smb + OFF_B2L + row2 * 144 + half * 64;

    int nodeA = nb + row2; if (nodeA >= N) nodeA = N - 1;

    auto issue_win = [&](int cn) {
        int buf = cn & 1;
        const __nv_bfloat16* shh = (cn < 2)
            ? g_h_hi + nodeA * 128 + cn * 64 + half * 32
            : g_agg_hi + nodeA * 128 + (cn - 2) * 64 + half * 32;
        const __nv_bfloat16* shl = (cn < 2)
            ? g_h_lo + nodeA * 128 + cn * 64 + half * 32
            : g_agg_lo + nodeA * 128 + (cn - 2) * 64 + half * 32;
        const __nv_bfloat16* swh = g_nW1t_hi + row2 * 256 + cn * 64 + half * 32;
        const __nv_bfloat16* swl = g_nW1t_lo + row2 * 256 + cn * 64 + half * 32;
#pragma unroll
        for (int t = 0; t < 4; t++) {
            cpa16(dstAH[buf] + t * 16, shh + t * 8);
            cpa16(dstAL[buf] + t * 16, shl + t * 8);
            cpa16(dstBH[buf] + t * 16, swh + t * 8);
            cpa16(dstBL[buf] + t * 16, swl + t * 8);
        }
        CPA_COMMIT();
    };

    float d[16][4];
#pragma unroll
    for (int nt = 0; nt < 16; nt++)
#pragma unroll
        for (int q = 0; q < 4; q++) d[nt][q] = 0.f;

    issue_win(0);
    issue_win(1);
    {   // stage-2 B window0 (nW2t) -> B2
        const __nv_bfloat16* swh = g_nW2t_hi + row2 * 128 + half * 32;
        const __nv_bfloat16* swl = g_nW2t_lo + row2 * 128 + half * 32;
#pragma unroll
        for (int t = 0; t < 4; t++) {
            cpa16(dstB2H + t * 16, swh + t * 8);
            cpa16(dstB2L + t * 16, swl + t * 8);
        }
        CPA_COMMIT();
    }
    CPA_WAIT(2); __syncthreads();
    mma_win64(aA_h[0], aA_l[0], aB_h[0], aB_l[0], d);
    __syncthreads();
    issue_win(2);
    CPA_WAIT(2); __syncthreads();
    mma_win64(aA_h[1], aA_l[1], aB_h[1], aB_l[1], d);
    __syncthreads();
    issue_win(3);
    CPA_WAIT(1); __syncthreads();
    mma_win64(aA_h[0], aA_l[0], aB_h[0], aB_l[0], d);
    __syncthreads();
    {   // stage-2 B window1 -> B0
        const __nv_bfloat16* swh = g_nW2t_hi + row2 * 128 + 64 + half * 32;
        const __nv_bfloat16* swl = g_nW2t_lo + row2 * 128 + 64 + half * 32;
#pragma unroll
        for (int t = 0; t < 4; t++) {
            cpa16(dstBH[0] + t * 16, swh + t * 8);
            cpa16(dstBL[0] + t * 16, swl + t * 8);
        }
        CPA_COMMIT();
    }
    CPA_WAIT(1); __syncthreads();
    mma_win64(aA_h[1], aA_l[1], aB_h[1], aB_l[1], d);
    CPA_WAIT(0); __syncthreads();

    // fused ep1 + stage2 (3-pass)
    float e[16][4];
#pragma unroll
    for (int nt = 0; nt < 16; nt++)
#pragma unroll
        for (int q = 0; q < 4; q++) e[nt][q] = 0.f;
#pragma unroll
    for (int c = 0; c < 8; c++) {
        int nt0 = 2 * c, nt1 = 2 * c + 1;
        int j0 = nt0 * 8 + (lane & 3) * 2;
        int j1 = j0 + 8;
        uint32_t ah[4], al[4];
        float v00 = silu_f(d[nt0][0] + s_nb1[j0]);
        float v01 = silu_f(d[nt0][1] + s_nb1[j0 + 1]);
        float v10 = silu_f(d[nt0][2] + s_nb1[j0]);
        float v11 = silu_f(d[nt0][3] + s_nb1[j0 + 1]);
        split_pack(v00, v01, ah[0], al[0]);
        split_pack(v10, v11, ah[1], al[1]);
        float w00 = silu_f(d[nt1][0] + s_nb1[j1]);
        float w01 = silu_f(d[nt1][1] + s_nb1[j1 + 1]);
        float w10 = silu_f(d[nt1][2] + s_nb1[j1]);
        float w11 = silu_f(d[nt1][3] + s_nb1[j1 + 1]);
        split_pack(w00, w01, ah[2], al[2]);
        split_pack(w10, w11, ah[3], al[3]);
        mma_chunk3(ah, al, s2H[c >> 2] + (c & 3) * 32,
                   s2L[c >> 2] + (c & 3) * 32, e);
    }

    // epilogue: h_new = h + x
    {
        int n0 = nb + r0, n1 = nb + r1;
        bool v0 = n0 < N, v1 = n1 < N;
#pragma unroll
        for (int nt = 0; nt < 16; nt++) {
            int j = nt * 8 + (lane & 3) * 2;
            if (v0) {
                out[n0 * 128 + j]     = e[nt][0] + s_nb2[j] + h[n0 * 128 + j];
                out[n0 * 128 + j + 1] = e[nt][1] + s_nb2[j + 1] + h[n0 * 128 + j + 1];
            }
            if (v1) {
                out[n1 * 128 + j]     = e[nt][2] + s_nb2[j] + h[n1 * 128 + j];
                out[n1 * 128 + j + 1] = e[nt][3] + s_nb2[j + 1] + h[n1 * 128 + j + 1];
            }
        }
    }

    // pos_new = pos + pacc
    if (tid < 128) {
        int node = nb + tid;
        if (node < N) {
#pragma unroll
            for (int dd = 0; dd < 3; dd++)
                out[N * 128 + node * 3 + dd] =
                    pos[node * 3 + dd] + g_pacc[node * 3 + dd];
        }
    }
}

extern "C" void kernel_launch(void* const* d_in, const int* in_sizes, int n_in,
                              void* d_out, int out_size)
{
    const float* h   = (const float*)d_in[0];
    const float* pos = (const float*)d_in[1];
    const int*   snd = (const int*)d_in[2];
    const int*   rcv = (const int*)d_in[3];
    const float* eW1 = (const float*)d_in[4];
    const float* eb1 = (const float*)d_in[5];
    const float* eW2 = (const float*)d_in[6];
    const float* eb2 = (const float*)d_in[7];
    const float* nW1 = (const float*)d_in[8];
    const float* nb1 = (const float*)d_in[9];
    const float* nW2 = (const float*)d_in[10];
    const float* nb2 = (const float*)d_in[11];
    const float* pW1 = (const float*)d_in[12];
    const float* pb1 = (const float*)d_in[13];
    const float* pW2 = (const float*)d_in[14];
    float* out = (float*)d_out;

    int N = in_sizes[0] / 128;
    int E = in_sizes[2];
    int nTiles = (E + 127) / 128;
    int nBlocks = (N + 127) / 128;

    cudaFuncSetAttribute(h1_kernel, cudaFuncAttributeMaxDynamicSharedMemorySize, H1_TOTAL);
    cudaFuncSetAttribute(edge_kernel, cudaFuncAttributeMaxDynamicSharedMemorySize, ESM_TOTAL);
    cudaFuncSetAttribute(node_kernel, cudaFuncAttributeMaxDynamicSharedMemorySize, NOD_TOTAL);

    prep_kernel<<<512, 256>>>(h, eW1, eW2, pW1, nW1, nW2, N);
    h1_kernel<<<nBlocks, 256, H1_TOTAL>>>(N);
    int grid = nTiles < 152 ? nTiles : 152;
    edge_kernel<<<grid, 256, ESM_TOTAL>>>(pos, snd, rcv, eW1, eb1, eb2,
                                          pb1, pW2, E, nTiles);
    split_agg_kernel<<<512, 256>>>(N * 32);
    node_kernel<<<nBlocks, 256, NOD_TOTAL>>>(h, pos, nb1, nb2, out, N);
}